// round 4
// baseline (speedup 1.0000x reference)
#include <cuda_runtime.h>
#include <cuda_bf16.h>
#include <stdint.h>
#include <math.h>

#define BSZ   32
#define LSEQ  1024
#define DIM   512
#define MTOT  (BSZ*LSEQ)          // 32768
#define GDIM  2048                // 4*DIM
#define GRID_BLOCKS 128

// =================== scratch (device globals) ================================
__device__ __align__(128) __nv_bfloat16 g_aHi[(size_t)MTOT*DIM];
__device__ __align__(128) __nv_bfloat16 g_aLo[(size_t)MTOT*DIM];
__device__ __align__(128) __nv_bfloat16 g_bHi[(size_t)MTOT*DIM];
__device__ __align__(128) __nv_bfloat16 g_bLo[(size_t)MTOT*DIM];
__device__ __align__(128) __nv_bfloat16 g_wConv[3][(size_t)DIM*4608];   // [layer][n][kk]
__device__ __align__(128) __nv_bfloat16 g_wGate[2][(size_t)GDIM*1536];  // [dir][n][kk]
__device__ float g_gpre[2][(size_t)MTOT*GDIM];   // [dir][(t*32+b)*2048 + n]
__device__ float g_hstate[2][2][BSZ*DIM];        // [parity][dir][b*512+d]
__device__ float g_alpha[3][DIM];
__device__ float g_beta[3][DIM];
__device__ unsigned g_bar_arrive;
__device__ unsigned g_bar_gen;

// =================== SW128 swizzle (128B rows) ================================
#define SWZ(off) ((off) ^ (((off) >> 3) & 0x70))

// =================== warp MMA primitives (family-portable, sm_80+) ===========
__device__ __forceinline__ uint32_t smem_to_u32(const void* p) {
    uint32_t a;
    asm("{ .reg .u64 t; cvta.to.shared.u64 t, %1; cvt.u32.u64 %0, t; }" : "=r"(a) : "l"(p));
    return a;
}
#define LDSM_X4(r0, r1, r2, r3, addr) \
    asm volatile("ldmatrix.sync.aligned.m8n8.x4.shared.b16 {%0,%1,%2,%3}, [%4];" \
        : "=r"(r0), "=r"(r1), "=r"(r2), "=r"(r3) : "r"(addr))
#define MMA16816(c, a, b) \
    asm volatile("mma.sync.aligned.m16n8k16.row.col.f32.bf16.bf16.f32 " \
        "{%0,%1,%2,%3}, {%4,%5,%6,%7}, {%8,%9}, {%0,%1,%2,%3};" \
        : "+f"((c)[0]), "+f"((c)[1]), "+f"((c)[2]), "+f"((c)[3]) \
        : "r"((a)[0]), "r"((a)[1]), "r"((a)[2]), "r"((a)[3]), \
          "r"((b)[0]), "r"((b)[1]))
// packed dual-FMA (fp32 exact, sm_100+ family)
#define FMA2(acc, w, x) \
    asm("fma.rn.f32x2 %0, %1, %2, %0;" : "+l"(acc) : "l"(w), "l"(x))

// =================== misc helpers ============================================
__device__ __forceinline__ float sigmoidf_(float x) { return 1.0f / (1.0f + __expf(-x)); }

__device__ __forceinline__ void grid_sync_() {
    __threadfence();
    __syncthreads();
    if (threadIdx.x == 0) {
        unsigned cur = *(volatile unsigned*)&g_bar_gen;
        unsigned a = atomicAdd(&g_bar_arrive, 1u);
        if (a == GRID_BLOCKS - 1) {
            g_bar_arrive = 0u;
            __threadfence();
            atomicAdd(&g_bar_gen, 1u);
        } else {
            while (*(volatile unsigned*)&g_bar_gen == cur) { }
        }
    }
    __syncthreads();
}

// =================== BN fold =================================================
__global__ void bnprep_kernel(
    const float* __restrict__ b1, const float* __restrict__ s1, const float* __restrict__ o1,
    const float* __restrict__ m1, const float* __restrict__ v1,
    const float* __restrict__ b2, const float* __restrict__ s2, const float* __restrict__ o2,
    const float* __restrict__ m2, const float* __restrict__ v2,
    const float* __restrict__ b3, const float* __restrict__ s3, const float* __restrict__ o3,
    const float* __restrict__ m3, const float* __restrict__ v3)
{
    int i = threadIdx.x;
    if (i < DIM) {
        float g;
        g = s1[i] * rsqrtf(v1[i] + 1e-5f); g_alpha[0][i] = g; g_beta[0][i] = (b1[i] - m1[i]) * g + o1[i];
        g = s2[i] * rsqrtf(v2[i] + 1e-5f); g_alpha[1][i] = g; g_beta[1][i] = (b2[i] - m2[i]) * g + o2[i];
        g = s3[i] * rsqrtf(v3[i] + 1e-5f); g_alpha[2][i] = g; g_beta[2][i] = (b3[i] - m3[i]) * g + o3[i];
    }
}

// =================== weight prep: bf16 hi/lo sections ========================
__global__ void wprep_conv_kernel(const float* __restrict__ Wc, int layer)
{
    int idx = blockIdx.x * 256 + threadIdx.x;
    if (idx >= DIM * 4608) return;
    int n = idx / 4608, kk = idx % 4608;
    int s = kk / 1536, r = kk % 1536;
    float v = Wc[(size_t)r * DIM + n];
    __nv_bfloat16 h = __float2bfloat16(v);
    __nv_bfloat16 o = (s < 2) ? h : __float2bfloat16(v - __bfloat162float(h));
    g_wConv[layer][(size_t)n * 4608 + kk] = o;
}
__global__ void wprep_gate_kernel(const float* __restrict__ W, int dir)
{
    int idx = blockIdx.x * 256 + threadIdx.x;
    if (idx >= GDIM * 1536) return;
    int n = idx / 1536, kk = idx % 1536;
    int s = kk / 512, k = kk % 512;
    float v = W[(size_t)k * GDIM + n];
    __nv_bfloat16 h = __float2bfloat16(v);
    __nv_bfloat16 o = (s < 2) ? h : __float2bfloat16(v - __bfloat162float(h));
    g_wGate[dir][(size_t)n * 1536 + kk] = o;
}

// =================== embedding -> bf16 hi/lo =================================
__global__ void embed_kernel(const int* __restrict__ x, const float* __restrict__ ew)
{
    int m = blockIdx.x;
    int tok = x[m];
    int j = threadIdx.x;                       // 0..127
    float4 v = ((const float4*)(ew + (size_t)tok * DIM))[j];
    float f[4] = {v.x, v.y, v.z, v.w};
    __nv_bfloat16 h[4], l[4];
    #pragma unroll
    for (int i = 0; i < 4; i++) {
        h[i] = __float2bfloat16(f[i]);
        l[i] = __float2bfloat16(f[i] - __bfloat162float(h[i]));
    }
    *(uint2*)(g_aHi + (size_t)m * DIM + j * 4) = *(uint2*)h;
    *(uint2*)(g_aLo + (size_t)m * DIM + j * 4) = *(uint2*)l;
}

// =================== bf16 mma.sync GEMM (conv & gates) =======================
__global__ void __launch_bounds__(256) mma_gemm_kernel(
    const __nv_bfloat16* __restrict__ Ahi, const __nv_bfloat16* __restrict__ Alo,
    const __nv_bfloat16* __restrict__ Bw,  int Ktot, int convmode, int layer,
    __nv_bfloat16* __restrict__ outHi, __nv_bfloat16* __restrict__ outLo,
    const float* __restrict__ bias, float* __restrict__ gout)
{
    extern __shared__ char smem[];
    const int tid = threadIdx.x;
    const int lane = tid & 31, wid = tid >> 5;
    const int wm = wid & 3, wn = wid >> 2;
    const int m0 = blockIdx.x * 128, n0 = blockIdx.y * 128;
    const int t0 = m0 & (LSEQ - 1);
    const uint32_t sb = smem_to_u32(smem);

    const uint32_t sx   = (uint32_t)(lane & 7) << 4;
    const uint32_t rowA = (uint32_t)(lane & 15) * 128u;
    const uint32_t hiA  = (uint32_t)(lane >> 4) * 16u;
    const uint32_t rowB = (uint32_t)(((lane >> 4) << 3) | (lane & 7)) * 128u;
    const uint32_t hiB  = (uint32_t)((lane >> 3) & 1) * 16u;

    float acc[2][8][4];
    #pragma unroll
    for (int a = 0; a < 2; a++)
        #pragma unroll
        for (int b = 0; b < 8; b++)
            #pragma unroll
            for (int c = 0; c < 4; c++) acc[a][b][c] = 0.f;

    const int nch = Ktot >> 6;
    const int nsc = nch / 3;

    #define DO_COPY(CC, BSEL) do { \
        int _cc = (CC); \
        int _s = _cc / nsc, _r = _cc - _s * nsc; \
        const __nv_bfloat16* _Asrc = (_s == 1) ? Alo : Ahi; \
        int _shift, _kb; \
        if (convmode) { _shift = (_r >> 3) - 1; _kb = (_r & 7) << 6; } \
        else          { _shift = 0;             _kb = _r << 6; } \
        const int _kk0 = _cc << 6; \
        char* _aP = smem + (BSEL) * 32768; \
        char* _bP = _aP + 16384; \
        _Pragma("unroll") \
        for (int _i = 0; _i < 4; _i++) { \
            int _idx = _i * 256 + tid; \
            int _rowl = _idx >> 3, _cq = (_idx & 7) << 3; \
            uint32_t _off = SWZ((uint32_t)(_rowl * 128 + _cq * 2)); \
            int _tl = t0 + _rowl + _shift; \
            uint4 _va = make_uint4(0u, 0u, 0u, 0u); \
            if (_tl >= 0 && _tl < LSEQ) \
                _va = *(const uint4*)(_Asrc + (size_t)(m0 + _rowl + _shift) * DIM + _kb + _cq); \
            *(uint4*)(_aP + _off) = _va; \
            uint4 _vb = *(const uint4*)(Bw + (size_t)(n0 + _rowl) * Ktot + _kk0 + _cq); \
            *(uint4*)(_bP + _off) = _vb; \
        } \
    } while (0)

    DO_COPY(0, 0);
    __syncthreads();

    for (int cc = 0; cc < nch; cc++) {
        const int bsel = cc & 1;
        if (cc + 1 < nch) DO_COPY(cc + 1, bsel ^ 1);

        const uint32_t aBase = sb + bsel * 32768 + (uint32_t)(wm * 32) * 128;
        const uint32_t bBase = sb + bsel * 32768 + 16384 + (uint32_t)(wn * 64) * 128;

        #pragma unroll
        for (int k16 = 0; k16 < 4; k16++) {
            const uint32_t kcA = ((uint32_t)(k16 * 32) + hiA) ^ sx;
            const uint32_t kcB = ((uint32_t)(k16 * 32) + hiB) ^ sx;
            uint32_t afr[2][4];
            #pragma unroll
            for (int mt = 0; mt < 2; mt++) {
                uint32_t ad = aBase + (uint32_t)(mt * 2048) + rowA + kcA;
                LDSM_X4(afr[mt][0], afr[mt][1], afr[mt][2], afr[mt][3], ad);
            }
            uint32_t bfr[8][2];
            #pragma unroll
            for (int np = 0; np < 4; np++) {
                uint32_t bd = bBase + (uint32_t)(np * 2048) + rowB + kcB;
                LDSM_X4(bfr[2*np][0], bfr[2*np][1], bfr[2*np+1][0], bfr[2*np+1][1], bd);
            }
            #pragma unroll
            for (int mt = 0; mt < 2; mt++)
                #pragma unroll
                for (int nt = 0; nt < 8; nt++)
                    MMA16816(acc[mt][nt], afr[mt], bfr[nt]);
        }
        __syncthreads();
    }
    #undef DO_COPY

    const int g  = lane >> 2;
    const int tg = lane & 3;
    if (gout == nullptr) {
        #pragma unroll
        for (int mt = 0; mt < 2; mt++) {
            const int mlo = m0 + wm * 32 + mt * 16 + g;
            const int mhi = mlo + 8;
            #pragma unroll
            for (int nt = 0; nt < 8; nt++) {
                const int n = n0 + wn * 64 + nt * 8 + tg * 2;
                const float al0 = g_alpha[layer][n],     be0 = g_beta[layer][n];
                const float al1 = g_alpha[layer][n + 1], be1 = g_beta[layer][n + 1];
                float v00 = fmaxf(fmaf(acc[mt][nt][0], al0, be0), 0.f);
                float v01 = fmaxf(fmaf(acc[mt][nt][1], al1, be1), 0.f);
                float v10 = fmaxf(fmaf(acc[mt][nt][2], al0, be0), 0.f);
                float v11 = fmaxf(fmaf(acc[mt][nt][3], al1, be1), 0.f);
                __nv_bfloat16 h00 = __float2bfloat16(v00), h01 = __float2bfloat16(v01);
                __nv_bfloat16 h10 = __float2bfloat16(v10), h11 = __float2bfloat16(v11);
                __nv_bfloat16 l00 = __float2bfloat16(v00 - __bfloat162float(h00));
                __nv_bfloat16 l01 = __float2bfloat16(v01 - __bfloat162float(h01));
                __nv_bfloat16 l10 = __float2bfloat16(v10 - __bfloat162float(h10));
                __nv_bfloat16 l11 = __float2bfloat16(v11 - __bfloat162float(h11));
                __nv_bfloat162 ph0; ph0.x = h00; ph0.y = h01;
                __nv_bfloat162 ph1; ph1.x = h10; ph1.y = h11;
                __nv_bfloat162 pl0; pl0.x = l00; pl0.y = l01;
                __nv_bfloat162 pl1; pl1.x = l10; pl1.y = l11;
                *(__nv_bfloat162*)(outHi + (size_t)mlo * DIM + n) = ph0;
                *(__nv_bfloat162*)(outHi + (size_t)mhi * DIM + n) = ph1;
                *(__nv_bfloat162*)(outLo + (size_t)mlo * DIM + n) = pl0;
                *(__nv_bfloat162*)(outLo + (size_t)mhi * DIM + n) = pl1;
            }
        }
    } else {
        #pragma unroll
        for (int mt = 0; mt < 2; mt++) {
            const int mlo = m0 + wm * 32 + mt * 16 + g;
            const int mhi = mlo + 8;
            const int blo = mlo >> 10, tlo = mlo & (LSEQ - 1);
            const int bhi = mhi >> 10, thi = mhi & (LSEQ - 1);
            #pragma unroll
            for (int nt = 0; nt < 8; nt++) {
                const int n = n0 + wn * 64 + nt * 8 + tg * 2;
                const float b0 = bias[n], b1 = bias[n + 1];
                float2 o0, o1;
                o0.x = acc[mt][nt][0] + b0; o0.y = acc[mt][nt][1] + b1;
                o1.x = acc[mt][nt][2] + b0; o1.y = acc[mt][nt][3] + b1;
                *(float2*)(gout + ((size_t)(tlo << 5) + blo) * GDIM + n) = o0;
                *(float2*)(gout + ((size_t)(thi << 5) + bhi) * GDIM + n) = o1;
            }
        }
    }
}

// =================== persistent bidirectional LSTM recurrence =================
// smem: Wtp [32 cols][514 float2] pre-duplicated (w,w); hs_t [512 k][36 floats]
// thread (tx,ty): col = gate(tx>>3)*512 + dc + (tx&7); batches 4ty..4ty+3.
__global__ void __launch_bounds__(256, 1) lstm_recur_kernel(
    const float* __restrict__ wf, const float* __restrict__ wb,
    const int* __restrict__ lengths, float* __restrict__ out)
{
    extern __shared__ float sm[];
    float2* Wtp = (float2*)sm;                    // 32*514 float2 = 131584 B
    float*  hs_t = sm + 32 * 514 * 2;             // 512*36 floats = 73728 B
    __shared__ int len_s[32];

    const int tid = threadIdx.x;
    const int dir = blockIdx.x >> 6;
    const int dc  = (blockIdx.x & 63) << 3;
    const float* w = dir ? wb : wf;

    for (int idx = tid; idx < 32 * 512; idx += 256) {
        int nl = idx & 31;
        int k  = idx >> 5;
        int c  = ((nl >> 3) << 9) + dc + (nl & 7);
        float wv = w[(size_t)(512 + k) * GDIM + c];
        Wtp[nl * 514 + k] = make_float2(wv, wv);
    }
    if (tid < 32) len_s[tid] = lengths[tid];
    {
        int b = tid >> 3, j = tid & 7;
        g_hstate[0][dir][b * DIM + dc + j] = 0.f;
    }
    grid_sync_();

    const int tx = tid & 31;
    const int ty = tid >> 5;                 // warp id 0..7 -> batches 4ty..4ty+3
    const int jd = tx & 7;
    const int col = ((tx >> 3) << 9) + dc + jd;
    const float* gpre = g_gpre[dir];
    const float2* wrowp = Wtp + tx * 514;
    const unsigned FULL = 0xffffffffu;

    float c0 = 0.f, c1 = 0.f, c2 = 0.f, c3 = 0.f;   // cell state, batches 4ty+0..3

    for (int s = 0; s < LSEQ; s++) {
        const int t = dir ? (LSEQ - 1 - s) : s;
        const int p = s & 1;
        const float4* hp4 = (const float4*)g_hstate[p][dir];
        float* hn = g_hstate[p ^ 1][dir];

        // stage h_prev transposed: hs_t[k][b] (reset applied for backward dir)
        #pragma unroll
        for (int i = 0; i < 16; i++) {
            int idx4 = i * 256 + tid;                 // 0..4095 float4
            int b = idx4 >> 7, kc = idx4 & 127;
            float4 v = __ldcg(hp4 + idx4);
            if (dir && t >= len_s[b] - 1) v = make_float4(0.f, 0.f, 0.f, 0.f);
            int kb = kc << 2;
            hs_t[(kb + 0) * 36 + b] = v.x;
            hs_t[(kb + 1) * 36 + b] = v.y;
            hs_t[(kb + 2) * 36 + b] = v.z;
            hs_t[(kb + 3) * 36 + b] = v.w;
        }
        __syncthreads();

        // packed dual-FMA matvec: acc pairs over batches (4ty,4ty+1),(4ty+2,4ty+3)
        unsigned long long accP0 = 0ull, accP1 = 0ull;
        const float* xbase = hs_t + 4 * ty;
        #pragma unroll 8
        for (int k = 0; k < 512; k += 2) {
            ulonglong2 wq  = *(const ulonglong2*)(wrowp + k);
            ulonglong2 xq0 = *(const ulonglong2*)(xbase + (size_t)k * 36);
            ulonglong2 xq1 = *(const ulonglong2*)(xbase + (size_t)(k + 1) * 36);
            FMA2(accP0, wq.x, xq0.x);
            FMA2(accP1, wq.x, xq0.y);
            FMA2(accP0, wq.y, xq1.x);
            FMA2(accP1, wq.y, xq1.y);
        }
        float a0 = __uint_as_float((unsigned)(accP0 & 0xffffffffull));
        float a1 = __uint_as_float((unsigned)(accP0 >> 32));
        float a2 = __uint_as_float((unsigned)(accP1 & 0xffffffffull));
        float a3 = __uint_as_float((unsigned)(accP1 >> 32));

        const float* gp = gpre + (size_t)(t << 5) * GDIM + col;
        float p0 = a0 + __ldg(gp + (size_t)(4 * ty + 0) * GDIM);
        float p1 = a1 + __ldg(gp + (size_t)(4 * ty + 1) * GDIM);
        float p2 = a2 + __ldg(gp + (size_t)(4 * ty + 2) * GDIM);
        float p3 = a3 + __ldg(gp + (size_t)(4 * ty + 3) * GDIM);

        float vi0 = __shfl_sync(FULL, p0, jd),      vi1 = __shfl_sync(FULL, p1, jd);
        float vi2 = __shfl_sync(FULL, p2, jd),      vi3 = __shfl_sync(FULL, p3, jd);
        float vg0 = __shfl_sync(FULL, p0, jd + 8),  vg1 = __shfl_sync(FULL, p1, jd + 8);
        float vg2 = __shfl_sync(FULL, p2, jd + 8),  vg3 = __shfl_sync(FULL, p3, jd + 8);
        float vf0 = __shfl_sync(FULL, p0, jd + 16), vf1 = __shfl_sync(FULL, p1, jd + 16);
        float vf2 = __shfl_sync(FULL, p2, jd + 16), vf3 = __shfl_sync(FULL, p3, jd + 16);
        float vo0 = __shfl_sync(FULL, p0, jd + 24), vo1 = __shfl_sync(FULL, p1, jd + 24);
        float vo2 = __shfl_sync(FULL, p2, jd + 24), vo3 = __shfl_sync(FULL, p3, jd + 24);

        if (tx < 8) {
            const int d = dc + tx;
            {
                int b = 4 * ty + 0;
                float cc = (dir && t >= len_s[b] - 1) ? 0.f : c0;
                cc = sigmoidf_(vf0 + 1.f) * cc + sigmoidf_(vi0) * tanhf(vg0);
                c0 = cc;
                float hh = sigmoidf_(vo0) * tanhf(cc);
                hn[b * DIM + d] = hh;
                out[(((size_t)b << 10) + t) * 1024 + (dir << 9) + d] = hh;
            }
            {
                int b = 4 * ty + 1;
                float cc = (dir && t >= len_s[b] - 1) ? 0.f : c1;
                cc = sigmoidf_(vf1 + 1.f) * cc + sigmoidf_(vi1) * tanhf(vg1);
                c1 = cc;
                float hh = sigmoidf_(vo1) * tanhf(cc);
                hn[b * DIM + d] = hh;
                out[(((size_t)b << 10) + t) * 1024 + (dir << 9) + d] = hh;
            }
            {
                int b = 4 * ty + 2;
                float cc = (dir && t >= len_s[b] - 1) ? 0.f : c2;
                cc = sigmoidf_(vf2 + 1.f) * cc + sigmoidf_(vi2) * tanhf(vg2);
                c2 = cc;
                float hh = sigmoidf_(vo2) * tanhf(cc);
                hn[b * DIM + d] = hh;
                out[(((size_t)b << 10) + t) * 1024 + (dir << 9) + d] = hh;
            }
            {
                int b = 4 * ty + 3;
                float cc = (dir && t >= len_s[b] - 1) ? 0.f : c3;
                cc = sigmoidf_(vf3 + 1.f) * cc + sigmoidf_(vi3) * tanhf(vg3);
                c3 = cc;
                float hh = sigmoidf_(vo3) * tanhf(cc);
                hn[b * DIM + d] = hh;
                out[(((size_t)b << 10) + t) * 1024 + (dir << 9) + d] = hh;
            }
        }
        grid_sync_();
    }
}

// =================== launch ===================================================
extern "C" void kernel_launch(void* const* d_in, const int* in_sizes, int n_in,
                              void* d_out, int out_size)
{
    (void)in_sizes; (void)n_in; (void)out_size;
    const int*   x        = (const int*)  d_in[0];
    const int*   lengths  = (const int*)  d_in[1];
    const float* embed_w  = (const float*)d_in[2];
    const float* c1w = (const float*)d_in[3];
    const float* c1b = (const float*)d_in[4];
    const float* c2w = (const float*)d_in[5];
    const float* c2b = (const float*)d_in[6];
    const float* c3w = (const float*)d_in[7];
    const float* c3b = (const float*)d_in[8];
    const float* wf  = (const float*)d_in[9];
    const float* bf  = (const float*)d_in[10];
    const float* wb  = (const float*)d_in[11];
    const float* bb  = (const float*)d_in[12];
    const float* s1 = (const float*)d_in[13]; const float* o1 = (const float*)d_in[14];
    const float* m1 = (const float*)d_in[15]; const float* v1 = (const float*)d_in[16];
    const float* s2 = (const float*)d_in[17]; const float* o2 = (const float*)d_in[18];
    const float* m2 = (const float*)d_in[19]; const float* v2 = (const float*)d_in[20];
    const float* s3 = (const float*)d_in[21]; const float* o3 = (const float*)d_in[22];
    const float* m3 = (const float*)d_in[23]; const float* v3 = (const float*)d_in[24];
    float* out = (float*)d_out;

    __nv_bfloat16 *aHi, *aLo, *bHi, *bLo, *wC, *wG;
    cudaGetSymbolAddress((void**)&aHi, g_aHi);
    cudaGetSymbolAddress((void**)&aLo, g_aLo);
    cudaGetSymbolAddress((void**)&bHi, g_bHi);
    cudaGetSymbolAddress((void**)&bLo, g_bLo);
    cudaGetSymbolAddress((void**)&wC, g_wConv);
    cudaGetSymbolAddress((void**)&wG, g_wGate);
    float* gpre;
    cudaGetSymbolAddress((void**)&gpre, g_gpre);

    const int SMEM_GEMM  = 65536;
    const int SMEM_RECUR = 32 * 514 * 8 + 512 * 36 * 4;   // 131584 + 73728 = 205312
    cudaFuncSetAttribute(mma_gemm_kernel,
                         cudaFuncAttributeMaxDynamicSharedMemorySize, SMEM_GEMM);
    cudaFuncSetAttribute(lstm_recur_kernel,
                         cudaFuncAttributeMaxDynamicSharedMemorySize, SMEM_RECUR);

    // launch order chosen so ncu (-s 5 -c 1) profiles the conv GEMM (launch #5)
    embed_kernel<<<MTOT, 128>>>(x, embed_w);                       // 0
    const int NWC = (DIM * 4608 + 255) / 256;
    wprep_conv_kernel<<<NWC, 256>>>(c1w, 0);                       // 1
    wprep_conv_kernel<<<NWC, 256>>>(c2w, 1);                       // 2
    wprep_conv_kernel<<<NWC, 256>>>(c3w, 2);                       // 3
    bnprep_kernel<<<1, 512>>>(c1b, s1, o1, m1, v1,
                              c2b, s2, o2, m2, v2,
                              c3b, s3, o3, m3, v3);                // 4

    dim3 gconv(MTOT / 128, DIM / 128);       // (256, 4)
    mma_gemm_kernel<<<gconv, 256, SMEM_GEMM>>>(aHi, aLo, wC + 0 * (size_t)DIM * 4608,
        4608, 1, 0, bHi, bLo, nullptr, nullptr);                   // 5  <-- profiled
    mma_gemm_kernel<<<gconv, 256, SMEM_GEMM>>>(bHi, bLo, wC + 1 * (size_t)DIM * 4608,
        4608, 1, 1, aHi, aLo, nullptr, nullptr);                   // 6
    mma_gemm_kernel<<<gconv, 256, SMEM_GEMM>>>(aHi, aLo, wC + 2 * (size_t)DIM * 4608,
        4608, 1, 2, bHi, bLo, nullptr, nullptr);                   // 7

    const int NWG = (GDIM * 1536 + 255) / 256;
    wprep_gate_kernel<<<NWG, 256>>>(wf, 0);                        // 8
    wprep_gate_kernel<<<NWG, 256>>>(wb, 1);                        // 9

    dim3 ggate(MTOT / 128, GDIM / 128);      // (256, 16)
    mma_gemm_kernel<<<ggate, 256, SMEM_GEMM>>>(bHi, bLo, wG + 0 * (size_t)GDIM * 1536,
        1536, 0, -1, nullptr, nullptr, bf, gpre + 0);              // 10
    mma_gemm_kernel<<<ggate, 256, SMEM_GEMM>>>(bHi, bLo, wG + 1 * (size_t)GDIM * 1536,
        1536, 0, -1, nullptr, nullptr, bb, gpre + (size_t)MTOT * GDIM);  // 11

    lstm_recur_kernel<<<GRID_BLOCKS, 256, SMEM_RECUR>>>(wf, wb, lengths, out);  // 12
}

// round 5
// speedup vs baseline: 1.3277x; 1.3277x over previous
#include <cuda_runtime.h>
#include <cuda_bf16.h>
#include <stdint.h>
#include <math.h>

#define BSZ   32
#define LSEQ  1024
#define DIM   512
#define MTOT  (BSZ*LSEQ)          // 32768
#define GDIM  2048                // 4*DIM
#define GRID_BLOCKS 128

// =================== scratch (device globals) ================================
__device__ __align__(128) __nv_bfloat16 g_aHi[(size_t)MTOT*DIM];
__device__ __align__(128) __nv_bfloat16 g_aLo[(size_t)MTOT*DIM];
__device__ __align__(128) __nv_bfloat16 g_bHi[(size_t)MTOT*DIM];
__device__ __align__(128) __nv_bfloat16 g_bLo[(size_t)MTOT*DIM];
// conv weights: [layer][tap*512 + n][k]   (k-major rows of 512 bf16)
__device__ __align__(128) __nv_bfloat16 g_wcHi[3][(size_t)3*DIM*DIM];
__device__ __align__(128) __nv_bfloat16 g_wcLo[3][(size_t)3*DIM*DIM];
// gate weights: [dir][n][k]
__device__ __align__(128) __nv_bfloat16 g_wgHi[2][(size_t)GDIM*DIM];
__device__ __align__(128) __nv_bfloat16 g_wgLo[2][(size_t)GDIM*DIM];
__device__ float g_gpre[2][(size_t)MTOT*GDIM];   // [dir][(t*32+b)*2048 + n]
__device__ float g_hstate[2][2][BSZ*DIM];        // [parity][dir][b*512+d]
__device__ float g_alpha[3][DIM];
__device__ float g_beta[3][DIM];
__device__ unsigned g_bar_arrive;
__device__ unsigned g_bar_gen;

// =================== primitives ===============================================
__device__ __forceinline__ uint32_t smem_to_u32(const void* p) {
    uint32_t a;
    asm("{ .reg .u64 t; cvta.to.shared.u64 t, %1; cvt.u32.u64 %0, t; }" : "=r"(a) : "l"(p));
    return a;
}
#define LDSM_X4(r0, r1, r2, r3, addr) \
    asm volatile("ldmatrix.sync.aligned.m8n8.x4.shared.b16 {%0,%1,%2,%3}, [%4];" \
        : "=r"(r0), "=r"(r1), "=r"(r2), "=r"(r3) : "r"(addr))
#define MMA16816(c, a, b) \
    asm volatile("mma.sync.aligned.m16n8k16.row.col.f32.bf16.bf16.f32 " \
        "{%0,%1,%2,%3}, {%4,%5,%6,%7}, {%8,%9}, {%0,%1,%2,%3};" \
        : "+f"((c)[0]), "+f"((c)[1]), "+f"((c)[2]), "+f"((c)[3]) \
        : "r"((a)[0]), "r"((a)[1]), "r"((a)[2]), "r"((a)[3]), \
          "r"((b)[0]), "r"((b)[1]))

__device__ __forceinline__ float sigmoidf_(float x) { return 1.0f / (1.0f + __expf(-x)); }

__device__ __forceinline__ void grid_sync_() {
    __threadfence();
    __syncthreads();
    if (threadIdx.x == 0) {
        unsigned cur = *(volatile unsigned*)&g_bar_gen;
        unsigned a = atomicAdd(&g_bar_arrive, 1u);
        if (a == GRID_BLOCKS - 1) {
            g_bar_arrive = 0u;
            __threadfence();
            atomicAdd(&g_bar_gen, 1u);
        } else {
            while (*(volatile unsigned*)&g_bar_gen == cur) { }
        }
    }
    __syncthreads();
}

// =================== BN fold =================================================
__global__ void bnprep_kernel(
    const float* __restrict__ b1, const float* __restrict__ s1, const float* __restrict__ o1,
    const float* __restrict__ m1, const float* __restrict__ v1,
    const float* __restrict__ b2, const float* __restrict__ s2, const float* __restrict__ o2,
    const float* __restrict__ m2, const float* __restrict__ v2,
    const float* __restrict__ b3, const float* __restrict__ s3, const float* __restrict__ o3,
    const float* __restrict__ m3, const float* __restrict__ v3)
{
    int i = threadIdx.x;
    if (i < DIM) {
        float g;
        g = s1[i] * rsqrtf(v1[i] + 1e-5f); g_alpha[0][i] = g; g_beta[0][i] = (b1[i] - m1[i]) * g + o1[i];
        g = s2[i] * rsqrtf(v2[i] + 1e-5f); g_alpha[1][i] = g; g_beta[1][i] = (b2[i] - m2[i]) * g + o2[i];
        g = s3[i] * rsqrtf(v3[i] + 1e-5f); g_alpha[2][i] = g; g_beta[2][i] = (b3[i] - m3[i]) * g + o3[i];
    }
}

// =================== weight prep ==============================================
__global__ void wprep_conv_kernel(const float* __restrict__ Wc, int layer)
{
    int idx = blockIdx.x * 256 + threadIdx.x;
    if (idx >= 3 * DIM * DIM) return;
    int tap = idx / (DIM * DIM);
    int rem = idx - tap * DIM * DIM;
    int n = rem / DIM, k = rem % DIM;
    float v = Wc[(size_t)(tap * DIM + k) * DIM + n];
    __nv_bfloat16 h = __float2bfloat16(v);
    __nv_bfloat16 l = __float2bfloat16(v - __bfloat162float(h));
    g_wcHi[layer][(size_t)(tap * DIM + n) * DIM + k] = h;
    g_wcLo[layer][(size_t)(tap * DIM + n) * DIM + k] = l;
}
__global__ void wprep_gate_kernel(const float* __restrict__ W, int dir)
{
    int idx = blockIdx.x * 256 + threadIdx.x;
    if (idx >= GDIM * DIM) return;
    int n = idx / DIM, k = idx % DIM;
    float v = W[(size_t)k * GDIM + n];
    __nv_bfloat16 h = __float2bfloat16(v);
    __nv_bfloat16 l = __float2bfloat16(v - __bfloat162float(h));
    g_wgHi[dir][idx] = h;
    g_wgLo[dir][idx] = l;
}

// =================== embedding -> bf16 hi/lo =================================
__global__ void embed_kernel(const int* __restrict__ x, const float* __restrict__ ew)
{
    int m = blockIdx.x;
    int tok = x[m];
    int j = threadIdx.x;                       // 0..127
    float4 v = ((const float4*)(ew + (size_t)tok * DIM))[j];
    float f[4] = {v.x, v.y, v.z, v.w};
    __nv_bfloat16 h[4], l[4];
    #pragma unroll
    for (int i = 0; i < 4; i++) {
        h[i] = __float2bfloat16(f[i]);
        l[i] = __float2bfloat16(f[i] - __bfloat162float(h[i]));
    }
    *(uint2*)(g_aHi + (size_t)m * DIM + j * 4) = *(uint2*)h;
    *(uint2*)(g_aLo + (size_t)m * DIM + j * 4) = *(uint2*)l;
}

// =================== bf16 mma.sync GEMM v2 ====================================
// taps=3 conv (A window 130 rows, B rows tap*512+n), taps=1 gates.
// Per K64-slice: A_hi/A_lo loaded once (single-buffered); per tap B_hi/B_lo
// double-buffered. acc += Ahi*Bhi + Alo*Bhi + Ahi*Blo.
// smem: Ahi[0,16640) Alo[16640,33280) Bstage{0,1}: 33280+s*32768 {hi,lo 16384 each}
__global__ void __launch_bounds__(256) mma_gemm_kernel(
    const __nv_bfloat16* __restrict__ Ahi, const __nv_bfloat16* __restrict__ Alo,
    const __nv_bfloat16* __restrict__ BwHi, const __nv_bfloat16* __restrict__ BwLo,
    int taps, int layer,
    __nv_bfloat16* __restrict__ outHi, __nv_bfloat16* __restrict__ outLo,
    const float* __restrict__ bias, float* __restrict__ gout)
{
    extern __shared__ char smem[];
    const int tid = threadIdx.x;
    const int lane = tid & 31, wid = tid >> 5;
    const int wm = wid & 3, wn = wid >> 2;
    const int m0 = blockIdx.x * 128, n0 = blockIdx.y * 128;
    const int t0 = m0 & (LSEQ - 1);
    const uint32_t sb = smem_to_u32(smem);

    const int off0  = taps >> 1;            // 1 for conv, 0 for gates
    const int arows = 128 + (taps - 1);     // 130 / 128

    float acc[2][8][4];
    #pragma unroll
    for (int a = 0; a < 2; a++)
        #pragma unroll
        for (int b = 0; b < 8; b++)
            #pragma unroll
            for (int c = 0; c < 4; c++) acc[a][b][c] = 0.f;

    // ---- copy helpers ----
    #define COPY_A(SLICE) do { \
        const int _kb = (SLICE) << 6; \
        const int _tot = arows * 8; \
        for (int _i = tid; _i < _tot; _i += 256) { \
            int _r = _i >> 3, _c8 = (_i & 7) << 3; \
            uint32_t _off = (uint32_t)(_r * 128) + (((uint32_t)_c8 * 2) ^ (((uint32_t)_r & 7) << 4)); \
            int _tl = t0 + _r - off0; \
            uint4 _vh = make_uint4(0u,0u,0u,0u), _vl = _vh; \
            if (_tl >= 0 && _tl < LSEQ) { \
                size_t _ga = (size_t)(m0 + _r - off0) * DIM + _kb + _c8; \
                _vh = *(const uint4*)(Ahi + _ga); \
                _vl = *(const uint4*)(Alo + _ga); \
            } \
            *(uint4*)(smem + _off) = _vh; \
            *(uint4*)(smem + 16640 + _off) = _vl; \
        } \
    } while (0)

    #define COPY_B(IDX, ST) do { \
        const int _sl = (IDX) / taps, _tp = (IDX) % taps; \
        const int _kb = _sl << 6; \
        const int _rbase = (taps == 3 ? _tp * DIM : 0) + n0; \
        char* _bp = smem + 33280 + (ST) * 32768; \
        for (int _i = tid; _i < 1024; _i += 256) { \
            int _r = _i >> 3, _c8 = (_i & 7) << 3; \
            uint32_t _off = (uint32_t)(_r * 128) + (((uint32_t)_c8 * 2) ^ (((uint32_t)_r & 7) << 4)); \
            size_t _ga = (size_t)(_rbase + _r) * DIM + _kb + _c8; \
            *(uint4*)(_bp + _off) = *(const uint4*)(BwHi + _ga); \
            *(uint4*)(_bp + 16384 + _off) = *(const uint4*)(BwLo + _ga); \
        } \
    } while (0)

    const int NB = 8 * taps;
    COPY_A(0);
    COPY_B(0, 0);
    __syncthreads();

    for (int idx = 0; idx < NB; idx++) {
        const int tap = idx % taps;
        const int bsel = idx & 1;
        const bool lastTap = (tap == taps - 1);

        if (idx + 1 < NB) COPY_B(idx + 1, bsel ^ 1);

        // ---- compute: 4 k16 steps over this K64 slice, 3 term-combos ----
        const uint32_t aHiB = sb;
        const uint32_t aLoB = sb + 16640;
        const uint32_t bHiB = sb + 33280 + (uint32_t)bsel * 32768;
        const uint32_t bLoB = bHiB + 16384;
        #pragma unroll
        for (int k16 = 0; k16 < 4; k16++) {
            const uint32_t colA = (uint32_t)(k16 * 32) + (((uint32_t)lane >> 4) << 4);
            const uint32_t colB = (uint32_t)(k16 * 32) + ((((uint32_t)lane >> 3) & 1) << 4);
            uint32_t afh[2][4], afl[2][4];
            #pragma unroll
            for (int mt = 0; mt < 2; mt++) {
                uint32_t row = (uint32_t)(wm * 32 + mt * 16 + (lane & 15) + tap);
                uint32_t ad = row * 128 + (colA ^ ((row & 7) << 4));
                LDSM_X4(afh[mt][0], afh[mt][1], afh[mt][2], afh[mt][3], aHiB + ad);
                LDSM_X4(afl[mt][0], afl[mt][1], afl[mt][2], afl[mt][3], aLoB + ad);
            }
            // process N in two halves to bound register pressure
            #pragma unroll
            for (int half = 0; half < 2; half++) {
                uint32_t bfh[4][2], bfl[4][2];
                #pragma unroll
                for (int np = 0; np < 2; np++) {
                    uint32_t row = (uint32_t)(wn * 64 + (half * 2 + np) * 16 +
                                              (((lane >> 4) << 3) | (lane & 7)));
                    uint32_t bd = row * 128 + (colB ^ ((row & 7) << 4));
                    LDSM_X4(bfh[2*np][0], bfh[2*np][1], bfh[2*np+1][0], bfh[2*np+1][1], bHiB + bd);
                    LDSM_X4(bfl[2*np][0], bfl[2*np][1], bfl[2*np+1][0], bfl[2*np+1][1], bLoB + bd);
                }
                #pragma unroll
                for (int mt = 0; mt < 2; mt++)
                    #pragma unroll
                    for (int nt = 0; nt < 4; nt++) {
                        float* ac = acc[mt][half * 4 + nt];
                        MMA16816(ac, afh[mt], bfh[nt]);
                        MMA16816(ac, afl[mt], bfh[nt]);
                        MMA16816(ac, afh[mt], bfl[nt]);
                    }
            }
        }
        __syncthreads();
        if (lastTap && idx + 1 < NB) {
            COPY_A((idx + 1) / taps);
            __syncthreads();
        }
    }
    #undef COPY_A
    #undef COPY_B

    // ---- epilogue ----
    const int g  = lane >> 2;
    const int tg = lane & 3;
    if (gout == nullptr) {            // conv: BN + ReLU + bf16 hi/lo split
        #pragma unroll
        for (int mt = 0; mt < 2; mt++) {
            const int mlo = m0 + wm * 32 + mt * 16 + g;
            const int mhi = mlo + 8;
            #pragma unroll
            for (int nt = 0; nt < 8; nt++) {
                const int n = n0 + wn * 64 + nt * 8 + tg * 2;
                const float al0 = g_alpha[layer][n],     be0 = g_beta[layer][n];
                const float al1 = g_alpha[layer][n + 1], be1 = g_beta[layer][n + 1];
                float v00 = fmaxf(fmaf(acc[mt][nt][0], al0, be0), 0.f);
                float v01 = fmaxf(fmaf(acc[mt][nt][1], al1, be1), 0.f);
                float v10 = fmaxf(fmaf(acc[mt][nt][2], al0, be0), 0.f);
                float v11 = fmaxf(fmaf(acc[mt][nt][3], al1, be1), 0.f);
                __nv_bfloat16 h00 = __float2bfloat16(v00), h01 = __float2bfloat16(v01);
                __nv_bfloat16 h10 = __float2bfloat16(v10), h11 = __float2bfloat16(v11);
                __nv_bfloat16 l00 = __float2bfloat16(v00 - __bfloat162float(h00));
                __nv_bfloat16 l01 = __float2bfloat16(v01 - __bfloat162float(h01));
                __nv_bfloat16 l10 = __float2bfloat16(v10 - __bfloat162float(h10));
                __nv_bfloat16 l11 = __float2bfloat16(v11 - __bfloat162float(h11));
                __nv_bfloat162 ph0; ph0.x = h00; ph0.y = h01;
                __nv_bfloat162 ph1; ph1.x = h10; ph1.y = h11;
                __nv_bfloat162 pl0; pl0.x = l00; pl0.y = l01;
                __nv_bfloat162 pl1; pl1.x = l10; pl1.y = l11;
                *(__nv_bfloat162*)(outHi + (size_t)mlo * DIM + n) = ph0;
                *(__nv_bfloat162*)(outHi + (size_t)mhi * DIM + n) = ph1;
                *(__nv_bfloat162*)(outLo + (size_t)mlo * DIM + n) = pl0;
                *(__nv_bfloat162*)(outLo + (size_t)mhi * DIM + n) = pl1;
            }
        }
    } else {                          // gates: +bias, fp32 time-major
        #pragma unroll
        for (int mt = 0; mt < 2; mt++) {
            const int mlo = m0 + wm * 32 + mt * 16 + g;
            const int mhi = mlo + 8;
            const int blo = mlo >> 10, tlo = mlo & (LSEQ - 1);
            const int bhi = mhi >> 10, thi = mhi & (LSEQ - 1);
            #pragma unroll
            for (int nt = 0; nt < 8; nt++) {
                const int n = n0 + wn * 64 + nt * 8 + tg * 2;
                const float b0 = bias[n], b1 = bias[n + 1];
                float2 o0, o1;
                o0.x = acc[mt][nt][0] + b0; o0.y = acc[mt][nt][1] + b1;
                o1.x = acc[mt][nt][2] + b0; o1.y = acc[mt][nt][3] + b1;
                *(float2*)(gout + ((size_t)(tlo << 5) + blo) * GDIM + n) = o0;
                *(float2*)(gout + ((size_t)(thi << 5) + bhi) * GDIM + n) = o1;
            }
        }
    }
}

// =================== persistent bidirectional LSTM recurrence (R3 proven) ====
__global__ void __launch_bounds__(256, 1) lstm_recur_kernel(
    const float* __restrict__ wf, const float* __restrict__ wb,
    const int* __restrict__ lengths, float* __restrict__ out)
{
    extern __shared__ float sm[];
    float* Wt = sm;               // [32][516]
    float* hs = sm + 32 * 516;    // [32][516]
    __shared__ int len_s[32];

    const int tid = threadIdx.x;
    const int dir = blockIdx.x >> 6;
    const int dc  = (blockIdx.x & 63) << 3;
    const float* w = dir ? wb : wf;

    for (int idx = tid; idx < 32 * 512; idx += 256) {
        int nl = idx & 31;
        int k  = idx >> 5;
        int c  = ((nl >> 3) << 9) + dc + (nl & 7);
        Wt[nl * 516 + k] = w[(size_t)(512 + k) * GDIM + c];
    }
    if (tid < 32) len_s[tid] = lengths[tid];
    {
        int b = tid >> 3, j = tid & 7;
        g_hstate[0][dir][b * DIM + dc + j] = 0.f;
    }
    grid_sync_();

    const int tx = tid & 31;
    const int ty = tid >> 5;
    const int jd = tx & 7;
    const int col = ((tx >> 3) << 9) + dc + jd;
    const float* gpre = g_gpre[dir];
    const float* wrow = Wt + tx * 516;
    const unsigned FULL = 0xffffffffu;

    float c0 = 0.f, c1 = 0.f, c2 = 0.f, c3 = 0.f;

    for (int s = 0; s < LSEQ; s++) {
        const int t = dir ? (LSEQ - 1 - s) : s;
        const int p = s & 1;
        const float4* hp4 = (const float4*)g_hstate[p][dir];
        float* hn = g_hstate[p ^ 1][dir];

        #pragma unroll
        for (int i = 0; i < 16; i++) {
            int idx4 = i * 256 + tid;
            int b = idx4 >> 7, kc = idx4 & 127;
            float4 v = __ldcg(hp4 + idx4);
            if (dir && t >= len_s[b] - 1) v = make_float4(0.f, 0.f, 0.f, 0.f);
            *(float4*)(hs + b * 516 + (kc << 2)) = v;
        }
        __syncthreads();

        const float* h0p = hs + (size_t)(ty     ) * 516;
        const float* h1p = hs + (size_t)(ty +  8) * 516;
        const float* h2p = hs + (size_t)(ty + 16) * 516;
        const float* h3p = hs + (size_t)(ty + 24) * 516;
        float a0 = 0.f, a1 = 0.f, a2 = 0.f, a3 = 0.f;
        #pragma unroll 4
        for (int kc = 0; kc < 128; kc++) {
            float4 wv = *(const float4*)(wrow + (kc << 2));
            float4 x0 = *(const float4*)(h0p + (kc << 2));
            float4 x1 = *(const float4*)(h1p + (kc << 2));
            float4 x2 = *(const float4*)(h2p + (kc << 2));
            float4 x3 = *(const float4*)(h3p + (kc << 2));
            a0 = fmaf(wv.x, x0.x, fmaf(wv.y, x0.y, fmaf(wv.z, x0.z, fmaf(wv.w, x0.w, a0))));
            a1 = fmaf(wv.x, x1.x, fmaf(wv.y, x1.y, fmaf(wv.z, x1.z, fmaf(wv.w, x1.w, a1))));
            a2 = fmaf(wv.x, x2.x, fmaf(wv.y, x2.y, fmaf(wv.z, x2.z, fmaf(wv.w, x2.w, a2))));
            a3 = fmaf(wv.x, x3.x, fmaf(wv.y, x3.y, fmaf(wv.z, x3.z, fmaf(wv.w, x3.w, a3))));
        }

        const float* gp = gpre + (size_t)(t << 5) * GDIM + col;
        float p0 = a0 + __ldg(gp + (size_t)(ty     ) * GDIM);
        float p1 = a1 + __ldg(gp + (size_t)(ty +  8) * GDIM);
        float p2 = a2 + __ldg(gp + (size_t)(ty + 16) * GDIM);
        float p3 = a3 + __ldg(gp + (size_t)(ty + 24) * GDIM);

        float vi0 = __shfl_sync(FULL, p0, jd),      vi1 = __shfl_sync(FULL, p1, jd);
        float vi2 = __shfl_sync(FULL, p2, jd),      vi3 = __shfl_sync(FULL, p3, jd);
        float vg0 = __shfl_sync(FULL, p0, jd + 8),  vg1 = __shfl_sync(FULL, p1, jd + 8);
        float vg2 = __shfl_sync(FULL, p2, jd + 8),  vg3 = __shfl_sync(FULL, p3, jd + 8);
        float vf0 = __shfl_sync(FULL, p0, jd + 16), vf1 = __shfl_sync(FULL, p1, jd + 16);
        float vf2 = __shfl_sync(FULL, p2, jd + 16), vf3 = __shfl_sync(FULL, p3, jd + 16);
        float vo0 = __shfl_sync(FULL, p0, jd + 24), vo1 = __shfl_sync(FULL, p1, jd + 24);
        float vo2 = __shfl_sync(FULL, p2, jd + 24), vo3 = __shfl_sync(FULL, p3, jd + 24);

        if (tx < 8) {
            const int d = dc + tx;
            {
                int b = ty;
                float cc = (dir && t >= len_s[b] - 1) ? 0.f : c0;
                cc = sigmoidf_(vf0 + 1.f) * cc + sigmoidf_(vi0) * tanhf(vg0);
                c0 = cc;
                float hh = sigmoidf_(vo0) * tanhf(cc);
                hn[b * DIM + d] = hh;
                out[(((size_t)b << 10) + t) * 1024 + (dir << 9) + d] = hh;
            }
            {
                int b = ty + 8;
                float cc = (dir && t >= len_s[b] - 1) ? 0.f : c1;
                cc = sigmoidf_(vf1 + 1.f) * cc + sigmoidf_(vi1) * tanhf(vg1);
                c1 = cc;
                float hh = sigmoidf_(vo1) * tanhf(cc);
                hn[b * DIM + d] = hh;
                out[(((size_t)b << 10) + t) * 1024 + (dir << 9) + d] = hh;
            }
            {
                int b = ty + 16;
                float cc = (dir && t >= len_s[b] - 1) ? 0.f : c2;
                cc = sigmoidf_(vf2 + 1.f) * cc + sigmoidf_(vi2) * tanhf(vg2);
                c2 = cc;
                float hh = sigmoidf_(vo2) * tanhf(cc);
                hn[b * DIM + d] = hh;
                out[(((size_t)b << 10) + t) * 1024 + (dir << 9) + d] = hh;
            }
            {
                int b = ty + 24;
                float cc = (dir && t >= len_s[b] - 1) ? 0.f : c3;
                cc = sigmoidf_(vf3 + 1.f) * cc + sigmoidf_(vi3) * tanhf(vg3);
                c3 = cc;
                float hh = sigmoidf_(vo3) * tanhf(cc);
                hn[b * DIM + d] = hh;
                out[(((size_t)b << 10) + t) * 1024 + (dir << 9) + d] = hh;
            }
        }
        grid_sync_();
    }
}

// =================== launch ===================================================
extern "C" void kernel_launch(void* const* d_in, const int* in_sizes, int n_in,
                              void* d_out, int out_size)
{
    (void)in_sizes; (void)n_in; (void)out_size;
    const int*   x        = (const int*)  d_in[0];
    const int*   lengths  = (const int*)  d_in[1];
    const float* embed_w  = (const float*)d_in[2];
    const float* c1w = (const float*)d_in[3];
    const float* c1b = (const float*)d_in[4];
    const float* c2w = (const float*)d_in[5];
    const float* c2b = (const float*)d_in[6];
    const float* c3w = (const float*)d_in[7];
    const float* c3b = (const float*)d_in[8];
    const float* wf  = (const float*)d_in[9];
    const float* bf  = (const float*)d_in[10];
    const float* wb  = (const float*)d_in[11];
    const float* bb  = (const float*)d_in[12];
    const float* s1 = (const float*)d_in[13]; const float* o1 = (const float*)d_in[14];
    const float* m1 = (const float*)d_in[15]; const float* v1 = (const float*)d_in[16];
    const float* s2 = (const float*)d_in[17]; const float* o2 = (const float*)d_in[18];
    const float* m2 = (const float*)d_in[19]; const float* v2 = (const float*)d_in[20];
    const float* s3 = (const float*)d_in[21]; const float* o3 = (const float*)d_in[22];
    const float* m3 = (const float*)d_in[23]; const float* v3 = (const float*)d_in[24];
    float* out = (float*)d_out;

    __nv_bfloat16 *aHi, *aLo, *bHi, *bLo, *wcH, *wcL, *wgH, *wgL;
    cudaGetSymbolAddress((void**)&aHi, g_aHi);
    cudaGetSymbolAddress((void**)&aLo, g_aLo);
    cudaGetSymbolAddress((void**)&bHi, g_bHi);
    cudaGetSymbolAddress((void**)&bLo, g_bLo);
    cudaGetSymbolAddress((void**)&wcH, g_wcHi);
    cudaGetSymbolAddress((void**)&wcL, g_wcLo);
    cudaGetSymbolAddress((void**)&wgH, g_wgHi);
    cudaGetSymbolAddress((void**)&wgL, g_wgLo);
    float* gpre;
    cudaGetSymbolAddress((void**)&gpre, g_gpre);

    const size_t WC = (size_t)3 * DIM * DIM;      // per conv layer
    const size_t WG = (size_t)GDIM * DIM;         // per direction

    const int SMEM_GEMM  = 33280 + 2 * 32768;     // 98816
    const int SMEM_RECUR = 2 * 32 * 516 * (int)sizeof(float);
    cudaFuncSetAttribute(mma_gemm_kernel,
                         cudaFuncAttributeMaxDynamicSharedMemorySize, SMEM_GEMM);
    cudaFuncSetAttribute(lstm_recur_kernel,
                         cudaFuncAttributeMaxDynamicSharedMemorySize, SMEM_RECUR);

    dim3 gconv(MTOT / 128, DIM / 128);       // (256, 4)
    dim3 ggate(MTOT / 128, GDIM / 128);      // (256, 16)
    const int NWC = (3 * DIM * DIM + 255) / 256;
    const int NWG = (GDIM * DIM + 255) / 256;

    // order: conv GEMMs at overall launch index 3 and 5 (catches ncu -s 5
    // offsets of both 2 and 0 observed in prior rounds)
    wprep_conv_kernel<<<NWC, 256>>>(c1w, 0);                                  // 0
    bnprep_kernel<<<1, 512>>>(c1b, s1, o1, m1, v1,
                              c2b, s2, o2, m2, v2,
                              c3b, s3, o3, m3, v3);                           // 1
    embed_kernel<<<MTOT, 128>>>(x, embed_w);                                  // 2
    mma_gemm_kernel<<<gconv, 256, SMEM_GEMM>>>(aHi, aLo, wcH + 0 * WC, wcL + 0 * WC,
        3, 0, bHi, bLo, nullptr, nullptr);                                    // 3
    wprep_conv_kernel<<<NWC, 256>>>(c2w, 1);                                  // 4
    mma_gemm_kernel<<<gconv, 256, SMEM_GEMM>>>(bHi, bLo, wcH + 1 * WC, wcL + 1 * WC,
        3, 1, aHi, aLo, nullptr, nullptr);                                    // 5
    wprep_conv_kernel<<<NWC, 256>>>(c3w, 2);                                  // 6
    mma_gemm_kernel<<<gconv, 256, SMEM_GEMM>>>(aHi, aLo, wcH + 2 * WC, wcL + 2 * WC,
        3, 2, bHi, bLo, nullptr, nullptr);                                    // 7
    wprep_gate_kernel<<<NWG, 256>>>(wf, 0);                                   // 8
    wprep_gate_kernel<<<NWG, 256>>>(wb, 1);                                   // 9
    mma_gemm_kernel<<<ggate, 256, SMEM_GEMM>>>(bHi, bLo, wgH + 0 * WG, wgL + 0 * WG,
        1, -1, nullptr, nullptr, bf, gpre + 0);                               // 10
    mma_gemm_kernel<<<ggate, 256, SMEM_GEMM>>>(bHi, bLo, wgH + 1 * WG, wgL + 1 * WG,
        1, -1, nullptr, nullptr, bb, gpre + (size_t)MTOT * GDIM);             // 11
    lstm_recur_kernel<<<GRID_BLOCKS, 256, SMEM_RECUR>>>(wf, wb, lengths, out);// 12
}

// round 6
// speedup vs baseline: 1.8705x; 1.4088x over previous
#include <cuda_runtime.h>
#include <cuda_bf16.h>
#include <stdint.h>
#include <math.h>

#define BSZ   32
#define LSEQ  1024
#define DIM   512
#define MTOT  (BSZ*LSEQ)          // 32768
#define GDIM  2048                // 4*DIM
#define GRID_BLOCKS 128

// =================== scratch (device globals) ================================
__device__ __align__(128) __nv_bfloat16 g_aHi[(size_t)MTOT*DIM];
__device__ __align__(128) __nv_bfloat16 g_aLo[(size_t)MTOT*DIM];
__device__ __align__(128) __nv_bfloat16 g_bHi[(size_t)MTOT*DIM];
__device__ __align__(128) __nv_bfloat16 g_bLo[(size_t)MTOT*DIM];
__device__ __align__(128) __nv_bfloat16 g_wcHi[3][(size_t)3*DIM*DIM];   // [layer][tap*512+n][k]
__device__ __align__(128) __nv_bfloat16 g_wcLo[3][(size_t)3*DIM*DIM];
__device__ __align__(128) __nv_bfloat16 g_wgHi[2][(size_t)GDIM*DIM];    // [dir][n][k]
__device__ __align__(128) __nv_bfloat16 g_wgLo[2][(size_t)GDIM*DIM];
__device__ float g_gpre[2][(size_t)MTOT*GDIM];   // [dir][ (t*2048 + col)*32 + b ]
__device__ unsigned g_hpk[2][2][BSZ*DIM];        // [parity][dir][b*512+d] packed (hi|lo<<16)
__device__ float g_alpha[3][DIM];
__device__ float g_beta[3][DIM];
__device__ unsigned g_bar_arrive;
__device__ unsigned g_bar_gen;

// =================== primitives ===============================================
__device__ __forceinline__ uint32_t smem_to_u32(const void* p) {
    uint32_t a;
    asm("{ .reg .u64 t; cvta.to.shared.u64 t, %1; cvt.u32.u64 %0, t; }" : "=r"(a) : "l"(p));
    return a;
}
#define LDSM_X4(r0, r1, r2, r3, addr) \
    asm volatile("ldmatrix.sync.aligned.m8n8.x4.shared.b16 {%0,%1,%2,%3}, [%4];" \
        : "=r"(r0), "=r"(r1), "=r"(r2), "=r"(r3) : "r"(addr))
#define MMA16816(c, a, b) \
    asm volatile("mma.sync.aligned.m16n8k16.row.col.f32.bf16.bf16.f32 " \
        "{%0,%1,%2,%3}, {%4,%5,%6,%7}, {%8,%9}, {%0,%1,%2,%3};" \
        : "+f"((c)[0]), "+f"((c)[1]), "+f"((c)[2]), "+f"((c)[3]) \
        : "r"((a)[0]), "r"((a)[1]), "r"((a)[2]), "r"((a)[3]), \
          "r"((b)[0]), "r"((b)[1]))

__device__ __forceinline__ float sigmoidf_(float x) { return 1.0f / (1.0f + __expf(-x)); }

__device__ __forceinline__ void grid_sync_() {
    __threadfence();
    __syncthreads();
    if (threadIdx.x == 0) {
        unsigned cur = *(volatile unsigned*)&g_bar_gen;
        unsigned a = atomicAdd(&g_bar_arrive, 1u);
        if (a == GRID_BLOCKS - 1) {
            g_bar_arrive = 0u;
            __threadfence();
            atomicAdd(&g_bar_gen, 1u);
        } else {
            while (*(volatile unsigned*)&g_bar_gen == cur) { }
        }
    }
    __syncthreads();
}

// =================== BN fold =================================================
__global__ void bnprep_kernel(
    const float* __restrict__ b1, const float* __restrict__ s1, const float* __restrict__ o1,
    const float* __restrict__ m1, const float* __restrict__ v1,
    const float* __restrict__ b2, const float* __restrict__ s2, const float* __restrict__ o2,
    const float* __restrict__ m2, const float* __restrict__ v2,
    const float* __restrict__ b3, const float* __restrict__ s3, const float* __restrict__ o3,
    const float* __restrict__ m3, const float* __restrict__ v3)
{
    int i = threadIdx.x;
    if (i < DIM) {
        float g;
        g = s1[i] * rsqrtf(v1[i] + 1e-5f); g_alpha[0][i] = g; g_beta[0][i] = (b1[i] - m1[i]) * g + o1[i];
        g = s2[i] * rsqrtf(v2[i] + 1e-5f); g_alpha[1][i] = g; g_beta[1][i] = (b2[i] - m2[i]) * g + o2[i];
        g = s3[i] * rsqrtf(v3[i] + 1e-5f); g_alpha[2][i] = g; g_beta[2][i] = (b3[i] - m3[i]) * g + o3[i];
    }
}

// =================== weight prep ==============================================
__global__ void wprep_conv_kernel(const float* __restrict__ Wc, int layer)
{
    int idx = blockIdx.x * 256 + threadIdx.x;
    if (idx >= 3 * DIM * DIM) return;
    int tap = idx / (DIM * DIM);
    int rem = idx - tap * DIM * DIM;
    int n = rem / DIM, k = rem % DIM;
    float v = Wc[(size_t)(tap * DIM + k) * DIM + n];
    __nv_bfloat16 h = __float2bfloat16(v);
    __nv_bfloat16 l = __float2bfloat16(v - __bfloat162float(h));
    g_wcHi[layer][(size_t)(tap * DIM + n) * DIM + k] = h;
    g_wcLo[layer][(size_t)(tap * DIM + n) * DIM + k] = l;
}
// gates: input rows k<512 go to g_wgHi/Lo[n][k] for the GEMM; recurrent rows
// (k in [512,1024)) go to the SAME arrays at column offset? No — separate call:
// recurrent weights prepped into the same [n][k] layout from rows 512+k.
__global__ void wprep_gate_kernel(const float* __restrict__ W, int dir, int krow0,
                                  __nv_bfloat16* __restrict__ dstHi,
                                  __nv_bfloat16* __restrict__ dstLo)
{
    int idx = blockIdx.x * 256 + threadIdx.x;
    if (idx >= GDIM * DIM) return;
    int n = idx / DIM, k = idx % DIM;
    float v = W[(size_t)(krow0 + k) * GDIM + n];
    __nv_bfloat16 h = __float2bfloat16(v);
    __nv_bfloat16 l = __float2bfloat16(v - __bfloat162float(h));
    dstHi[idx] = h;
    dstLo[idx] = l;
}
__device__ __align__(128) __nv_bfloat16 g_wrHi[2][(size_t)GDIM*DIM];  // recurrent W
__device__ __align__(128) __nv_bfloat16 g_wrLo[2][(size_t)GDIM*DIM];

// =================== embedding -> bf16 hi/lo =================================
__global__ void embed_kernel(const int* __restrict__ x, const float* __restrict__ ew)
{
    int m = blockIdx.x;
    int tok = x[m];
    int j = threadIdx.x;
    float4 v = ((const float4*)(ew + (size_t)tok * DIM))[j];
    float f[4] = {v.x, v.y, v.z, v.w};
    __nv_bfloat16 h[4], l[4];
    #pragma unroll
    for (int i = 0; i < 4; i++) {
        h[i] = __float2bfloat16(f[i]);
        l[i] = __float2bfloat16(f[i] - __bfloat162float(h[i]));
    }
    *(uint2*)(g_aHi + (size_t)m * DIM + j * 4) = *(uint2*)h;
    *(uint2*)(g_aLo + (size_t)m * DIM + j * 4) = *(uint2*)l;
}

// =================== bf16 mma.sync GEMM (R5 engine, gates layout changed) =====
__global__ void __launch_bounds__(256) mma_gemm_kernel(
    const __nv_bfloat16* __restrict__ Ahi, const __nv_bfloat16* __restrict__ Alo,
    const __nv_bfloat16* __restrict__ BwHi, const __nv_bfloat16* __restrict__ BwLo,
    int taps, int layer,
    __nv_bfloat16* __restrict__ outHi, __nv_bfloat16* __restrict__ outLo,
    const float* __restrict__ bias, float* __restrict__ gout)
{
    extern __shared__ char smem[];
    const int tid = threadIdx.x;
    const int lane = tid & 31, wid = tid >> 5;
    const int wm = wid & 3, wn = wid >> 2;
    const int m0 = blockIdx.x * 128, n0 = blockIdx.y * 128;
    const int t0 = m0 & (LSEQ - 1);
    const uint32_t sb = smem_to_u32(smem);

    const int off0  = taps >> 1;
    const int arows = 128 + (taps - 1);

    float acc[2][8][4];
    #pragma unroll
    for (int a = 0; a < 2; a++)
        #pragma unroll
        for (int b = 0; b < 8; b++)
            #pragma unroll
            for (int c = 0; c < 4; c++) acc[a][b][c] = 0.f;

    #define DO_COPY_A(SLICE) do { \
        const int _kb = (SLICE) << 6; \
        const int _tot = arows * 8; \
        for (int _i = tid; _i < _tot; _i += 256) { \
            int _r = _i >> 3, _c8 = (_i & 7) << 3; \
            uint32_t _off = (uint32_t)(_r * 128) + (((uint32_t)_c8 * 2) ^ (((uint32_t)_r & 7) << 4)); \
            int _tl = t0 + _r - off0; \
            uint4 _vh = make_uint4(0u,0u,0u,0u), _vl = _vh; \
            if (_tl >= 0 && _tl < LSEQ) { \
                size_t _ga = (size_t)(m0 + _r - off0) * DIM + _kb + _c8; \
                _vh = *(const uint4*)(Ahi + _ga); \
                _vl = *(const uint4*)(Alo + _ga); \
            } \
            *(uint4*)(smem + _off) = _vh; \
            *(uint4*)(smem + 16640 + _off) = _vl; \
        } \
    } while (0)

    #define DO_COPY_B(IDX, ST) do { \
        const int _sl = (IDX) / taps, _tp = (IDX) % taps; \
        const int _kb = _sl << 6; \
        const int _rbase = (taps == 3 ? _tp * DIM : 0) + n0; \
        char* _bp = smem + 33280 + (ST) * 32768; \
        for (int _i = tid; _i < 1024; _i += 256) { \
            int _r = _i >> 3, _c8 = (_i & 7) << 3; \
            uint32_t _off = (uint32_t)(_r * 128) + (((uint32_t)_c8 * 2) ^ (((uint32_t)_r & 7) << 4)); \
            size_t _ga = (size_t)(_rbase + _r) * DIM + _kb + _c8; \
            *(uint4*)(_bp + _off) = *(const uint4*)(BwHi + _ga); \
            *(uint4*)(_bp + 16384 + _off) = *(const uint4*)(BwLo + _ga); \
        } \
    } while (0)

    const int NB = 8 * taps;
    DO_COPY_A(0);
    DO_COPY_B(0, 0);
    __syncthreads();

    for (int idx = 0; idx < NB; idx++) {
        const int tap = idx % taps;
        const int bsel = idx & 1;
        const bool lastTap = (tap == taps - 1);

        if (idx + 1 < NB) DO_COPY_B(idx + 1, bsel ^ 1);

        const uint32_t aHiB = sb;
        const uint32_t aLoB = sb + 16640;
        const uint32_t bHiB = sb + 33280 + (uint32_t)bsel * 32768;
        const uint32_t bLoB = bHiB + 16384;
        #pragma unroll
        for (int k16 = 0; k16 < 4; k16++) {
            const uint32_t colA = (uint32_t)(k16 * 32) + (((uint32_t)lane >> 4) << 4);
            const uint32_t colB = (uint32_t)(k16 * 32) + ((((uint32_t)lane >> 3) & 1) << 4);
            uint32_t afh[2][4], afl[2][4];
            #pragma unroll
            for (int mt = 0; mt < 2; mt++) {
                uint32_t row = (uint32_t)(wm * 32 + mt * 16 + (lane & 15) + tap);
                uint32_t ad = row * 128 + (colA ^ ((row & 7) << 4));
                LDSM_X4(afh[mt][0], afh[mt][1], afh[mt][2], afh[mt][3], aHiB + ad);
                LDSM_X4(afl[mt][0], afl[mt][1], afl[mt][2], afl[mt][3], aLoB + ad);
            }
            #pragma unroll
            for (int half = 0; half < 2; half++) {
                uint32_t bfh[4][2], bfl[4][2];
                #pragma unroll
                for (int np = 0; np < 2; np++) {
                    uint32_t row = (uint32_t)(wn * 64 + (half * 2 + np) * 16 +
                                              (((lane >> 4) << 3) | (lane & 7)));
                    uint32_t bd = row * 128 + (colB ^ ((row & 7) << 4));
                    LDSM_X4(bfh[2*np][0], bfh[2*np][1], bfh[2*np+1][0], bfh[2*np+1][1], bHiB + bd);
                    LDSM_X4(bfl[2*np][0], bfl[2*np][1], bfl[2*np+1][0], bfl[2*np+1][1], bLoB + bd);
                }
                #pragma unroll
                for (int mt = 0; mt < 2; mt++)
                    #pragma unroll
                    for (int nt = 0; nt < 4; nt++) {
                        float* ac = acc[mt][half * 4 + nt];
                        MMA16816(ac, afh[mt], bfh[nt]);
                        MMA16816(ac, afl[mt], bfh[nt]);
                        MMA16816(ac, afh[mt], bfl[nt]);
                    }
            }
        }
        __syncthreads();
        if (lastTap && idx + 1 < NB) {
            DO_COPY_A((idx + 1) / taps);
            __syncthreads();
        }
    }
    #undef DO_COPY_A
    #undef DO_COPY_B

    const int g  = lane >> 2;
    const int tg = lane & 3;
    if (gout == nullptr) {            // conv epilogue
        #pragma unroll
        for (int mt = 0; mt < 2; mt++) {
            const int mlo = m0 + wm * 32 + mt * 16 + g;
            const int mhi = mlo + 8;
            #pragma unroll
            for (int nt = 0; nt < 8; nt++) {
                const int n = n0 + wn * 64 + nt * 8 + tg * 2;
                const float al0 = g_alpha[layer][n],     be0 = g_beta[layer][n];
                const float al1 = g_alpha[layer][n + 1], be1 = g_beta[layer][n + 1];
                float v00 = fmaxf(fmaf(acc[mt][nt][0], al0, be0), 0.f);
                float v01 = fmaxf(fmaf(acc[mt][nt][1], al1, be1), 0.f);
                float v10 = fmaxf(fmaf(acc[mt][nt][2], al0, be0), 0.f);
                float v11 = fmaxf(fmaf(acc[mt][nt][3], al1, be1), 0.f);
                __nv_bfloat16 h00 = __float2bfloat16(v00), h01 = __float2bfloat16(v01);
                __nv_bfloat16 h10 = __float2bfloat16(v10), h11 = __float2bfloat16(v11);
                __nv_bfloat16 l00 = __float2bfloat16(v00 - __bfloat162float(h00));
                __nv_bfloat16 l01 = __float2bfloat16(v01 - __bfloat162float(h01));
                __nv_bfloat16 l10 = __float2bfloat16(v10 - __bfloat162float(h10));
                __nv_bfloat16 l11 = __float2bfloat16(v11 - __bfloat162float(h11));
                __nv_bfloat162 ph0; ph0.x = h00; ph0.y = h01;
                __nv_bfloat162 ph1; ph1.x = h10; ph1.y = h11;
                __nv_bfloat162 pl0; pl0.x = l00; pl0.y = l01;
                __nv_bfloat162 pl1; pl1.x = l10; pl1.y = l11;
                *(__nv_bfloat162*)(outHi + (size_t)mlo * DIM + n) = ph0;
                *(__nv_bfloat162*)(outHi + (size_t)mhi * DIM + n) = ph1;
                *(__nv_bfloat162*)(outLo + (size_t)mlo * DIM + n) = pl0;
                *(__nv_bfloat162*)(outLo + (size_t)mhi * DIM + n) = pl1;
            }
        }
    } else {                          // gates: +bias -> gpre[(t*2048+n)*32 + b]
        #pragma unroll
        for (int mt = 0; mt < 2; mt++) {
            const int mlo = m0 + wm * 32 + mt * 16 + g;
            const int mhi = mlo + 8;
            const int blo = mlo >> 10, tlo = mlo & (LSEQ - 1);
            const int bhi = mhi >> 10, thi = mhi & (LSEQ - 1);
            #pragma unroll
            for (int nt = 0; nt < 8; nt++) {
                const int n = n0 + wn * 64 + nt * 8 + tg * 2;
                const float b0 = bias[n], b1 = bias[n + 1];
                gout[((size_t)tlo * GDIM + n    ) * 32 + blo] = acc[mt][nt][0] + b0;
                gout[((size_t)tlo * GDIM + n + 1) * 32 + blo] = acc[mt][nt][1] + b1;
                gout[((size_t)thi * GDIM + n    ) * 32 + bhi] = acc[mt][nt][2] + b0;
                gout[((size_t)thi * GDIM + n + 1) * 32 + bhi] = acc[mt][nt][3] + b1;
            }
        }
    }
}

// =================== persistent LSTM recurrence — tensor-core matvec =========
// Block: dir = bid>>6, dims dc..dc+7 (dc=(bid&63)*8), N=32 permuted cols
// (r = g*8+j <-> col g*512+dc+j). K_eff = 1536: A sections [hi,lo,hi],
// W sections [Whi,Whi,Wlo]. Warp u owns k16 tiles u*12..u*12+11; 8-way smem
// reduction. Thread (lane=b, warp=u=j): owns h[b][dc+u].
#define R_WHI 0
#define R_WLO 33280
#define R_AHI 66560
#define R_ALO 99840
#define R_PART 133120
#define R_SMEM (133120 + 8*32*33*4)     // 166912

__global__ void __launch_bounds__(256, 1) lstm_recur_kernel(
    const __nv_bfloat16* __restrict__ wrHi, const __nv_bfloat16* __restrict__ wrLo,
    const int* __restrict__ lengths, const float* __restrict__ gpreAll,
    float* __restrict__ out)
{
    extern __shared__ char sm[];
    float* part = (float*)(sm + R_PART);
    __shared__ int len_s[32];

    const int tid = threadIdx.x;
    const int lane = tid & 31, u = tid >> 5;
    const int dir = blockIdx.x >> 6;
    const int dc  = (blockIdx.x & 63) << 3;
    const uint32_t sb = smem_to_u32(sm);
    const float* gpre = gpreAll + (size_t)dir * MTOT * GDIM;
    const __nv_bfloat16* wHi = wrHi + (size_t)dir * GDIM * DIM;
    const __nv_bfloat16* wLo = wrLo + (size_t)dir * GDIM * DIM;

    // ---- stage W (permuted rows, 1040B padded stride) ----
    for (int i = tid; i < 2048; i += 256) {
        int r = i >> 6, c16 = i & 63;
        int n = ((r >> 3) << 9) + dc + (r & 7);
        uint4 vh = *(const uint4*)(wHi + (size_t)n * DIM + c16 * 8);
        uint4 vl = *(const uint4*)(wLo + (size_t)n * DIM + c16 * 8);
        *(uint4*)(sm + R_WHI + r * 1040 + c16 * 16) = vh;
        *(uint4*)(sm + R_WLO + r * 1040 + c16 * 16) = vl;
    }
    if (tid < 32) len_s[tid] = lengths[tid];
    g_hpk[0][dir][lane * DIM + dc + u] = 0u;       // zero parity-0 h slice
    __syncthreads();

    // ---- preload W fragments (96 regs/thread) ----
    uint32_t wf[12][8];
    {
        const uint32_t rB = (uint32_t)(((lane >> 4) << 3) | (lane & 7));
        const uint32_t hB = (uint32_t)(((lane >> 3) & 1) << 4);
        #pragma unroll
        for (int i = 0; i < 12; i++) {
            int tt = u * 12 + i;
            int sec = tt >> 5, kk = tt & 31;
            uint32_t base = sb + (sec == 2 ? R_WLO : R_WHI);
            uint32_t col = (uint32_t)(kk * 32) + hB;
            LDSM_X4(wf[i][0], wf[i][1], wf[i][2], wf[i][3], base + rB * 1040 + col);
            LDSM_X4(wf[i][4], wf[i][5], wf[i][6], wf[i][7], base + (rB + 16) * 1040 + col);
        }
    }
    const int lenb = len_s[lane];
    grid_sync_();

    const uint32_t rA = (uint32_t)(lane & 15);
    const uint32_t hA = (uint32_t)((lane >> 4) << 4);
    float cst = 0.f;

    for (int s = 0; s < LSEQ; s++) {
        const int t = dir ? (LSEQ - 1 - s) : s;
        const int p = s & 1;

        // gpre prefetch (constant data, coalesced 128B per warp-load)
        const float* gq = gpre + ((size_t)t * GDIM + dc + u) * 32 + lane;
        float gp0 = __ldg(gq + (size_t)(0 * 512) * 32);
        float gp1 = __ldg(gq + (size_t)(1 * 512) * 32);
        float gp2 = __ldg(gq + (size_t)(2 * 512) * 32);
        float gp3 = __ldg(gq + (size_t)(3 * 512) * 32);

        // ---- stage h_prev (packed bf16 hi|lo) into Ahi/Alo smem ----
        {
            const uint4* hp = (const uint4*)g_hpk[p][dir];
            #pragma unroll
            for (int i = 0; i < 16; i++) {
                int idx = i * 256 + tid;            // 0..4095 uint4 (4 pairs each)
                int b_ = idx >> 7, c4 = idx & 127;
                uint4 v = __ldcg(hp + idx);
                if (dir && t >= len_s[b_] - 1) v = make_uint4(0u, 0u, 0u, 0u);
                unsigned h01 = __byte_perm(v.x, v.y, 0x5410);
                unsigned h23 = __byte_perm(v.z, v.w, 0x5410);
                unsigned l01 = __byte_perm(v.x, v.y, 0x7632);
                unsigned l23 = __byte_perm(v.z, v.w, 0x7632);
                *(uint2*)(sm + R_AHI + b_ * 1040 + c4 * 8) = make_uint2(h01, h23);
                *(uint2*)(sm + R_ALO + b_ * 1040 + c4 * 8) = make_uint2(l01, l23);
            }
        }
        __syncthreads();

        // ---- warp matvec: 12 k16 tiles ----
        float acc[2][4][4];
        #pragma unroll
        for (int a = 0; a < 2; a++)
            #pragma unroll
            for (int b = 0; b < 4; b++)
                #pragma unroll
                for (int c = 0; c < 4; c++) acc[a][b][c] = 0.f;

        #pragma unroll
        for (int i = 0; i < 12; i++) {
            int tt = u * 12 + i;
            int sec = tt >> 5, kk = tt & 31;
            uint32_t base = sb + (sec == 1 ? R_ALO : R_AHI);
            uint32_t col = (uint32_t)(kk * 32) + hA;
            uint32_t af0[4], af1[4];
            LDSM_X4(af0[0], af0[1], af0[2], af0[3], base + rA * 1040 + col);
            LDSM_X4(af1[0], af1[1], af1[2], af1[3], base + (rA + 16) * 1040 + col);
            #pragma unroll
            for (int nt = 0; nt < 4; nt++) {
                MMA16816(acc[0][nt], af0, &wf[i][nt * 2]);
                MMA16816(acc[1][nt], af1, &wf[i][nt * 2]);
            }
        }

        // ---- store partials [u][row][33] ----
        {
            int row = lane >> 2, colp = (lane & 3) * 2;
            #pragma unroll
            for (int mt = 0; mt < 2; mt++)
                #pragma unroll
                for (int nt = 0; nt < 4; nt++) {
                    float* p0 = part + (u * 32 + mt * 16 + row) * 33 + nt * 8 + colp;
                    p0[0] = acc[mt][nt][0]; p0[1] = acc[mt][nt][1];
                    float* p1 = part + (u * 32 + mt * 16 + row + 8) * 33 + nt * 8 + colp;
                    p1[0] = acc[mt][nt][2]; p1[1] = acc[mt][nt][3];
                }
        }
        __syncthreads();

        // ---- reduce 8 warps + cell update (thread: b=lane, dim=dc+u) ----
        float s0 = 0.f, s1 = 0.f, s2 = 0.f, s3 = 0.f;
        #pragma unroll
        for (int w = 0; w < 8; w++) {
            const float* pr = part + (w * 32 + lane) * 33;
            s0 += pr[u]; s1 += pr[8 + u]; s2 += pr[16 + u]; s3 += pr[24 + u];
        }
        float iv = sigmoidf_(gp0 + s0);
        float gv = tanhf(gp1 + s1);
        float fv = sigmoidf_(gp2 + s2 + 1.f);
        float ov = sigmoidf_(gp3 + s3);
        if (dir && t >= lenb - 1) cst = 0.f;
        cst = fv * cst + iv * gv;
        float hh = ov * tanhf(cst);

        __nv_bfloat16 hb = __float2bfloat16(hh);
        __nv_bfloat16 lb = __float2bfloat16(hh - __bfloat162float(hb));
        unsigned pk = (unsigned)__bfloat16_as_ushort(hb) |
                      ((unsigned)__bfloat16_as_ushort(lb) << 16);
        g_hpk[p ^ 1][dir][lane * DIM + dc + u] = pk;
        out[(((size_t)lane << 10) + t) * 1024 + (dir << 9) + dc + u] = hh;

        grid_sync_();
    }
}

// =================== launch ===================================================
extern "C" void kernel_launch(void* const* d_in, const int* in_sizes, int n_in,
                              void* d_out, int out_size)
{
    (void)in_sizes; (void)n_in; (void)out_size;
    const int*   x        = (const int*)  d_in[0];
    const int*   lengths  = (const int*)  d_in[1];
    const float* embed_w  = (const float*)d_in[2];
    const float* c1w = (const float*)d_in[3];
    const float* c1b = (const float*)d_in[4];
    const float* c2w = (const float*)d_in[5];
    const float* c2b = (const float*)d_in[6];
    const float* c3w = (const float*)d_in[7];
    const float* c3b = (const float*)d_in[8];
    const float* wf  = (const float*)d_in[9];
    const float* bf  = (const float*)d_in[10];
    const float* wb  = (const float*)d_in[11];
    const float* bb  = (const float*)d_in[12];
    const float* s1 = (const float*)d_in[13]; const float* o1 = (const float*)d_in[14];
    const float* m1 = (const float*)d_in[15]; const float* v1 = (const float*)d_in[16];
    const float* s2 = (const float*)d_in[17]; const float* o2 = (const float*)d_in[18];
    const float* m2 = (const float*)d_in[19]; const float* v2 = (const float*)d_in[20];
    const float* s3 = (const float*)d_in[21]; const float* o3 = (const float*)d_in[22];
    const float* m3 = (const float*)d_in[23]; const float* v3 = (const float*)d_in[24];
    float* out = (float*)d_out;

    __nv_bfloat16 *aHi, *aLo, *bHi, *bLo, *wcH, *wcL, *wgH, *wgL, *wrH, *wrL;
    cudaGetSymbolAddress((void**)&aHi, g_aHi);
    cudaGetSymbolAddress((void**)&aLo, g_aLo);
    cudaGetSymbolAddress((void**)&bHi, g_bHi);
    cudaGetSymbolAddress((void**)&bLo, g_bLo);
    cudaGetSymbolAddress((void**)&wcH, g_wcHi);
    cudaGetSymbolAddress((void**)&wcL, g_wcLo);
    cudaGetSymbolAddress((void**)&wgH, g_wgHi);
    cudaGetSymbolAddress((void**)&wgL, g_wgLo);
    cudaGetSymbolAddress((void**)&wrH, g_wrHi);
    cudaGetSymbolAddress((void**)&wrL, g_wrLo);
    float* gpre;
    cudaGetSymbolAddress((void**)&gpre, g_gpre);

    const size_t WC = (size_t)3 * DIM * DIM;
    const size_t WG = (size_t)GDIM * DIM;

    const int SMEM_GEMM  = 33280 + 2 * 32768;     // 98816
    cudaFuncSetAttribute(mma_gemm_kernel,
                         cudaFuncAttributeMaxDynamicSharedMemorySize, SMEM_GEMM);
    cudaFuncSetAttribute(lstm_recur_kernel,
                         cudaFuncAttributeMaxDynamicSharedMemorySize, R_SMEM);

    dim3 gconv(MTOT / 128, DIM / 128);
    dim3 ggate(MTOT / 128, GDIM / 128);
    const int NWC = (3 * DIM * DIM + 255) / 256;
    const int NWG = (GDIM * DIM + 255) / 256;

    wprep_conv_kernel<<<NWC, 256>>>(c1w, 0);
    bnprep_kernel<<<1, 512>>>(c1b, s1, o1, m1, v1,
                              c2b, s2, o2, m2, v2,
                              c3b, s3, o3, m3, v3);
    embed_kernel<<<MTOT, 128>>>(x, embed_w);
    mma_gemm_kernel<<<gconv, 256, SMEM_GEMM>>>(aHi, aLo, wcH + 0 * WC, wcL + 0 * WC,
        3, 0, bHi, bLo, nullptr, nullptr);
    wprep_conv_kernel<<<NWC, 256>>>(c2w, 1);
    mma_gemm_kernel<<<gconv, 256, SMEM_GEMM>>>(bHi, bLo, wcH + 1 * WC, wcL + 1 * WC,
        3, 1, aHi, aLo, nullptr, nullptr);
    wprep_conv_kernel<<<NWC, 256>>>(c3w, 2);
    mma_gemm_kernel<<<gconv, 256, SMEM_GEMM>>>(aHi, aLo, wcH + 2 * WC, wcL + 2 * WC,
        3, 2, bHi, bLo, nullptr, nullptr);
    wprep_gate_kernel<<<NWG, 256>>>(wf, 0, 0,   wgH + 0 * WG, wgL + 0 * WG);
    wprep_gate_kernel<<<NWG, 256>>>(wb, 1, 0,   wgH + 1 * WG, wgL + 1 * WG);
    wprep_gate_kernel<<<NWG, 256>>>(wf, 0, DIM, wrH + 0 * WG, wrL + 0 * WG);
    wprep_gate_kernel<<<NWG, 256>>>(wb, 1, DIM, wrH + 1 * WG, wrL + 1 * WG);
    mma_gemm_kernel<<<ggate, 256, SMEM_GEMM>>>(bHi, bLo, wgH + 0 * WG, wgL + 0 * WG,
        1, -1, nullptr, nullptr, bf, gpre + 0);
    mma_gemm_kernel<<<ggate, 256, SMEM_GEMM>>>(bHi, bLo, wgH + 1 * WG, wgL + 1 * WG,
        1, -1, nullptr, nullptr, bb, gpre + (size_t)MTOT * GDIM);
    lstm_recur_kernel<<<GRID_BLOCKS, 256, R_SMEM>>>(wrH, wrL, lengths, gpre, out);
}

// round 7
// speedup vs baseline: 2.1870x; 1.1693x over previous
#include <cuda_runtime.h>
#include <cuda_bf16.h>
#include <stdint.h>
#include <math.h>

#define BSZ   32
#define LSEQ  1024
#define DIM   512
#define MTOT  (BSZ*LSEQ)          // 32768
#define GDIM  2048                // 4*DIM

// =================== scratch (device globals) ================================
__device__ __align__(128) __nv_bfloat16 g_aHi[(size_t)MTOT*DIM];
__device__ __align__(128) __nv_bfloat16 g_aLo[(size_t)MTOT*DIM];
__device__ __align__(128) __nv_bfloat16 g_bHi[(size_t)MTOT*DIM];
__device__ __align__(128) __nv_bfloat16 g_bLo[(size_t)MTOT*DIM];
__device__ __align__(128) __nv_bfloat16 g_wcHi[3][(size_t)3*DIM*DIM];   // [layer][tap*512+n][k]
__device__ __align__(128) __nv_bfloat16 g_wcLo[3][(size_t)3*DIM*DIM];
__device__ __align__(128) __nv_bfloat16 g_wgHi[2][(size_t)GDIM*DIM];    // [dir][n][k]
__device__ __align__(128) __nv_bfloat16 g_wgLo[2][(size_t)GDIM*DIM];
__device__ __align__(128) __nv_bfloat16 g_wrHi[2][(size_t)GDIM*DIM];    // recurrent W
__device__ __align__(128) __nv_bfloat16 g_wrLo[2][(size_t)GDIM*DIM];
__device__ float g_gpre[2][(size_t)MTOT*GDIM];   // [dir][ (t*2048 + col)*32 + b ]
__device__ unsigned g_hpk[2][2][BSZ*DIM];        // [parity][dir][b*512+d] packed
__device__ float g_alpha[3][DIM];
__device__ float g_beta[3][DIM];
__device__ unsigned g_arr2[2];                   // per-direction barrier state
__device__ unsigned g_gen2[2];

// =================== primitives ===============================================
__device__ __forceinline__ uint32_t smem_to_u32(const void* p) {
    uint32_t a;
    asm("{ .reg .u64 t; cvta.to.shared.u64 t, %1; cvt.u32.u64 %0, t; }" : "=r"(a) : "l"(p));
    return a;
}
#define LDSM_X4(r0, r1, r2, r3, addr) \
    asm volatile("ldmatrix.sync.aligned.m8n8.x4.shared.b16 {%0,%1,%2,%3}, [%4];" \
        : "=r"(r0), "=r"(r1), "=r"(r2), "=r"(r3) : "r"(addr))
#define MMA16816(c, a, b) \
    asm volatile("mma.sync.aligned.m16n8k16.row.col.f32.bf16.bf16.f32 " \
        "{%0,%1,%2,%3}, {%4,%5,%6,%7}, {%8,%9}, {%0,%1,%2,%3};" \
        : "+f"((c)[0]), "+f"((c)[1]), "+f"((c)[2]), "+f"((c)[3]) \
        : "r"((a)[0]), "r"((a)[1]), "r"((a)[2]), "r"((a)[3]), \
          "r"((b)[0]), "r"((b)[1]))

__device__ __forceinline__ float sigmoidf_(float x) { return 1.0f / (1.0f + __expf(-x)); }

// per-direction sense-reversal barrier, release/acquire (no membar.gl/CCTL)
__device__ __forceinline__ void dir_sync_(int dir, unsigned nblk) {
    __syncthreads();
    if (threadIdx.x == 0) {
        unsigned* arr = &g_arr2[dir];
        unsigned* gen = &g_gen2[dir];
        unsigned cur;
        asm volatile("ld.acquire.gpu.global.u32 %0, [%1];" : "=r"(cur) : "l"(gen));
        unsigned prev;
        asm volatile("atom.release.gpu.global.add.u32 %0, [%1], 1;"
                     : "=r"(prev) : "l"(arr) : "memory");
        if (prev == nblk - 1) {
            *arr = 0u;
            unsigned nxt = cur + 1u;
            asm volatile("st.release.gpu.global.u32 [%0], %1;" :: "l"(gen), "r"(nxt) : "memory");
        } else {
            unsigned g;
            do {
                asm volatile("ld.acquire.gpu.global.u32 %0, [%1];" : "=r"(g) : "l"(gen));
            } while (g == cur);
        }
    }
    __syncthreads();
}

// =================== BN fold =================================================
__global__ void bnprep_kernel(
    const float* __restrict__ b1, const float* __restrict__ s1, const float* __restrict__ o1,
    const float* __restrict__ m1, const float* __restrict__ v1,
    const float* __restrict__ b2, const float* __restrict__ s2, const float* __restrict__ o2,
    const float* __restrict__ m2, const float* __restrict__ v2,
    const float* __restrict__ b3, const float* __restrict__ s3, const float* __restrict__ o3,
    const float* __restrict__ m3, const float* __restrict__ v3)
{
    int i = threadIdx.x;
    if (i < DIM) {
        float g;
        g = s1[i] * rsqrtf(v1[i] + 1e-5f); g_alpha[0][i] = g; g_beta[0][i] = (b1[i] - m1[i]) * g + o1[i];
        g = s2[i] * rsqrtf(v2[i] + 1e-5f); g_alpha[1][i] = g; g_beta[1][i] = (b2[i] - m2[i]) * g + o2[i];
        g = s3[i] * rsqrtf(v3[i] + 1e-5f); g_alpha[2][i] = g; g_beta[2][i] = (b3[i] - m3[i]) * g + o3[i];
    }
}

// =================== weight prep ==============================================
__global__ void wprep_conv_kernel(const float* __restrict__ Wc, int layer)
{
    int idx = blockIdx.x * 256 + threadIdx.x;
    if (idx >= 3 * DIM * DIM) return;
    int tap = idx / (DIM * DIM);
    int rem = idx - tap * DIM * DIM;
    int n = rem / DIM, k = rem % DIM;
    float v = Wc[(size_t)(tap * DIM + k) * DIM + n];
    __nv_bfloat16 h = __float2bfloat16(v);
    __nv_bfloat16 l = __float2bfloat16(v - __bfloat162float(h));
    g_wcHi[layer][(size_t)(tap * DIM + n) * DIM + k] = h;
    g_wcLo[layer][(size_t)(tap * DIM + n) * DIM + k] = l;
}
__global__ void wprep_gate_kernel(const float* __restrict__ W, int dir, int krow0,
                                  __nv_bfloat16* __restrict__ dstHi,
                                  __nv_bfloat16* __restrict__ dstLo)
{
    int idx = blockIdx.x * 256 + threadIdx.x;
    if (idx >= GDIM * DIM) return;
    int n = idx / DIM, k = idx % DIM;
    float v = W[(size_t)(krow0 + k) * GDIM + n];
    __nv_bfloat16 h = __float2bfloat16(v);
    __nv_bfloat16 l = __float2bfloat16(v - __bfloat162float(h));
    dstHi[idx] = h;
    dstLo[idx] = l;
}

// =================== embedding -> bf16 hi/lo =================================
__global__ void embed_kernel(const int* __restrict__ x, const float* __restrict__ ew)
{
    int m = blockIdx.x;
    int tok = x[m];
    int j = threadIdx.x;
    float4 v = ((const float4*)(ew + (size_t)tok * DIM))[j];
    float f[4] = {v.x, v.y, v.z, v.w};
    __nv_bfloat16 h[4], l[4];
    #pragma unroll
    for (int i = 0; i < 4; i++) {
        h[i] = __float2bfloat16(f[i]);
        l[i] = __float2bfloat16(f[i] - __bfloat162float(h[i]));
    }
    *(uint2*)(g_aHi + (size_t)m * DIM + j * 4) = *(uint2*)h;
    *(uint2*)(g_aLo + (size_t)m * DIM + j * 4) = *(uint2*)l;
}

// =================== bf16 mma.sync GEMM =======================================
__global__ void __launch_bounds__(256, 2) mma_gemm_kernel(
    const __nv_bfloat16* __restrict__ Ahi, const __nv_bfloat16* __restrict__ Alo,
    const __nv_bfloat16* __restrict__ BwHi, const __nv_bfloat16* __restrict__ BwLo,
    int taps, int layer,
    __nv_bfloat16* __restrict__ outHi, __nv_bfloat16* __restrict__ outLo,
    const float* __restrict__ bias, float* __restrict__ gout)
{
    extern __shared__ char smem[];
    const int tid = threadIdx.x;
    const int lane = tid & 31, wid = tid >> 5;
    const int wm = wid & 3, wn = wid >> 2;
    const int m0 = blockIdx.x * 128, n0 = blockIdx.y * 128;
    const int t0 = m0 & (LSEQ - 1);
    const uint32_t sb = smem_to_u32(smem);

    const int off0  = taps >> 1;
    const int arows = 128 + (taps - 1);

    float acc[2][8][4];
    #pragma unroll
    for (int a = 0; a < 2; a++)
        #pragma unroll
        for (int b = 0; b < 8; b++)
            #pragma unroll
            for (int c = 0; c < 4; c++) acc[a][b][c] = 0.f;

    #define DO_COPY_A(SLICE) do { \
        const int _kb = (SLICE) << 6; \
        const int _tot = arows * 8; \
        for (int _i = tid; _i < _tot; _i += 256) { \
            int _r = _i >> 3, _c8 = (_i & 7) << 3; \
            uint32_t _off = (uint32_t)(_r * 128) + (((uint32_t)_c8 * 2) ^ (((uint32_t)_r & 7) << 4)); \
            int _tl = t0 + _r - off0; \
            uint4 _vh = make_uint4(0u,0u,0u,0u), _vl = _vh; \
            if (_tl >= 0 && _tl < LSEQ) { \
                size_t _ga = (size_t)(m0 + _r - off0) * DIM + _kb + _c8; \
                _vh = *(const uint4*)(Ahi + _ga); \
                _vl = *(const uint4*)(Alo + _ga); \
            } \
            *(uint4*)(smem + _off) = _vh; \
            *(uint4*)(smem + 16640 + _off) = _vl; \
        } \
    } while (0)

    #define DO_COPY_B(IDX, ST) do { \
        const int _sl = (IDX) / taps, _tp = (IDX) % taps; \
        const int _kb = _sl << 6; \
        const int _rbase = (taps == 3 ? _tp * DIM : 0) + n0; \
        char* _bp = smem + 33280 + (ST) * 32768; \
        for (int _i = tid; _i < 1024; _i += 256) { \
            int _r = _i >> 3, _c8 = (_i & 7) << 3; \
            uint32_t _off = (uint32_t)(_r * 128) + (((uint32_t)_c8 * 2) ^ (((uint32_t)_r & 7) << 4)); \
            size_t _ga = (size_t)(_rbase + _r) * DIM + _kb + _c8; \
            *(uint4*)(_bp + _off) = *(const uint4*)(BwHi + _ga); \
            *(uint4*)(_bp + 16384 + _off) = *(const uint4*)(BwLo + _ga); \
        } \
    } while (0)

    const int NB = 8 * taps;
    DO_COPY_A(0);
    DO_COPY_B(0, 0);
    __syncthreads();

    for (int idx = 0; idx < NB; idx++) {
        const int tap = idx % taps;
        const int bsel = idx & 1;
        const bool lastTap = (tap == taps - 1);

        if (idx + 1 < NB) DO_COPY_B(idx + 1, bsel ^ 1);

        const uint32_t aHiB = sb;
        const uint32_t aLoB = sb + 16640;
        const uint32_t bHiB = sb + 33280 + (uint32_t)bsel * 32768;
        const uint32_t bLoB = bHiB + 16384;
        #pragma unroll
        for (int k16 = 0; k16 < 4; k16++) {
            const uint32_t colA = (uint32_t)(k16 * 32) + (((uint32_t)lane >> 4) << 4);
            const uint32_t colB = (uint32_t)(k16 * 32) + ((((uint32_t)lane >> 3) & 1) << 4);
            uint32_t afh[2][4], afl[2][4];
            #pragma unroll
            for (int mt = 0; mt < 2; mt++) {
                uint32_t row = (uint32_t)(wm * 32 + mt * 16 + (lane & 15) + tap);
                uint32_t ad = row * 128 + (colA ^ ((row & 7) << 4));
                LDSM_X4(afh[mt][0], afh[mt][1], afh[mt][2], afh[mt][3], aHiB + ad);
                LDSM_X4(afl[mt][0], afl[mt][1], afl[mt][2], afl[mt][3], aLoB + ad);
            }
            #pragma unroll
            for (int half = 0; half < 2; half++) {
                uint32_t bfh[4][2], bfl[4][2];
                #pragma unroll
                for (int np = 0; np < 2; np++) {
                    uint32_t row = (uint32_t)(wn * 64 + (half * 2 + np) * 16 +
                                              (((lane >> 4) << 3) | (lane & 7)));
                    uint32_t bd = row * 128 + (colB ^ ((row & 7) << 4));
                    LDSM_X4(bfh[2*np][0], bfh[2*np][1], bfh[2*np+1][0], bfh[2*np+1][1], bHiB + bd);
                    LDSM_X4(bfl[2*np][0], bfl[2*np][1], bfl[2*np+1][0], bfl[2*np+1][1], bLoB + bd);
                }
                #pragma unroll
                for (int mt = 0; mt < 2; mt++)
                    #pragma unroll
                    for (int nt = 0; nt < 4; nt++) {
                        float* ac = acc[mt][half * 4 + nt];
                        MMA16816(ac, afh[mt], bfh[nt]);
                        MMA16816(ac, afl[mt], bfh[nt]);
                        MMA16816(ac, afh[mt], bfl[nt]);
                    }
            }
        }
        __syncthreads();
        if (lastTap && idx + 1 < NB) {
            DO_COPY_A((idx + 1) / taps);
            __syncthreads();
        }
    }
    #undef DO_COPY_A
    #undef DO_COPY_B

    const int g  = lane >> 2;
    const int tg = lane & 3;
    if (gout == nullptr) {            // conv epilogue
        #pragma unroll
        for (int mt = 0; mt < 2; mt++) {
            const int mlo = m0 + wm * 32 + mt * 16 + g;
            const int mhi = mlo + 8;
            #pragma unroll
            for (int nt = 0; nt < 8; nt++) {
                const int n = n0 + wn * 64 + nt * 8 + tg * 2;
                const float al0 = g_alpha[layer][n],     be0 = g_beta[layer][n];
                const float al1 = g_alpha[layer][n + 1], be1 = g_beta[layer][n + 1];
                float v00 = fmaxf(fmaf(acc[mt][nt][0], al0, be0), 0.f);
                float v01 = fmaxf(fmaf(acc[mt][nt][1], al1, be1), 0.f);
                float v10 = fmaxf(fmaf(acc[mt][nt][2], al0, be0), 0.f);
                float v11 = fmaxf(fmaf(acc[mt][nt][3], al1, be1), 0.f);
                __nv_bfloat16 h00 = __float2bfloat16(v00), h01 = __float2bfloat16(v01);
                __nv_bfloat16 h10 = __float2bfloat16(v10), h11 = __float2bfloat16(v11);
                __nv_bfloat16 l00 = __float2bfloat16(v00 - __bfloat162float(h00));
                __nv_bfloat16 l01 = __float2bfloat16(v01 - __bfloat162float(h01));
                __nv_bfloat16 l10 = __float2bfloat16(v10 - __bfloat162float(h10));
                __nv_bfloat16 l11 = __float2bfloat16(v11 - __bfloat162float(h11));
                __nv_bfloat162 ph0; ph0.x = h00; ph0.y = h01;
                __nv_bfloat162 ph1; ph1.x = h10; ph1.y = h11;
                __nv_bfloat162 pl0; pl0.x = l00; pl0.y = l01;
                __nv_bfloat162 pl1; pl1.x = l10; pl1.y = l11;
                *(__nv_bfloat162*)(outHi + (size_t)mlo * DIM + n) = ph0;
                *(__nv_bfloat162*)(outHi + (size_t)mhi * DIM + n) = ph1;
                *(__nv_bfloat162*)(outLo + (size_t)mlo * DIM + n) = pl0;
                *(__nv_bfloat162*)(outLo + (size_t)mhi * DIM + n) = pl1;
            }
        }
    } else {                          // gates: +bias -> gpre[(t*2048+n)*32 + b]
        #pragma unroll
        for (int mt = 0; mt < 2; mt++) {
            const int mlo = m0 + wm * 32 + mt * 16 + g;
            const int mhi = mlo + 8;
            const int blo = mlo >> 10, tlo = mlo & (LSEQ - 1);
            const int bhi = mhi >> 10, thi = mhi & (LSEQ - 1);
            #pragma unroll
            for (int nt = 0; nt < 8; nt++) {
                const int n = n0 + wn * 64 + nt * 8 + tg * 2;
                const float b0 = bias[n], b1 = bias[n + 1];
                gout[((size_t)tlo * GDIM + n    ) * 32 + blo] = acc[mt][nt][0] + b0;
                gout[((size_t)tlo * GDIM + n + 1) * 32 + blo] = acc[mt][nt][1] + b1;
                gout[((size_t)thi * GDIM + n    ) * 32 + bhi] = acc[mt][nt][2] + b0;
                gout[((size_t)thi * GDIM + n + 1) * 32 + bhi] = acc[mt][nt][3] + b1;
            }
        }
    }
}

// =================== persistent LSTM recurrence — tensor-core matvec =========
#define R_WHI 0
#define R_WLO 33280
#define R_AHI 66560
#define R_ALO 99840
#define R_PART 133120
#define R_SMEM (133120 + 8*32*33*4)     // 166912

__global__ void __launch_bounds__(256, 1) lstm_recur_kernel(
    const __nv_bfloat16* __restrict__ wrHi, const __nv_bfloat16* __restrict__ wrLo,
    const int* __restrict__ lengths, const float* __restrict__ gpreAll,
    float* __restrict__ out)
{
    extern __shared__ char sm[];
    float* part = (float*)(sm + R_PART);
    __shared__ int len_s[32];

    const int tid = threadIdx.x;
    const int lane = tid & 31, u = tid >> 5;
    const int dir = blockIdx.x >> 6;
    const int dc  = (blockIdx.x & 63) << 3;
    const uint32_t sb = smem_to_u32(sm);
    const float* gpre = gpreAll + (size_t)dir * MTOT * GDIM;
    const __nv_bfloat16* wHi = wrHi + (size_t)dir * GDIM * DIM;
    const __nv_bfloat16* wLo = wrLo + (size_t)dir * GDIM * DIM;

    for (int i = tid; i < 2048; i += 256) {
        int r = i >> 6, c16 = i & 63;
        int n = ((r >> 3) << 9) + dc + (r & 7);
        uint4 vh = *(const uint4*)(wHi + (size_t)n * DIM + c16 * 8);
        uint4 vl = *(const uint4*)(wLo + (size_t)n * DIM + c16 * 8);
        *(uint4*)(sm + R_WHI + r * 1040 + c16 * 16) = vh;
        *(uint4*)(sm + R_WLO + r * 1040 + c16 * 16) = vl;
    }
    if (tid < 32) len_s[tid] = lengths[tid];
    g_hpk[0][dir][lane * DIM + dc + u] = 0u;
    __syncthreads();

    uint32_t wf[12][8];
    {
        const uint32_t rB = (uint32_t)(((lane >> 4) << 3) | (lane & 7));
        const uint32_t hB = (uint32_t)(((lane >> 3) & 1) << 4);
        #pragma unroll
        for (int i = 0; i < 12; i++) {
            int tt = u * 12 + i;
            int sec = tt >> 5, kk = tt & 31;
            uint32_t base = sb + (sec == 2 ? R_WLO : R_WHI);
            uint32_t col = (uint32_t)(kk * 32) + hB;
            LDSM_X4(wf[i][0], wf[i][1], wf[i][2], wf[i][3], base + rB * 1040 + col);
            LDSM_X4(wf[i][4], wf[i][5], wf[i][6], wf[i][7], base + (rB + 16) * 1040 + col);
        }
    }
    const int lenb = len_s[lane];
    dir_sync_(dir, 64);

    const uint32_t rA = (uint32_t)(lane & 15);
    const uint32_t hA = (uint32_t)((lane >> 4) << 4);
    float cst = 0.f;

    for (int s = 0; s < LSEQ; s++) {
        const int t = dir ? (LSEQ - 1 - s) : s;
        const int p = s & 1;

        const float* gq = gpre + ((size_t)t * GDIM + dc + u) * 32 + lane;
        float gp0 = __ldg(gq + (size_t)(0 * 512) * 32);
        float gp1 = __ldg(gq + (size_t)(1 * 512) * 32);
        float gp2 = __ldg(gq + (size_t)(2 * 512) * 32);
        float gp3 = __ldg(gq + (size_t)(3 * 512) * 32);

        {
            const uint4* hp = (const uint4*)g_hpk[p][dir];
            #pragma unroll
            for (int i = 0; i < 16; i++) {
                int idx = i * 256 + tid;
                int b_ = idx >> 7, c4 = idx & 127;
                uint4 v = __ldcg(hp + idx);
                if (dir && t >= len_s[b_] - 1) v = make_uint4(0u, 0u, 0u, 0u);
                unsigned h01 = __byte_perm(v.x, v.y, 0x5410);
                unsigned h23 = __byte_perm(v.z, v.w, 0x5410);
                unsigned l01 = __byte_perm(v.x, v.y, 0x7632);
                unsigned l23 = __byte_perm(v.z, v.w, 0x7632);
                *(uint2*)(sm + R_AHI + b_ * 1040 + c4 * 8) = make_uint2(h01, h23);
                *(uint2*)(sm + R_ALO + b_ * 1040 + c4 * 8) = make_uint2(l01, l23);
            }
        }
        __syncthreads();

        float acc[2][4][4];
        #pragma unroll
        for (int a = 0; a < 2; a++)
            #pragma unroll
            for (int b = 0; b < 4; b++)
                #pragma unroll
                for (int c = 0; c < 4; c++) acc[a][b][c] = 0.f;

        #pragma unroll
        for (int i = 0; i < 12; i++) {
            int tt = u * 12 + i;
            int sec = tt >> 5, kk = tt & 31;
            uint32_t base = sb + (sec == 1 ? R_ALO : R_AHI);
            uint32_t col = (uint32_t)(kk * 32) + hA;
            uint32_t af0[4], af1[4];
            LDSM_X4(af0[0], af0[1], af0[2], af0[3], base + rA * 1040 + col);
            LDSM_X4(af1[0], af1[1], af1[2], af1[3], base + (rA + 16) * 1040 + col);
            #pragma unroll
            for (int nt = 0; nt < 4; nt++) {
                MMA16816(acc[0][nt], af0, &wf[i][nt * 2]);
                MMA16816(acc[1][nt], af1, &wf[i][nt * 2]);
            }
        }

        {
            int row = lane >> 2, colp = (lane & 3) * 2;
            #pragma unroll
            for (int mt = 0; mt < 2; mt++)
                #pragma unroll
                for (int nt = 0; nt < 4; nt++) {
                    float* p0 = part + (u * 32 + mt * 16 + row) * 33 + nt * 8 + colp;
                    p0[0] = acc[mt][nt][0]; p0[1] = acc[mt][nt][1];
                    float* p1 = part + (u * 32 + mt * 16 + row + 8) * 33 + nt * 8 + colp;
                    p1[0] = acc[mt][nt][2]; p1[1] = acc[mt][nt][3];
                }
        }
        __syncthreads();

        float s0 = 0.f, s1 = 0.f, s2 = 0.f, s3 = 0.f;
        #pragma unroll
        for (int w = 0; w < 8; w++) {
            const float* pr = part + (w * 32 + lane) * 33;
            s0 += pr[u]; s1 += pr[8 + u]; s2 += pr[16 + u]; s3 += pr[24 + u];
        }
        float iv = sigmoidf_(gp0 + s0);
        float gv = tanhf(gp1 + s1);
        float fv = sigmoidf_(gp2 + s2 + 1.f);
        float ov = sigmoidf_(gp3 + s3);
        if (dir && t >= lenb - 1) cst = 0.f;
        cst = fv * cst + iv * gv;
        float hh = ov * tanhf(cst);

        __nv_bfloat16 hb = __float2bfloat16(hh);
        __nv_bfloat16 lb = __float2bfloat16(hh - __bfloat162float(hb));
        unsigned pk = (unsigned)__bfloat16_as_ushort(hb) |
                      ((unsigned)__bfloat16_as_ushort(lb) << 16);
        g_hpk[p ^ 1][dir][lane * DIM + dc + u] = pk;
        out[(((size_t)lane << 10) + t) * 1024 + (dir << 9) + dc + u] = hh;

        dir_sync_(dir, 64);
    }
}

// =================== launch ===================================================
extern "C" void kernel_launch(void* const* d_in, const int* in_sizes, int n_in,
                              void* d_out, int out_size)
{
    (void)in_sizes; (void)n_in; (void)out_size;
    const int*   x        = (const int*)  d_in[0];
    const int*   lengths  = (const int*)  d_in[1];
    const float* embed_w  = (const float*)d_in[2];
    const float* c1w = (const float*)d_in[3];
    const float* c1b = (const float*)d_in[4];
    const float* c2w = (const float*)d_in[5];
    const float* c2b = (const float*)d_in[6];
    const float* c3w = (const float*)d_in[7];
    const float* c3b = (const float*)d_in[8];
    const float* wf  = (const float*)d_in[9];
    const float* bf  = (const float*)d_in[10];
    const float* wb  = (const float*)d_in[11];
    const float* bb  = (const float*)d_in[12];
    const float* s1 = (const float*)d_in[13]; const float* o1 = (const float*)d_in[14];
    const float* m1 = (const float*)d_in[15]; const float* v1 = (const float*)d_in[16];
    const float* s2 = (const float*)d_in[17]; const float* o2 = (const float*)d_in[18];
    const float* m2 = (const float*)d_in[19]; const float* v2 = (const float*)d_in[20];
    const float* s3 = (const float*)d_in[21]; const float* o3 = (const float*)d_in[22];
    const float* m3 = (const float*)d_in[23]; const float* v3 = (const float*)d_in[24];
    float* out = (float*)d_out;

    __nv_bfloat16 *aHi, *aLo, *bHi, *bLo, *wcH, *wcL, *wgH, *wgL, *wrH, *wrL;
    cudaGetSymbolAddress((void**)&aHi, g_aHi);
    cudaGetSymbolAddress((void**)&aLo, g_aLo);
    cudaGetSymbolAddress((void**)&bHi, g_bHi);
    cudaGetSymbolAddress((void**)&bLo, g_bLo);
    cudaGetSymbolAddress((void**)&wcH, g_wcHi);
    cudaGetSymbolAddress((void**)&wcL, g_wcLo);
    cudaGetSymbolAddress((void**)&wgH, g_wgHi);
    cudaGetSymbolAddress((void**)&wgL, g_wgLo);
    cudaGetSymbolAddress((void**)&wrH, g_wrHi);
    cudaGetSymbolAddress((void**)&wrL, g_wrLo);
    float* gpre;
    cudaGetSymbolAddress((void**)&gpre, g_gpre);

    const size_t WC = (size_t)3 * DIM * DIM;
    const size_t WG = (size_t)GDIM * DIM;

    const int SMEM_GEMM  = 33280 + 2 * 32768;     // 98816
    cudaFuncSetAttribute(mma_gemm_kernel,
                         cudaFuncAttributeMaxDynamicSharedMemorySize, SMEM_GEMM);
    cudaFuncSetAttribute(lstm_recur_kernel,
                         cudaFuncAttributeMaxDynamicSharedMemorySize, R_SMEM);

    dim3 gconv(MTOT / 128, DIM / 128);
    dim3 ggate(MTOT / 128, GDIM / 128);
    const int NWC = (3 * DIM * DIM + 255) / 256;
    const int NWG = (GDIM * DIM + 255) / 256;

    wprep_conv_kernel<<<NWC, 256>>>(c1w, 0);
    bnprep_kernel<<<1, 512>>>(c1b, s1, o1, m1, v1,
                              c2b, s2, o2, m2, v2,
                              c3b, s3, o3, m3, v3);
    embed_kernel<<<MTOT, 128>>>(x, embed_w);
    mma_gemm_kernel<<<gconv, 256, SMEM_GEMM>>>(aHi, aLo, wcH + 0 * WC, wcL + 0 * WC,
        3, 0, bHi, bLo, nullptr, nullptr);
    wprep_conv_kernel<<<NWC, 256>>>(c2w, 1);
    mma_gemm_kernel<<<gconv, 256, SMEM_GEMM>>>(bHi, bLo, wcH + 1 * WC, wcL + 1 * WC,
        3, 1, aHi, aLo, nullptr, nullptr);
    wprep_conv_kernel<<<NWC, 256>>>(c3w, 2);
    mma_gemm_kernel<<<gconv, 256, SMEM_GEMM>>>(aHi, aLo, wcH + 2 * WC, wcL + 2 * WC,
        3, 2, bHi, bLo, nullptr, nullptr);
    wprep_gate_kernel<<<NWG, 256>>>(wf, 0, 0,   wgH + 0 * WG, wgL + 0 * WG);
    wprep_gate_kernel<<<NWG, 256>>>(wb, 1, 0,   wgH + 1 * WG, wgL + 1 * WG);
    wprep_gate_kernel<<<NWG, 256>>>(wf, 0, DIM, wrH + 0 * WG, wrL + 0 * WG);
    wprep_gate_kernel<<<NWG, 256>>>(wb, 1, DIM, wrH + 1 * WG, wrL + 1 * WG);
    mma_gemm_kernel<<<ggate, 256, SMEM_GEMM>>>(bHi, bLo, wgH + 0 * WG, wgL + 0 * WG,
        1, -1, nullptr, nullptr, bf, gpre + 0);
    mma_gemm_kernel<<<ggate, 256, SMEM_GEMM>>>(bHi, bLo, wgH + 1 * WG, wgL + 1 * WG,
        1, -1, nullptr, nullptr, bb, gpre + (size_t)MTOT * GDIM);
    lstm_recur_kernel<<<128, 256, R_SMEM>>>(wrH, wrL, lengths, gpre, out);
}

// round 8
// speedup vs baseline: 2.5360x; 1.1596x over previous
#include <cuda_runtime.h>
#include <cuda_bf16.h>
#include <stdint.h>
#include <math.h>

#define BSZ   32
#define LSEQ  1024
#define DIM   512
#define MTOT  (BSZ*LSEQ)          // 32768
#define GDIM  2048                // 4*DIM

// =================== scratch (device globals) ================================
__device__ __align__(128) __nv_bfloat16 g_aHi[(size_t)MTOT*DIM];
__device__ __align__(128) __nv_bfloat16 g_aLo[(size_t)MTOT*DIM];
__device__ __align__(128) __nv_bfloat16 g_bHi[(size_t)MTOT*DIM];
__device__ __align__(128) __nv_bfloat16 g_bLo[(size_t)MTOT*DIM];
__device__ __align__(128) __nv_bfloat16 g_wcHi[3][(size_t)3*DIM*DIM];   // [layer][tap*512+n][k]
__device__ __align__(128) __nv_bfloat16 g_wcLo[3][(size_t)3*DIM*DIM];
__device__ __align__(128) __nv_bfloat16 g_wgHi[2][(size_t)GDIM*DIM];    // [dir][n][k]
__device__ __align__(128) __nv_bfloat16 g_wgLo[2][(size_t)GDIM*DIM];
__device__ __align__(128) __nv_bfloat16 g_wrHi[2][(size_t)GDIM*DIM];    // recurrent W
__device__ __align__(128) __nv_bfloat16 g_wrLo[2][(size_t)GDIM*DIM];
__device__ float g_gpre[2][(size_t)MTOT*GDIM];   // [dir][ (t*2048 + col)*32 + b ]
__device__ unsigned g_hpk[2][2][BSZ*DIM];        // [parity][dir][b*512+d] packed
__device__ float g_alpha[3][DIM];
__device__ float g_beta[3][DIM];
__device__ __align__(1024) unsigned g_arr2[2][256];   // padded: dirs 1KB apart
__device__ __align__(1024) unsigned g_gen2[2][256];

// =================== primitives ===============================================
__device__ __forceinline__ uint32_t smem_to_u32(const void* p) {
    uint32_t a;
    asm("{ .reg .u64 t; cvta.to.shared.u64 t, %1; cvt.u32.u64 %0, t; }" : "=r"(a) : "l"(p));
    return a;
}
#define LDSM_X4(r0, r1, r2, r3, addr) \
    asm volatile("ldmatrix.sync.aligned.m8n8.x4.shared.b16 {%0,%1,%2,%3}, [%4];" \
        : "=r"(r0), "=r"(r1), "=r"(r2), "=r"(r3) : "r"(addr))
#define MMA16816(c, a, b) \
    asm volatile("mma.sync.aligned.m16n8k16.row.col.f32.bf16.bf16.f32 " \
        "{%0,%1,%2,%3}, {%4,%5,%6,%7}, {%8,%9}, {%0,%1,%2,%3};" \
        : "+f"((c)[0]), "+f"((c)[1]), "+f"((c)[2]), "+f"((c)[3]) \
        : "r"((a)[0]), "r"((a)[1]), "r"((a)[2]), "r"((a)[3]), \
          "r"((b)[0]), "r"((b)[1]))

__device__ __forceinline__ float sigmoidf_(float x) { return 1.0f / (1.0f + __expf(-x)); }

// per-direction sense-reversal barrier (padded counters, release/acquire)
__device__ __forceinline__ void dir_sync_(int dir, unsigned nblk) {
    __syncthreads();
    if (threadIdx.x == 0) {
        unsigned* arr = &g_arr2[dir][0];
        unsigned* gen = &g_gen2[dir][0];
        unsigned cur;
        asm volatile("ld.acquire.gpu.global.u32 %0, [%1];" : "=r"(cur) : "l"(gen));
        unsigned prev;
        asm volatile("atom.release.gpu.global.add.u32 %0, [%1], 1;"
                     : "=r"(prev) : "l"(arr) : "memory");
        if (prev == nblk - 1) {
            *arr = 0u;
            unsigned nxt = cur + 1u;
            asm volatile("st.release.gpu.global.u32 [%0], %1;" :: "l"(gen), "r"(nxt) : "memory");
        } else {
            unsigned g;
            do {
                asm volatile("ld.acquire.gpu.global.u32 %0, [%1];" : "=r"(g) : "l"(gen));
            } while (g == cur);
        }
    }
    __syncthreads();
}

// =================== BN fold =================================================
__global__ void bnprep_kernel(
    const float* __restrict__ b1, const float* __restrict__ s1, const float* __restrict__ o1,
    const float* __restrict__ m1, const float* __restrict__ v1,
    const float* __restrict__ b2, const float* __restrict__ s2, const float* __restrict__ o2,
    const float* __restrict__ m2, const float* __restrict__ v2,
    const float* __restrict__ b3, const float* __restrict__ s3, const float* __restrict__ o3,
    const float* __restrict__ m3, const float* __restrict__ v3)
{
    int i = threadIdx.x;
    if (i < DIM) {
        float g;
        g = s1[i] * rsqrtf(v1[i] + 1e-5f); g_alpha[0][i] = g; g_beta[0][i] = (b1[i] - m1[i]) * g + o1[i];
        g = s2[i] * rsqrtf(v2[i] + 1e-5f); g_alpha[1][i] = g; g_beta[1][i] = (b2[i] - m2[i]) * g + o2[i];
        g = s3[i] * rsqrtf(v3[i] + 1e-5f); g_alpha[2][i] = g; g_beta[2][i] = (b3[i] - m3[i]) * g + o3[i];
    }
}

// =================== weight prep ==============================================
__global__ void wprep_conv_kernel(const float* __restrict__ Wc, int layer)
{
    int idx = blockIdx.x * 256 + threadIdx.x;
    if (idx >= 3 * DIM * DIM) return;
    int tap = idx / (DIM * DIM);
    int rem = idx - tap * DIM * DIM;
    int n = rem / DIM, k = rem % DIM;
    float v = Wc[(size_t)(tap * DIM + k) * DIM + n];
    __nv_bfloat16 h = __float2bfloat16(v);
    __nv_bfloat16 l = __float2bfloat16(v - __bfloat162float(h));
    g_wcHi[layer][(size_t)(tap * DIM + n) * DIM + k] = h;
    g_wcLo[layer][(size_t)(tap * DIM + n) * DIM + k] = l;
}
__global__ void wprep_gate_kernel(const float* __restrict__ W, int dir, int krow0,
                                  __nv_bfloat16* __restrict__ dstHi,
                                  __nv_bfloat16* __restrict__ dstLo)
{
    int idx = blockIdx.x * 256 + threadIdx.x;
    if (idx >= GDIM * DIM) return;
    int n = idx / DIM, k = idx % DIM;
    float v = W[(size_t)(krow0 + k) * GDIM + n];
    __nv_bfloat16 h = __float2bfloat16(v);
    __nv_bfloat16 l = __float2bfloat16(v - __bfloat162float(h));
    dstHi[idx] = h;
    dstLo[idx] = l;
}

// =================== embedding -> bf16 hi/lo =================================
__global__ void embed_kernel(const int* __restrict__ x, const float* __restrict__ ew)
{
    int m = blockIdx.x;
    int tok = x[m];
    int j = threadIdx.x;
    float4 v = ((const float4*)(ew + (size_t)tok * DIM))[j];
    float f[4] = {v.x, v.y, v.z, v.w};
    __nv_bfloat16 h[4], l[4];
    #pragma unroll
    for (int i = 0; i < 4; i++) {
        h[i] = __float2bfloat16(f[i]);
        l[i] = __float2bfloat16(f[i] - __bfloat162float(h[i]));
    }
    *(uint2*)(g_aHi + (size_t)m * DIM + j * 4) = *(uint2*)h;
    *(uint2*)(g_aLo + (size_t)m * DIM + j * 4) = *(uint2*)l;
}

// =================== bf16 mma.sync GEMM =======================================
// bperm=0 (conv): tile rows = 128 consecutive m.  bperm=1 (gates): tile rows =
// 32 batches x 4 timesteps (m = (r&31)*1024 + blockIdx.x*4 + (r>>5)) so the
// gpre epilogue can write full 128B lines of [t][n][b-contiguous].
__global__ void __launch_bounds__(256, 2) mma_gemm_kernel(
    const __nv_bfloat16* __restrict__ Ahi, const __nv_bfloat16* __restrict__ Alo,
    const __nv_bfloat16* __restrict__ BwHi, const __nv_bfloat16* __restrict__ BwLo,
    int taps, int layer, int bperm,
    __nv_bfloat16* __restrict__ outHi, __nv_bfloat16* __restrict__ outLo,
    const float* __restrict__ bias, float* __restrict__ gout)
{
    extern __shared__ char smem[];
    const int tid = threadIdx.x;
    const int lane = tid & 31, wid = tid >> 5;
    const int wm = wid & 3, wn = wid >> 2;
    const int m0 = blockIdx.x * 128, n0 = blockIdx.y * 128;
    const int t0 = m0 & (LSEQ - 1);
    const int tb4 = blockIdx.x * 4;      // bperm: base timestep
    const uint32_t sb = smem_to_u32(smem);

    const int off0  = taps >> 1;
    const int arows = 128 + (taps - 1);

    float acc[2][8][4];
    #pragma unroll
    for (int a = 0; a < 2; a++)
        #pragma unroll
        for (int b = 0; b < 8; b++)
            #pragma unroll
            for (int c = 0; c < 4; c++) acc[a][b][c] = 0.f;

    #define DO_COPY_A(SLICE) do { \
        const int _kb = (SLICE) << 6; \
        const int _tot = arows * 8; \
        for (int _i = tid; _i < _tot; _i += 256) { \
            int _r = _i >> 3, _c8 = (_i & 7) << 3; \
            uint32_t _off = (uint32_t)(_r * 128) + (((uint32_t)_c8 * 2) ^ (((uint32_t)_r & 7) << 4)); \
            uint4 _vh = make_uint4(0u,0u,0u,0u), _vl = _vh; \
            if (bperm) { \
                size_t _ga = (size_t)(((_r & 31) << 10) + tb4 + (_r >> 5)) * DIM + _kb + _c8; \
                _vh = *(const uint4*)(Ahi + _ga); \
                _vl = *(const uint4*)(Alo + _ga); \
            } else { \
                int _tl = t0 + _r - off0; \
                if (_tl >= 0 && _tl < LSEQ) { \
                    size_t _ga = (size_t)(m0 + _r - off0) * DIM + _kb + _c8; \
                    _vh = *(const uint4*)(Ahi + _ga); \
                    _vl = *(const uint4*)(Alo + _ga); \
                } \
            } \
            *(uint4*)(smem + _off) = _vh; \
            *(uint4*)(smem + 16640 + _off) = _vl; \
        } \
    } while (0)

    #define DO_COPY_B(IDX, ST) do { \
        const int _sl = (IDX) / taps, _tp = (IDX) % taps; \
        const int _kb = _sl << 6; \
        const int _rbase = (taps == 3 ? _tp * DIM : 0) + n0; \
        char* _bp = smem + 33280 + (ST) * 32768; \
        for (int _i = tid; _i < 1024; _i += 256) { \
            int _r = _i >> 3, _c8 = (_i & 7) << 3; \
            uint32_t _off = (uint32_t)(_r * 128) + (((uint32_t)_c8 * 2) ^ (((uint32_t)_r & 7) << 4)); \
            size_t _ga = (size_t)(_rbase + _r) * DIM + _kb + _c8; \
            *(uint4*)(_bp + _off) = *(const uint4*)(BwHi + _ga); \
            *(uint4*)(_bp + 16384 + _off) = *(const uint4*)(BwLo + _ga); \
        } \
    } while (0)

    const int NB = 8 * taps;
    DO_COPY_A(0);
    DO_COPY_B(0, 0);
    __syncthreads();

    for (int idx = 0; idx < NB; idx++) {
        const int tap = idx % taps;
        const int bsel = idx & 1;
        const bool lastTap = (tap == taps - 1);

        if (idx + 1 < NB) DO_COPY_B(idx + 1, bsel ^ 1);

        const uint32_t aHiB = sb;
        const uint32_t aLoB = sb + 16640;
        const uint32_t bHiB = sb + 33280 + (uint32_t)bsel * 32768;
        const uint32_t bLoB = bHiB + 16384;
        #pragma unroll
        for (int k16 = 0; k16 < 4; k16++) {
            const uint32_t colA = (uint32_t)(k16 * 32) + (((uint32_t)lane >> 4) << 4);
            const uint32_t colB = (uint32_t)(k16 * 32) + ((((uint32_t)lane >> 3) & 1) << 4);
            uint32_t afh[2][4], afl[2][4];
            #pragma unroll
            for (int mt = 0; mt < 2; mt++) {
                uint32_t row = (uint32_t)(wm * 32 + mt * 16 + (lane & 15) + tap);
                uint32_t ad = row * 128 + (colA ^ ((row & 7) << 4));
                LDSM_X4(afh[mt][0], afh[mt][1], afh[mt][2], afh[mt][3], aHiB + ad);
                LDSM_X4(afl[mt][0], afl[mt][1], afl[mt][2], afl[mt][3], aLoB + ad);
            }
            #pragma unroll
            for (int half = 0; half < 2; half++) {
                uint32_t bfh[4][2], bfl[4][2];
                #pragma unroll
                for (int np = 0; np < 2; np++) {
                    uint32_t row = (uint32_t)(wn * 64 + (half * 2 + np) * 16 +
                                              (((lane >> 4) << 3) | (lane & 7)));
                    uint32_t bd = row * 128 + (colB ^ ((row & 7) << 4));
                    LDSM_X4(bfh[2*np][0], bfh[2*np][1], bfh[2*np+1][0], bfh[2*np+1][1], bHiB + bd);
                    LDSM_X4(bfl[2*np][0], bfl[2*np][1], bfl[2*np+1][0], bfl[2*np+1][1], bLoB + bd);
                }
                #pragma unroll
                for (int mt = 0; mt < 2; mt++)
                    #pragma unroll
                    for (int nt = 0; nt < 4; nt++) {
                        float* ac = acc[mt][half * 4 + nt];
                        MMA16816(ac, afh[mt], bfh[nt]);
                        MMA16816(ac, afl[mt], bfh[nt]);
                        MMA16816(ac, afh[mt], bfl[nt]);
                    }
            }
        }
        __syncthreads();
        if (lastTap && idx + 1 < NB) {
            DO_COPY_A((idx + 1) / taps);
            __syncthreads();
        }
    }
    #undef DO_COPY_A
    #undef DO_COPY_B

    const int g  = lane >> 2;
    const int tg = lane & 3;
    if (gout == nullptr) {            // conv epilogue
        #pragma unroll
        for (int mt = 0; mt < 2; mt++) {
            const int mlo = m0 + wm * 32 + mt * 16 + g;
            const int mhi = mlo + 8;
            #pragma unroll
            for (int nt = 0; nt < 8; nt++) {
                const int n = n0 + wn * 64 + nt * 8 + tg * 2;
                const float al0 = g_alpha[layer][n],     be0 = g_beta[layer][n];
                const float al1 = g_alpha[layer][n + 1], be1 = g_beta[layer][n + 1];
                float v00 = fmaxf(fmaf(acc[mt][nt][0], al0, be0), 0.f);
                float v01 = fmaxf(fmaf(acc[mt][nt][1], al1, be1), 0.f);
                float v10 = fmaxf(fmaf(acc[mt][nt][2], al0, be0), 0.f);
                float v11 = fmaxf(fmaf(acc[mt][nt][3], al1, be1), 0.f);
                __nv_bfloat16 h00 = __float2bfloat16(v00), h01 = __float2bfloat16(v01);
                __nv_bfloat16 h10 = __float2bfloat16(v10), h11 = __float2bfloat16(v11);
                __nv_bfloat16 l00 = __float2bfloat16(v00 - __bfloat162float(h00));
                __nv_bfloat16 l01 = __float2bfloat16(v01 - __bfloat162float(h01));
                __nv_bfloat16 l10 = __float2bfloat16(v10 - __bfloat162float(h10));
                __nv_bfloat16 l11 = __float2bfloat16(v11 - __bfloat162float(h11));
                __nv_bfloat162 ph0; ph0.x = h00; ph0.y = h01;
                __nv_bfloat162 ph1; ph1.x = h10; ph1.y = h11;
                __nv_bfloat162 pl0; pl0.x = l00; pl0.y = l01;
                __nv_bfloat162 pl1; pl1.x = l10; pl1.y = l11;
                *(__nv_bfloat162*)(outHi + (size_t)mlo * DIM + n) = ph0;
                *(__nv_bfloat162*)(outHi + (size_t)mhi * DIM + n) = ph1;
                *(__nv_bfloat162*)(outLo + (size_t)mlo * DIM + n) = pl0;
                *(__nv_bfloat162*)(outLo + (size_t)mhi * DIM + n) = pl1;
            }
        }
    } else {                          // gates (bperm): smem transpose -> coalesced
        float* tile = (float*)smem;   // [128 rows][129] fp32 = 66048 B
        #pragma unroll
        for (int mt = 0; mt < 2; mt++) {
            const int rlo = wm * 32 + mt * 16 + g;
            const int rhi = rlo + 8;
            #pragma unroll
            for (int nt = 0; nt < 8; nt++) {
                const int nl = wn * 64 + nt * 8 + tg * 2;
                const float b0 = bias[n0 + nl], b1 = bias[n0 + nl + 1];
                tile[rlo * 129 + nl    ] = acc[mt][nt][0] + b0;
                tile[rlo * 129 + nl + 1] = acc[mt][nt][1] + b1;
                tile[rhi * 129 + nl    ] = acc[mt][nt][2] + b0;
                tile[rhi * 129 + nl + 1] = acc[mt][nt][3] + b1;
            }
        }
        __syncthreads();
        // write: warp covers 32 contiguous b for fixed (t, n) -> full 128B lines
        for (int i = tid; i < 16384; i += 256) {
            int b_  = i & 31;
            int nl  = (i >> 5) & 127;
            int tt  = i >> 12;
            gout[((size_t)(tb4 + tt) * GDIM + n0 + nl) * 32 + b_] =
                tile[(tt * 32 + b_) * 129 + nl];
        }
    }
}

// =================== persistent LSTM recurrence — tensor-core matvec =========
// 512 threads, 16 warps. Block: dir = bid>>6, dims dc..dc+7, N=32 permuted cols.
// Warp u owns 6 k16 tiles (96 total over K_eff=1536: A [hi,lo,hi], W [hi,hi,lo]).
#define R_WHI 0
#define R_WLO 33280
#define R_AHI 66560
#define R_ALO 99840
#define R_PART 133120                       // 16*32*33*4 = 67584
#define R_OUT  (R_PART + 67584)             // hh 288 f32 + pk 288 u32
#define R_SMEM (R_OUT + 2304)               // 203008

__global__ void __launch_bounds__(512, 1) lstm_recur_kernel(
    const __nv_bfloat16* __restrict__ wrHi, const __nv_bfloat16* __restrict__ wrLo,
    const int* __restrict__ lengths, const float* __restrict__ gpreAll,
    float* __restrict__ out)
{
    extern __shared__ char sm[];
    float* part = (float*)(sm + R_PART);
    float* obh  = (float*)(sm + R_OUT);
    unsigned* obp = (unsigned*)(sm + R_OUT + 1152);
    __shared__ int len_s[32];

    const int tid = threadIdx.x;
    const int lane = tid & 31, u = tid >> 5;        // u in [0,16)
    const int dir = blockIdx.x >> 6;
    const int dc  = (blockIdx.x & 63) << 3;
    const uint32_t sb = smem_to_u32(sm);
    const float* gpre = gpreAll + (size_t)dir * MTOT * GDIM;
    const __nv_bfloat16* wHi = wrHi + (size_t)dir * GDIM * DIM;
    const __nv_bfloat16* wLo = wrLo + (size_t)dir * GDIM * DIM;

    for (int i = tid; i < 2048; i += 512) {
        int r = i >> 6, c16 = i & 63;
        int n = ((r >> 3) << 9) + dc + (r & 7);
        uint4 vh = *(const uint4*)(wHi + (size_t)n * DIM + c16 * 8);
        uint4 vl = *(const uint4*)(wLo + (size_t)n * DIM + c16 * 8);
        *(uint4*)(sm + R_WHI + r * 1040 + c16 * 16) = vh;
        *(uint4*)(sm + R_WLO + r * 1040 + c16 * 16) = vl;
    }
    if (tid < 32) len_s[tid] = lengths[tid];
    if (tid < 256) g_hpk[0][dir][lane * DIM + dc + (u & 7)] = 0u;
    __syncthreads();

    // preload W fragments: 6 tiles/warp x 8 regs = 48 regs
    uint32_t wf[6][8];
    {
        const uint32_t rB = (uint32_t)(((lane >> 4) << 3) | (lane & 7));
        const uint32_t hB = (uint32_t)(((lane >> 3) & 1) << 4);
        #pragma unroll
        for (int i = 0; i < 6; i++) {
            int tt = u * 6 + i;
            int sec = tt >> 5, kk = tt & 31;
            uint32_t base = sb + (sec == 2 ? R_WLO : R_WHI);
            uint32_t col = (uint32_t)(kk * 32) + hB;
            LDSM_X4(wf[i][0], wf[i][1], wf[i][2], wf[i][3], base + rB * 1040 + col);
            LDSM_X4(wf[i][4], wf[i][5], wf[i][6], wf[i][7], base + (rB + 16) * 1040 + col);
        }
    }
    const int lenb = len_s[lane];
    dir_sync_(dir, 64);

    const uint32_t rA = (uint32_t)(lane & 15);
    const uint32_t hA = (uint32_t)((lane >> 4) << 4);
    float cst = 0.f;

    for (int s = 0; s < LSEQ; s++) {
        const int t = dir ? (LSEQ - 1 - s) : s;
        const int p = s & 1;

        float gp0 = 0.f, gp1 = 0.f, gp2 = 0.f, gp3 = 0.f;
        if (u < 8) {
            const float* gq = gpre + ((size_t)t * GDIM + dc + u) * 32 + lane;
            gp0 = __ldg(gq + (size_t)(0 * 512) * 32);
            gp1 = __ldg(gq + (size_t)(1 * 512) * 32);
            gp2 = __ldg(gq + (size_t)(2 * 512) * 32);
            gp3 = __ldg(gq + (size_t)(3 * 512) * 32);
        }

        {   // stage h_prev (packed bf16 hi|lo) into A smem
            const uint4* hp = (const uint4*)g_hpk[p][dir];
            #pragma unroll
            for (int i = 0; i < 8; i++) {
                int idx = i * 512 + tid;            // 0..4095
                int b_ = idx >> 7, c4 = idx & 127;
                uint4 v = __ldcg(hp + idx);
                if (dir && t >= len_s[b_] - 1) v = make_uint4(0u, 0u, 0u, 0u);
                unsigned h01 = __byte_perm(v.x, v.y, 0x5410);
                unsigned h23 = __byte_perm(v.z, v.w, 0x5410);
                unsigned l01 = __byte_perm(v.x, v.y, 0x7632);
                unsigned l23 = __byte_perm(v.z, v.w, 0x7632);
                *(uint2*)(sm + R_AHI + b_ * 1040 + c4 * 8) = make_uint2(h01, h23);
                *(uint2*)(sm + R_ALO + b_ * 1040 + c4 * 8) = make_uint2(l01, l23);
            }
        }
        __syncthreads();

        float acc[2][4][4];
        #pragma unroll
        for (int a = 0; a < 2; a++)
            #pragma unroll
            for (int b = 0; b < 4; b++)
                #pragma unroll
                for (int c = 0; c < 4; c++) acc[a][b][c] = 0.f;

        #pragma unroll
        for (int i = 0; i < 6; i++) {
            int tt = u * 6 + i;
            int sec = tt >> 5, kk = tt & 31;
            uint32_t base = sb + (sec == 1 ? R_ALO : R_AHI);
            uint32_t col = (uint32_t)(kk * 32) + hA;
            uint32_t af0[4], af1[4];
            LDSM_X4(af0[0], af0[1], af0[2], af0[3], base + rA * 1040 + col);
            LDSM_X4(af1[0], af1[1], af1[2], af1[3], base + (rA + 16) * 1040 + col);
            #pragma unroll
            for (int nt = 0; nt < 4; nt++) {
                MMA16816(acc[0][nt], af0, &wf[i][nt * 2]);
                MMA16816(acc[1][nt], af1, &wf[i][nt * 2]);
            }
        }

        {
            int row = lane >> 2, colp = (lane & 3) * 2;
            #pragma unroll
            for (int mt = 0; mt < 2; mt++)
                #pragma unroll
                for (int nt = 0; nt < 4; nt++) {
                    float* p0 = part + (u * 32 + mt * 16 + row) * 33 + nt * 8 + colp;
                    p0[0] = acc[mt][nt][0]; p0[1] = acc[mt][nt][1];
                    float* p1 = part + (u * 32 + mt * 16 + row + 8) * 33 + nt * 8 + colp;
                    p1[0] = acc[mt][nt][2]; p1[1] = acc[mt][nt][3];
                }
        }
        __syncthreads();

        if (u < 8) {   // thread (lane=b, u=dim): reduce 16 warps + cell update
            float s0 = 0.f, s1 = 0.f, s2 = 0.f, s3 = 0.f;
            #pragma unroll
            for (int w = 0; w < 16; w++) {
                const float* pr = part + (w * 32 + lane) * 33;
                s0 += pr[u]; s1 += pr[8 + u]; s2 += pr[16 + u]; s3 += pr[24 + u];
            }
            float iv = sigmoidf_(gp0 + s0);
            float gv = tanhf(gp1 + s1);
            float fv = sigmoidf_(gp2 + s2 + 1.f);
            float ov = sigmoidf_(gp3 + s3);
            if (dir && t >= lenb - 1) cst = 0.f;
            cst = fv * cst + iv * gv;
            float hh = ov * tanhf(cst);

            __nv_bfloat16 hb = __float2bfloat16(hh);
            __nv_bfloat16 lb = __float2bfloat16(hh - __bfloat162float(hb));
            unsigned pk = (unsigned)__bfloat16_as_ushort(hb) |
                          ((unsigned)__bfloat16_as_ushort(lb) << 16);
            obh[lane * 9 + u] = hh;
            obp[lane * 9 + u] = pk;
        }
        __syncthreads();

        if (tid < 256) {   // coalesced writes: warp = 4 b x 8 contiguous dims
            int b2 = tid >> 3, d2 = tid & 7;
            g_hpk[p ^ 1][dir][b2 * DIM + dc + d2] = obp[b2 * 9 + d2];
            out[(((size_t)b2 << 10) + t) * 1024 + (dir << 9) + dc + d2] = obh[b2 * 9 + d2];
        }

        dir_sync_(dir, 64);
    }
}

// =================== launch ===================================================
extern "C" void kernel_launch(void* const* d_in, const int* in_sizes, int n_in,
                              void* d_out, int out_size)
{
    (void)in_sizes; (void)n_in; (void)out_size;
    const int*   x        = (const int*)  d_in[0];
    const int*   lengths  = (const int*)  d_in[1];
    const float* embed_w  = (const float*)d_in[2];
    const float* c1w = (const float*)d_in[3];
    const float* c1b = (const float*)d_in[4];
    const float* c2w = (const float*)d_in[5];
    const float* c2b = (const float*)d_in[6];
    const float* c3w = (const float*)d_in[7];
    const float* c3b = (const float*)d_in[8];
    const float* wf  = (const float*)d_in[9];
    const float* bf  = (const float*)d_in[10];
    const float* wb  = (const float*)d_in[11];
    const float* bb  = (const float*)d_in[12];
    const float* s1 = (const float*)d_in[13]; const float* o1 = (const float*)d_in[14];
    const float* m1 = (const float*)d_in[15]; const float* v1 = (const float*)d_in[16];
    const float* s2 = (const float*)d_in[17]; const float* o2 = (const float*)d_in[18];
    const float* m2 = (const float*)d_in[19]; const float* v2 = (const float*)d_in[20];
    const float* s3 = (const float*)d_in[21]; const float* o3 = (const float*)d_in[22];
    const float* m3 = (const float*)d_in[23]; const float* v3 = (const float*)d_in[24];
    float* out = (float*)d_out;

    __nv_bfloat16 *aHi, *aLo, *bHi, *bLo, *wcH, *wcL, *wgH, *wgL, *wrH, *wrL;
    cudaGetSymbolAddress((void**)&aHi, g_aHi);
    cudaGetSymbolAddress((void**)&aLo, g_aLo);
    cudaGetSymbolAddress((void**)&bHi, g_bHi);
    cudaGetSymbolAddress((void**)&bLo, g_bLo);
    cudaGetSymbolAddress((void**)&wcH, g_wcHi);
    cudaGetSymbolAddress((void**)&wcL, g_wcLo);
    cudaGetSymbolAddress((void**)&wgH, g_wgHi);
    cudaGetSymbolAddress((void**)&wgL, g_wgLo);
    cudaGetSymbolAddress((void**)&wrH, g_wrHi);
    cudaGetSymbolAddress((void**)&wrL, g_wrLo);
    float* gpre;
    cudaGetSymbolAddress((void**)&gpre, g_gpre);

    const size_t WC = (size_t)3 * DIM * DIM;
    const size_t WG = (size_t)GDIM * DIM;

    const int SMEM_GEMM  = 33280 + 2 * 32768;     // 98816
    cudaFuncSetAttribute(mma_gemm_kernel,
                         cudaFuncAttributeMaxDynamicSharedMemorySize, SMEM_GEMM);
    cudaFuncSetAttribute(lstm_recur_kernel,
                         cudaFuncAttributeMaxDynamicSharedMemorySize, R_SMEM);

    dim3 gconv(MTOT / 128, DIM / 128);
    dim3 ggate(MTOT / 128, GDIM / 128);
    const int NWC = (3 * DIM * DIM + 255) / 256;
    const int NWG = (GDIM * DIM + 255) / 256;

    wprep_conv_kernel<<<NWC, 256>>>(c1w, 0);
    bnprep_kernel<<<1, 512>>>(c1b, s1, o1, m1, v1,
                              c2b, s2, o2, m2, v2,
                              c3b, s3, o3, m3, v3);
    embed_kernel<<<MTOT, 128>>>(x, embed_w);
    mma_gemm_kernel<<<gconv, 256, SMEM_GEMM>>>(aHi, aLo, wcH + 0 * WC, wcL + 0 * WC,
        3, 0, 0, bHi, bLo, nullptr, nullptr);
    wprep_conv_kernel<<<NWC, 256>>>(c2w, 1);
    mma_gemm_kernel<<<gconv, 256, SMEM_GEMM>>>(bHi, bLo, wcH + 1 * WC, wcL + 1 * WC,
        3, 1, 0, aHi, aLo, nullptr, nullptr);
    wprep_conv_kernel<<<NWC, 256>>>(c3w, 2);
    mma_gemm_kernel<<<gconv, 256, SMEM_GEMM>>>(aHi, aLo, wcH + 2 * WC, wcL + 2 * WC,
        3, 2, 0, bHi, bLo, nullptr, nullptr);
    wprep_gate_kernel<<<NWG, 256>>>(wf, 0, 0,   wgH + 0 * WG, wgL + 0 * WG);
    wprep_gate_kernel<<<NWG, 256>>>(wb, 1, 0,   wgH + 1 * WG, wgL + 1 * WG);
    wprep_gate_kernel<<<NWG, 256>>>(wf, 0, DIM, wrH + 0 * WG, wrL + 0 * WG);
    wprep_gate_kernel<<<NWG, 256>>>(wb, 1, DIM, wrH + 1 * WG, wrL + 1 * WG);
    mma_gemm_kernel<<<ggate, 256, SMEM_GEMM>>>(bHi, bLo, wgH + 0 * WG, wgL + 0 * WG,
        1, -1, 1, nullptr, nullptr, bf, gpre + 0);
    mma_gemm_kernel<<<ggate, 256, SMEM_GEMM>>>(bHi, bLo, wgH + 1 * WG, wgL + 1 * WG,
        1, -1, 1, nullptr, nullptr, bb, gpre + (size_t)MTOT * GDIM);
    lstm_recur_kernel<<<128, 512, R_SMEM>>>(wrH, wrL, lengths, gpre, out);
}

// round 9
// speedup vs baseline: 2.6013x; 1.0257x over previous
#include <cuda_runtime.h>
#include <cuda_bf16.h>
#include <stdint.h>
#include <math.h>

#define BSZ   32
#define LSEQ  1024
#define DIM   512
#define MTOT  (BSZ*LSEQ)          // 32768
#define GDIM  2048                // 4*DIM

// =================== scratch (device globals) ================================
__device__ __align__(128) __nv_bfloat16 g_aHi[(size_t)MTOT*DIM];
__device__ __align__(128) __nv_bfloat16 g_aLo[(size_t)MTOT*DIM];
__device__ __align__(128) __nv_bfloat16 g_bHi[(size_t)MTOT*DIM];
__device__ __align__(128) __nv_bfloat16 g_bLo[(size_t)MTOT*DIM];
__device__ __align__(128) __nv_bfloat16 g_wcHi[3][(size_t)3*DIM*DIM];   // [layer][tap*512+n][k]
__device__ __align__(128) __nv_bfloat16 g_wcLo[3][(size_t)3*DIM*DIM];
__device__ __align__(128) __nv_bfloat16 g_wgHi[2][(size_t)GDIM*DIM];    // [dir][n][k]
__device__ __align__(128) __nv_bfloat16 g_wgLo[2][(size_t)GDIM*DIM];
__device__ __align__(128) __nv_bfloat16 g_wrHi[2][(size_t)GDIM*DIM];    // recurrent W
__device__ __align__(128) __nv_bfloat16 g_wrLo[2][(size_t)GDIM*DIM];
__device__ float g_gpre[2][(size_t)MTOT*GDIM];   // [dir][ (t*2048 + col)*32 + b ]
__device__ unsigned g_hpk[2][2][BSZ*DIM];        // [parity][dir][b*512+d] packed
__device__ float g_alpha[3][DIM];
__device__ float g_beta[3][DIM];
__device__ __align__(1024) unsigned g_arr2[2][256];   // padded: dirs 1KB apart
__device__ __align__(1024) unsigned g_gen2[2][256];

// =================== primitives ===============================================
__device__ __forceinline__ uint32_t smem_to_u32(const void* p) {
    uint32_t a;
    asm("{ .reg .u64 t; cvta.to.shared.u64 t, %1; cvt.u32.u64 %0, t; }" : "=r"(a) : "l"(p));
    return a;
}
#define LDSM_X4(r0, r1, r2, r3, addr) \
    asm volatile("ldmatrix.sync.aligned.m8n8.x4.shared.b16 {%0,%1,%2,%3}, [%4];" \
        : "=r"(r0), "=r"(r1), "=r"(r2), "=r"(r3) : "r"(addr))
#define MMA16816(c, a, b) \
    asm volatile("mma.sync.aligned.m16n8k16.row.col.f32.bf16.bf16.f32 " \
        "{%0,%1,%2,%3}, {%4,%5,%6,%7}, {%8,%9}, {%0,%1,%2,%3};" \
        : "+f"((c)[0]), "+f"((c)[1]), "+f"((c)[2]), "+f"((c)[3]) \
        : "r"((a)[0]), "r"((a)[1]), "r"((a)[2]), "r"((a)[3]), \
          "r"((b)[0]), "r"((b)[1]))

__device__ __forceinline__ float tanh_fast_(float x) {
    float y;
    asm("tanh.approx.f32 %0, %1;" : "=f"(y) : "f"(x));
    return y;
}
__device__ __forceinline__ float sigmoid_fast_(float x) {
    return fmaf(tanh_fast_(0.5f * x), 0.5f, 0.5f);
}

// per-direction sense-reversal barrier (padded counters, release/acquire)
__device__ __forceinline__ void dir_sync_(int dir, unsigned nblk) {
    __syncthreads();
    if (threadIdx.x == 0) {
        unsigned* arr = &g_arr2[dir][0];
        unsigned* gen = &g_gen2[dir][0];
        unsigned cur;
        asm volatile("ld.acquire.gpu.global.u32 %0, [%1];" : "=r"(cur) : "l"(gen));
        unsigned prev;
        asm volatile("atom.release.gpu.global.add.u32 %0, [%1], 1;"
                     : "=r"(prev) : "l"(arr) : "memory");
        if (prev == nblk - 1) {
            *arr = 0u;
            unsigned nxt = cur + 1u;
            asm volatile("st.release.gpu.global.u32 [%0], %1;" :: "l"(gen), "r"(nxt) : "memory");
        } else {
            unsigned g;
            do {
                asm volatile("ld.acquire.gpu.global.u32 %0, [%1];" : "=r"(g) : "l"(gen));
            } while (g == cur);
        }
    }
    __syncthreads();
}

// =================== BN fold =================================================
__global__ void bnprep_kernel(
    const float* __restrict__ b1, const float* __restrict__ s1, const float* __restrict__ o1,
    const float* __restrict__ m1, const float* __restrict__ v1,
    const float* __restrict__ b2, const float* __restrict__ s2, const float* __restrict__ o2,
    const float* __restrict__ m2, const float* __restrict__ v2,
    const float* __restrict__ b3, const float* __restrict__ s3, const float* __restrict__ o3,
    const float* __restrict__ m3, const float* __restrict__ v3)
{
    int i = threadIdx.x;
    if (i < DIM) {
        float g;
        g = s1[i] * rsqrtf(v1[i] + 1e-5f); g_alpha[0][i] = g; g_beta[0][i] = (b1[i] - m1[i]) * g + o1[i];
        g = s2[i] * rsqrtf(v2[i] + 1e-5f); g_alpha[1][i] = g; g_beta[1][i] = (b2[i] - m2[i]) * g + o2[i];
        g = s3[i] * rsqrtf(v3[i] + 1e-5f); g_alpha[2][i] = g; g_beta[2][i] = (b3[i] - m3[i]) * g + o3[i];
    }
}

// =================== weight prep ==============================================
__global__ void wprep_conv_kernel(const float* __restrict__ Wc, int layer)
{
    int idx = blockIdx.x * 256 + threadIdx.x;
    if (idx >= 3 * DIM * DIM) return;
    int tap = idx / (DIM * DIM);
    int rem = idx - tap * DIM * DIM;
    int n = rem / DIM, k = rem % DIM;
    float v = Wc[(size_t)(tap * DIM + k) * DIM + n];
    __nv_bfloat16 h = __float2bfloat16(v);
    __nv_bfloat16 l = __float2bfloat16(v - __bfloat162float(h));
    g_wcHi[layer][(size_t)(tap * DIM + n) * DIM + k] = h;
    g_wcLo[layer][(size_t)(tap * DIM + n) * DIM + k] = l;
}
// coalesced transpose: W rows (krow0+k)[GDIM] -> dst[n][k], 32x32 tiles
__global__ void wprep_gate_kernel(const float* __restrict__ W, int krow0,
                                  __nv_bfloat16* __restrict__ dstHi,
                                  __nv_bfloat16* __restrict__ dstLo)
{
    __shared__ float tile[32][33];
    const int tx = threadIdx.x;          // 0..31
    const int ty = threadIdx.y;          // 0..7
    const int k0 = blockIdx.x * 32;
    const int n0 = blockIdx.y * 32;
    #pragma unroll
    for (int i = 0; i < 4; i++) {
        int k = k0 + ty + i * 8;
        tile[ty + i * 8][tx] = W[(size_t)(krow0 + k) * GDIM + n0 + tx];
    }
    __syncthreads();
    #pragma unroll
    for (int i = 0; i < 4; i++) {
        int n = n0 + ty + i * 8;
        float v = tile[tx][ty + i * 8];
        __nv_bfloat16 h = __float2bfloat16(v);
        __nv_bfloat16 l = __float2bfloat16(v - __bfloat162float(h));
        dstHi[(size_t)n * DIM + k0 + tx] = h;
        dstLo[(size_t)n * DIM + k0 + tx] = l;
    }
}

// =================== embedding -> bf16 hi/lo =================================
__global__ void embed_kernel(const int* __restrict__ x, const float* __restrict__ ew)
{
    int m = blockIdx.x;
    int tok = x[m];
    int j = threadIdx.x;
    float4 v = ((const float4*)(ew + (size_t)tok * DIM))[j];
    float f[4] = {v.x, v.y, v.z, v.w};
    __nv_bfloat16 h[4], l[4];
    #pragma unroll
    for (int i = 0; i < 4; i++) {
        h[i] = __float2bfloat16(f[i]);
        l[i] = __float2bfloat16(f[i] - __bfloat162float(h[i]));
    }
    *(uint2*)(g_aHi + (size_t)m * DIM + j * 4) = *(uint2*)h;
    *(uint2*)(g_aLo + (size_t)m * DIM + j * 4) = *(uint2*)l;
}

// =================== bf16 mma.sync GEMM =======================================
// bperm=0 (conv): tile rows = 128 consecutive m.  bperm=1 (gates): rows =
// 32 batches x 4 timesteps; blockIdx.z = direction (weights/bias/gout offset).
__global__ void __launch_bounds__(256, 2) mma_gemm_kernel(
    const __nv_bfloat16* __restrict__ Ahi, const __nv_bfloat16* __restrict__ Alo,
    const __nv_bfloat16* __restrict__ BwHi, const __nv_bfloat16* __restrict__ BwLo,
    int taps, int layer, int bperm,
    __nv_bfloat16* __restrict__ outHi, __nv_bfloat16* __restrict__ outLo,
    const float* __restrict__ biasA, const float* __restrict__ biasB,
    float* __restrict__ gout)
{
    extern __shared__ char smem[];
    const int tid = threadIdx.x;
    const int lane = tid & 31, wid = tid >> 5;
    const int wm = wid & 3, wn = wid >> 2;
    const int m0 = blockIdx.x * 128, n0 = blockIdx.y * 128;
    const int t0 = m0 & (LSEQ - 1);
    const int tb4 = blockIdx.x * 4;
    const int dz = blockIdx.z;
    const uint32_t sb = smem_to_u32(smem);

    if (bperm) {
        BwHi += (size_t)dz * GDIM * DIM;
        BwLo += (size_t)dz * GDIM * DIM;
        gout += (size_t)dz * MTOT * GDIM;
    }
    const float* bias = dz ? biasB : biasA;

    const int off0  = taps >> 1;
    const int arows = 128 + (taps - 1);

    float acc[2][8][4];
    #pragma unroll
    for (int a = 0; a < 2; a++)
        #pragma unroll
        for (int b = 0; b < 8; b++)
            #pragma unroll
            for (int c = 0; c < 4; c++) acc[a][b][c] = 0.f;

    #define DO_COPY_A(SLICE) do { \
        const int _kb = (SLICE) << 6; \
        const int _tot = arows * 8; \
        for (int _i = tid; _i < _tot; _i += 256) { \
            int _r = _i >> 3, _c8 = (_i & 7) << 3; \
            uint32_t _off = (uint32_t)(_r * 128) + (((uint32_t)_c8 * 2) ^ (((uint32_t)_r & 7) << 4)); \
            uint4 _vh = make_uint4(0u,0u,0u,0u), _vl = _vh; \
            if (bperm) { \
                size_t _ga = (size_t)(((_r & 31) << 10) + tb4 + (_r >> 5)) * DIM + _kb + _c8; \
                _vh = *(const uint4*)(Ahi + _ga); \
                _vl = *(const uint4*)(Alo + _ga); \
            } else { \
                int _tl = t0 + _r - off0; \
                if (_tl >= 0 && _tl < LSEQ) { \
                    size_t _ga = (size_t)(m0 + _r - off0) * DIM + _kb + _c8; \
                    _vh = *(const uint4*)(Ahi + _ga); \
                    _vl = *(const uint4*)(Alo + _ga); \
                } \
            } \
            *(uint4*)(smem + _off) = _vh; \
            *(uint4*)(smem + 16640 + _off) = _vl; \
        } \
    } while (0)

    #define DO_COPY_B(IDX, ST) do { \
        const int _sl = (IDX) / taps, _tp = (IDX) % taps; \
        const int _kb = _sl << 6; \
        const int _rbase = (taps == 3 ? _tp * DIM : 0) + n0; \
        char* _bp = smem + 33280 + (ST) * 32768; \
        for (int _i = tid; _i < 1024; _i += 256) { \
            int _r = _i >> 3, _c8 = (_i & 7) << 3; \
            uint32_t _off = (uint32_t)(_r * 128) + (((uint32_t)_c8 * 2) ^ (((uint32_t)_r & 7) << 4)); \
            size_t _ga = (size_t)(_rbase + _r) * DIM + _kb + _c8; \
            *(uint4*)(_bp + _off) = *(const uint4*)(BwHi + _ga); \
            *(uint4*)(_bp + 16384 + _off) = *(const uint4*)(BwLo + _ga); \
        } \
    } while (0)

    const int NB = 8 * taps;
    DO_COPY_A(0);
    DO_COPY_B(0, 0);
    __syncthreads();

    for (int idx = 0; idx < NB; idx++) {
        const int tap = idx % taps;
        const int bsel = idx & 1;
        const bool lastTap = (tap == taps - 1);

        if (idx + 1 < NB) DO_COPY_B(idx + 1, bsel ^ 1);

        const uint32_t aHiB = sb;
        const uint32_t aLoB = sb + 16640;
        const uint32_t bHiB = sb + 33280 + (uint32_t)bsel * 32768;
        const uint32_t bLoB = bHiB + 16384;
        #pragma unroll
        for (int k16 = 0; k16 < 4; k16++) {
            const uint32_t colA = (uint32_t)(k16 * 32) + (((uint32_t)lane >> 4) << 4);
            const uint32_t colB = (uint32_t)(k16 * 32) + ((((uint32_t)lane >> 3) & 1) << 4);
            uint32_t afh[2][4], afl[2][4];
            #pragma unroll
            for (int mt = 0; mt < 2; mt++) {
                uint32_t row = (uint32_t)(wm * 32 + mt * 16 + (lane & 15) + tap);
                uint32_t ad = row * 128 + (colA ^ ((row & 7) << 4));
                LDSM_X4(afh[mt][0], afh[mt][1], afh[mt][2], afh[mt][3], aHiB + ad);
                LDSM_X4(afl[mt][0], afl[mt][1], afl[mt][2], afl[mt][3], aLoB + ad);
            }
            #pragma unroll
            for (int half = 0; half < 2; half++) {
                uint32_t bfh[4][2], bfl[4][2];
                #pragma unroll
                for (int np = 0; np < 2; np++) {
                    uint32_t row = (uint32_t)(wn * 64 + (half * 2 + np) * 16 +
                                              (((lane >> 4) << 3) | (lane & 7)));
                    uint32_t bd = row * 128 + (colB ^ ((row & 7) << 4));
                    LDSM_X4(bfh[2*np][0], bfh[2*np][1], bfh[2*np+1][0], bfh[2*np+1][1], bHiB + bd);
                    LDSM_X4(bfl[2*np][0], bfl[2*np][1], bfl[2*np+1][0], bfl[2*np+1][1], bLoB + bd);
                }
                #pragma unroll
                for (int mt = 0; mt < 2; mt++)
                    #pragma unroll
                    for (int nt = 0; nt < 4; nt++) {
                        float* ac = acc[mt][half * 4 + nt];
                        MMA16816(ac, afh[mt], bfh[nt]);
                        MMA16816(ac, afl[mt], bfh[nt]);
                        MMA16816(ac, afh[mt], bfl[nt]);
                    }
            }
        }
        __syncthreads();
        if (lastTap && idx + 1 < NB) {
            DO_COPY_A((idx + 1) / taps);
            __syncthreads();
        }
    }
    #undef DO_COPY_A
    #undef DO_COPY_B

    const int g  = lane >> 2;
    const int tg = lane & 3;
    if (gout == nullptr) {            // conv epilogue
        #pragma unroll
        for (int mt = 0; mt < 2; mt++) {
            const int mlo = m0 + wm * 32 + mt * 16 + g;
            const int mhi = mlo + 8;
            #pragma unroll
            for (int nt = 0; nt < 8; nt++) {
                const int n = n0 + wn * 64 + nt * 8 + tg * 2;
                const float al0 = g_alpha[layer][n],     be0 = g_beta[layer][n];
                const float al1 = g_alpha[layer][n + 1], be1 = g_beta[layer][n + 1];
                float v00 = fmaxf(fmaf(acc[mt][nt][0], al0, be0), 0.f);
                float v01 = fmaxf(fmaf(acc[mt][nt][1], al1, be1), 0.f);
                float v10 = fmaxf(fmaf(acc[mt][nt][2], al0, be0), 0.f);
                float v11 = fmaxf(fmaf(acc[mt][nt][3], al1, be1), 0.f);
                __nv_bfloat16 h00 = __float2bfloat16(v00), h01 = __float2bfloat16(v01);
                __nv_bfloat16 h10 = __float2bfloat16(v10), h11 = __float2bfloat16(v11);
                __nv_bfloat16 l00 = __float2bfloat16(v00 - __bfloat162float(h00));
                __nv_bfloat16 l01 = __float2bfloat16(v01 - __bfloat162float(h01));
                __nv_bfloat16 l10 = __float2bfloat16(v10 - __bfloat162float(h10));
                __nv_bfloat16 l11 = __float2bfloat16(v11 - __bfloat162float(h11));
                __nv_bfloat162 ph0; ph0.x = h00; ph0.y = h01;
                __nv_bfloat162 ph1; ph1.x = h10; ph1.y = h11;
                __nv_bfloat162 pl0; pl0.x = l00; pl0.y = l01;
                __nv_bfloat162 pl1; pl1.x = l10; pl1.y = l11;
                *(__nv_bfloat162*)(outHi + (size_t)mlo * DIM + n) = ph0;
                *(__nv_bfloat162*)(outHi + (size_t)mhi * DIM + n) = ph1;
                *(__nv_bfloat162*)(outLo + (size_t)mlo * DIM + n) = pl0;
                *(__nv_bfloat162*)(outLo + (size_t)mhi * DIM + n) = pl1;
            }
        }
    } else {                          // gates (bperm): smem transpose -> coalesced
        float* tile = (float*)smem;   // [128 rows][129] fp32
        #pragma unroll
        for (int mt = 0; mt < 2; mt++) {
            const int rlo = wm * 32 + mt * 16 + g;
            const int rhi = rlo + 8;
            #pragma unroll
            for (int nt = 0; nt < 8; nt++) {
                const int nl = wn * 64 + nt * 8 + tg * 2;
                const float b0 = bias[n0 + nl], b1 = bias[n0 + nl + 1];
                tile[rlo * 129 + nl    ] = acc[mt][nt][0] + b0;
                tile[rlo * 129 + nl + 1] = acc[mt][nt][1] + b1;
                tile[rhi * 129 + nl    ] = acc[mt][nt][2] + b0;
                tile[rhi * 129 + nl + 1] = acc[mt][nt][3] + b1;
            }
        }
        __syncthreads();
        for (int i = tid; i < 16384; i += 256) {
            int b_  = i & 31;
            int nl  = (i >> 5) & 127;
            int tt  = i >> 12;
            gout[((size_t)(tb4 + tt) * GDIM + n0 + nl) * 32 + b_] =
                tile[(tt * 32 + b_) * 129 + nl];
        }
    }
}

// =================== persistent LSTM recurrence — tensor-core matvec =========
#define R_WHI 0
#define R_WLO 33280
#define R_AHI 66560
#define R_ALO 99840
#define R_PART 133120                       // 16*32*33*4 = 67584
#define R_OUT  (R_PART + 67584)
#define R_SMEM (R_OUT + 2304)               // 203008

__global__ void __launch_bounds__(512, 1) lstm_recur_kernel(
    const __nv_bfloat16* __restrict__ wrHi, const __nv_bfloat16* __restrict__ wrLo,
    const int* __restrict__ lengths, const float* __restrict__ gpreAll,
    float* __restrict__ out)
{
    extern __shared__ char sm[];
    float* part = (float*)(sm + R_PART);
    float* obh  = (float*)(sm + R_OUT);
    unsigned* obp = (unsigned*)(sm + R_OUT + 1152);
    __shared__ int len_s[32];

    const int tid = threadIdx.x;
    const int lane = tid & 31, u = tid >> 5;        // u in [0,16)
    const int dir = blockIdx.x >> 6;
    const int dc  = (blockIdx.x & 63) << 3;
    const uint32_t sb = smem_to_u32(sm);
    const float* gpre = gpreAll + (size_t)dir * MTOT * GDIM;
    const __nv_bfloat16* wHi = wrHi + (size_t)dir * GDIM * DIM;
    const __nv_bfloat16* wLo = wrLo + (size_t)dir * GDIM * DIM;

    for (int i = tid; i < 2048; i += 512) {
        int r = i >> 6, c16 = i & 63;
        int n = ((r >> 3) << 9) + dc + (r & 7);
        uint4 vh = *(const uint4*)(wHi + (size_t)n * DIM + c16 * 8);
        uint4 vl = *(const uint4*)(wLo + (size_t)n * DIM + c16 * 8);
        *(uint4*)(sm + R_WHI + r * 1040 + c16 * 16) = vh;
        *(uint4*)(sm + R_WLO + r * 1040 + c16 * 16) = vl;
    }
    if (tid < 32) len_s[tid] = lengths[tid];
    if (tid < 256) g_hpk[0][dir][lane * DIM + dc + (u & 7)] = 0u;
    __syncthreads();

    uint32_t wf[6][8];
    {
        const uint32_t rB = (uint32_t)(((lane >> 4) << 3) | (lane & 7));
        const uint32_t hB = (uint32_t)(((lane >> 3) & 1) << 4);
        #pragma unroll
        for (int i = 0; i < 6; i++) {
            int tt = u * 6 + i;
            int sec = tt >> 5, kk = tt & 31;
            uint32_t base = sb + (sec == 2 ? R_WLO : R_WHI);
            uint32_t col = (uint32_t)(kk * 32) + hB;
            LDSM_X4(wf[i][0], wf[i][1], wf[i][2], wf[i][3], base + rB * 1040 + col);
            LDSM_X4(wf[i][4], wf[i][5], wf[i][6], wf[i][7], base + (rB + 16) * 1040 + col);
        }
    }
    const int lenb = len_s[lane];
    dir_sync_(dir, 64);

    const uint32_t rA = (uint32_t)(lane & 15);
    const uint32_t hA = (uint32_t)((lane >> 4) << 4);
    float cst = 0.f;

    // gpre double-buffer: preload step 0
    float gp0 = 0.f, gp1 = 0.f, gp2 = 0.f, gp3 = 0.f;
    if (u < 8) {
        const int t0_ = dir ? (LSEQ - 1) : 0;
        const float* gq = gpre + ((size_t)t0_ * GDIM + dc + u) * 32 + lane;
        gp0 = __ldg(gq);
        gp1 = __ldg(gq + (size_t)512 * 32);
        gp2 = __ldg(gq + (size_t)1024 * 32);
        gp3 = __ldg(gq + (size_t)1536 * 32);
    }

    for (int s = 0; s < LSEQ; s++) {
        const int t = dir ? (LSEQ - 1 - s) : s;
        const int p = s & 1;

        // issue next-step gpre loads immediately (hidden behind this step)
        float gn0 = 0.f, gn1 = 0.f, gn2 = 0.f, gn3 = 0.f;
        if (u < 8 && s + 1 < LSEQ) {
            const int tn = dir ? (LSEQ - 2 - s) : (s + 1);
            const float* gq = gpre + ((size_t)tn * GDIM + dc + u) * 32 + lane;
            gn0 = __ldg(gq);
            gn1 = __ldg(gq + (size_t)512 * 32);
            gn2 = __ldg(gq + (size_t)1024 * 32);
            gn3 = __ldg(gq + (size_t)1536 * 32);
        }

        {   // stage h_prev (packed bf16 hi|lo) into A smem
            const uint4* hp = (const uint4*)g_hpk[p][dir];
            #pragma unroll
            for (int i = 0; i < 8; i++) {
                int idx = i * 512 + tid;
                int b_ = idx >> 7, c4 = idx & 127;
                uint4 v = __ldcg(hp + idx);
                if (dir && t >= len_s[b_] - 1) v = make_uint4(0u, 0u, 0u, 0u);
                unsigned h01 = __byte_perm(v.x, v.y, 0x5410);
                unsigned h23 = __byte_perm(v.z, v.w, 0x5410);
                unsigned l01 = __byte_perm(v.x, v.y, 0x7632);
                unsigned l23 = __byte_perm(v.z, v.w, 0x7632);
                *(uint2*)(sm + R_AHI + b_ * 1040 + c4 * 8) = make_uint2(h01, h23);
                *(uint2*)(sm + R_ALO + b_ * 1040 + c4 * 8) = make_uint2(l01, l23);
            }
        }
        __syncthreads();

        float acc[2][4][4];
        #pragma unroll
        for (int a = 0; a < 2; a++)
            #pragma unroll
            for (int b = 0; b < 4; b++)
                #pragma unroll
                for (int c = 0; c < 4; c++) acc[a][b][c] = 0.f;

        #pragma unroll
        for (int i = 0; i < 6; i++) {
            int tt = u * 6 + i;
            int sec = tt >> 5, kk = tt & 31;
            uint32_t base = sb + (sec == 1 ? R_ALO : R_AHI);
            uint32_t col = (uint32_t)(kk * 32) + hA;
            uint32_t af0[4], af1[4];
            LDSM_X4(af0[0], af0[1], af0[2], af0[3], base + rA * 1040 + col);
            LDSM_X4(af1[0], af1[1], af1[2], af1[3], base + (rA + 16) * 1040 + col);
            #pragma unroll
            for (int nt = 0; nt < 4; nt++) {
                MMA16816(acc[0][nt], af0, &wf[i][nt * 2]);
                MMA16816(acc[1][nt], af1, &wf[i][nt * 2]);
            }
        }

        {
            int row = lane >> 2, colp = (lane & 3) * 2;
            #pragma unroll
            for (int mt = 0; mt < 2; mt++)
                #pragma unroll
                for (int nt = 0; nt < 4; nt++) {
                    float* p0 = part + (u * 32 + mt * 16 + row) * 33 + nt * 8 + colp;
                    p0[0] = acc[mt][nt][0]; p0[1] = acc[mt][nt][1];
                    float* p1 = part + (u * 32 + mt * 16 + row + 8) * 33 + nt * 8 + colp;
                    p1[0] = acc[mt][nt][2]; p1[1] = acc[mt][nt][3];
                }
        }
        __syncthreads();

        if (u < 8) {
            float s0 = 0.f, s1 = 0.f, s2 = 0.f, s3 = 0.f;
            #pragma unroll
            for (int w = 0; w < 16; w++) {
                const float* pr = part + (w * 32 + lane) * 33;
                s0 += pr[u]; s1 += pr[8 + u]; s2 += pr[16 + u]; s3 += pr[24 + u];
            }
            float iv = sigmoid_fast_(gp0 + s0);
            float gv = tanh_fast_(gp1 + s1);
            float fv = sigmoid_fast_(gp2 + s2 + 1.f);
            float ov = sigmoid_fast_(gp3 + s3);
            if (dir && t >= lenb - 1) cst = 0.f;
            cst = fv * cst + iv * gv;
            float hh = ov * tanh_fast_(cst);

            __nv_bfloat16 hb = __float2bfloat16(hh);
            __nv_bfloat16 lb = __float2bfloat16(hh - __bfloat162float(hb));
            unsigned pk = (unsigned)__bfloat16_as_ushort(hb) |
                          ((unsigned)__bfloat16_as_ushort(lb) << 16);
            obh[lane * 9 + u] = hh;
            obp[lane * 9 + u] = pk;
        }
        gp0 = gn0; gp1 = gn1; gp2 = gn2; gp3 = gn3;
        __syncthreads();

        if (tid < 256) {
            int b2 = tid >> 3, d2 = tid & 7;
            g_hpk[p ^ 1][dir][b2 * DIM + dc + d2] = obp[b2 * 9 + d2];
            out[(((size_t)b2 << 10) + t) * 1024 + (dir << 9) + dc + d2] = obh[b2 * 9 + d2];
        }

        dir_sync_(dir, 64);
    }
}

// =================== launch ===================================================
extern "C" void kernel_launch(void* const* d_in, const int* in_sizes, int n_in,
                              void* d_out, int out_size)
{
    (void)in_sizes; (void)n_in; (void)out_size;
    const int*   x        = (const int*)  d_in[0];
    const int*   lengths  = (const int*)  d_in[1];
    const float* embed_w  = (const float*)d_in[2];
    const float* c1w = (const float*)d_in[3];
    const float* c1b = (const float*)d_in[4];
    const float* c2w = (const float*)d_in[5];
    const float* c2b = (const float*)d_in[6];
    const float* c3w = (const float*)d_in[7];
    const float* c3b = (const float*)d_in[8];
    const float* wf  = (const float*)d_in[9];
    const float* bf  = (const float*)d_in[10];
    const float* wb  = (const float*)d_in[11];
    const float* bb  = (const float*)d_in[12];
    const float* s1 = (const float*)d_in[13]; const float* o1 = (const float*)d_in[14];
    const float* m1 = (const float*)d_in[15]; const float* v1 = (const float*)d_in[16];
    const float* s2 = (const float*)d_in[17]; const float* o2 = (const float*)d_in[18];
    const float* m2 = (const float*)d_in[19]; const float* v2 = (const float*)d_in[20];
    const float* s3 = (const float*)d_in[21]; const float* o3 = (const float*)d_in[22];
    const float* m3 = (const float*)d_in[23]; const float* v3 = (const float*)d_in[24];
    float* out = (float*)d_out;

    __nv_bfloat16 *aHi, *aLo, *bHi, *bLo, *wcH, *wcL, *wgH, *wgL, *wrH, *wrL;
    cudaGetSymbolAddress((void**)&aHi, g_aHi);
    cudaGetSymbolAddress((void**)&aLo, g_aLo);
    cudaGetSymbolAddress((void**)&bHi, g_bHi);
    cudaGetSymbolAddress((void**)&bLo, g_bLo);
    cudaGetSymbolAddress((void**)&wcH, g_wcHi);
    cudaGetSymbolAddress((void**)&wcL, g_wcLo);
    cudaGetSymbolAddress((void**)&wgH, g_wgHi);
    cudaGetSymbolAddress((void**)&wgL, g_wgLo);
    cudaGetSymbolAddress((void**)&wrH, g_wrHi);
    cudaGetSymbolAddress((void**)&wrL, g_wrLo);
    float* gpre;
    cudaGetSymbolAddress((void**)&gpre, g_gpre);

    const size_t WC = (size_t)3 * DIM * DIM;
    const size_t WG = (size_t)GDIM * DIM;

    const int SMEM_GEMM  = 33280 + 2 * 32768;     // 98816
    cudaFuncSetAttribute(mma_gemm_kernel,
                         cudaFuncAttributeMaxDynamicSharedMemorySize, SMEM_GEMM);
    cudaFuncSetAttribute(lstm_recur_kernel,
                         cudaFuncAttributeMaxDynamicSharedMemorySize, R_SMEM);

    dim3 gconv(MTOT / 128, DIM / 128, 1);
    dim3 ggate(MTOT / 128, GDIM / 128, 2);
    const int NWC = (3 * DIM * DIM + 255) / 256;
    dim3 gwp(DIM / 32, GDIM / 32);
    dim3 bwp(32, 8);

    wprep_conv_kernel<<<NWC, 256>>>(c1w, 0);
    bnprep_kernel<<<1, 512>>>(c1b, s1, o1, m1, v1,
                              c2b, s2, o2, m2, v2,
                              c3b, s3, o3, m3, v3);
    embed_kernel<<<MTOT, 128>>>(x, embed_w);
    mma_gemm_kernel<<<gconv, 256, SMEM_GEMM>>>(aHi, aLo, wcH + 0 * WC, wcL + 0 * WC,
        3, 0, 0, bHi, bLo, nullptr, nullptr, nullptr);
    wprep_conv_kernel<<<NWC, 256>>>(c2w, 1);
    mma_gemm_kernel<<<gconv, 256, SMEM_GEMM>>>(bHi, bLo, wcH + 1 * WC, wcL + 1 * WC,
        3, 1, 0, aHi, aLo, nullptr, nullptr, nullptr);
    wprep_conv_kernel<<<NWC, 256>>>(c3w, 2);
    mma_gemm_kernel<<<gconv, 256, SMEM_GEMM>>>(aHi, aLo, wcH + 2 * WC, wcL + 2 * WC,
        3, 2, 0, bHi, bLo, nullptr, nullptr, nullptr);
    wprep_gate_kernel<<<gwp, bwp>>>(wf, 0,   wgH + 0 * WG, wgL + 0 * WG);
    wprep_gate_kernel<<<gwp, bwp>>>(wb, 0,   wgH + 1 * WG, wgL + 1 * WG);
    wprep_gate_kernel<<<gwp, bwp>>>(wf, DIM, wrH + 0 * WG, wrL + 0 * WG);
    wprep_gate_kernel<<<gwp, bwp>>>(wb, DIM, wrH + 1 * WG, wrL + 1 * WG);
    mma_gemm_kernel<<<ggate, 256, SMEM_GEMM>>>(bHi, bLo, wgH, wgL,
        1, -1, 1, nullptr, nullptr, bf, bb, gpre);
    lstm_recur_kernel<<<128, 512, R_SMEM>>>(wrH, wrL, lengths, gpre, out);
}

// round 10
// speedup vs baseline: 2.8271x; 1.0868x over previous
#include <cuda_runtime.h>
#include <cuda_bf16.h>
#include <cuda_fp16.h>
#include <stdint.h>
#include <math.h>

#define BSZ   32
#define LSEQ  1024
#define DIM   512
#define MTOT  (BSZ*LSEQ)          // 32768
#define GDIM  2048                // 4*DIM

// =================== scratch (device globals) ================================
__device__ __align__(128) __nv_bfloat16 g_aHi[(size_t)MTOT*DIM];
__device__ __align__(128) __nv_bfloat16 g_aLo[(size_t)MTOT*DIM];
__device__ __align__(128) __nv_bfloat16 g_bHi[(size_t)MTOT*DIM];
__device__ __align__(128) __nv_bfloat16 g_bLo[(size_t)MTOT*DIM];
__device__ __align__(128) __nv_bfloat16 g_wcHi[3][(size_t)3*DIM*DIM];   // [layer][tap*512+n][k]
__device__ __align__(128) __nv_bfloat16 g_wcLo[3][(size_t)3*DIM*DIM];
__device__ __align__(128) __nv_bfloat16 g_wgHi[2][(size_t)GDIM*DIM];    // [dir][n][k]
__device__ __align__(128) __nv_bfloat16 g_wgLo[2][(size_t)GDIM*DIM];
__device__ __align__(128) __half g_wrHi[2][(size_t)GDIM*DIM];           // recurrent W fp16
__device__ __align__(128) __half g_wrLo[2][(size_t)GDIM*DIM];
__device__ float g_gpre[2][(size_t)MTOT*GDIM];   // [dir][ (t*2048 + col)*32 + b ]
__device__ __align__(128) __half g_h16[2][2][BSZ*DIM];  // [parity][dir][b*512+d]
__device__ float g_alpha[3][DIM];
__device__ float g_beta[3][DIM];
__device__ __align__(1024) unsigned g_arr2[2][256];   // padded: dirs 1KB apart
__device__ __align__(1024) unsigned g_gen2[2][256];

// =================== primitives ===============================================
__device__ __forceinline__ uint32_t smem_to_u32(const void* p) {
    uint32_t a;
    asm("{ .reg .u64 t; cvta.to.shared.u64 t, %1; cvt.u32.u64 %0, t; }" : "=r"(a) : "l"(p));
    return a;
}
#define LDSM_X4(r0, r1, r2, r3, addr) \
    asm volatile("ldmatrix.sync.aligned.m8n8.x4.shared.b16 {%0,%1,%2,%3}, [%4];" \
        : "=r"(r0), "=r"(r1), "=r"(r2), "=r"(r3) : "r"(addr))
#define MMA16816(c, a, b) \
    asm volatile("mma.sync.aligned.m16n8k16.row.col.f32.bf16.bf16.f32 " \
        "{%0,%1,%2,%3}, {%4,%5,%6,%7}, {%8,%9}, {%0,%1,%2,%3};" \
        : "+f"((c)[0]), "+f"((c)[1]), "+f"((c)[2]), "+f"((c)[3]) \
        : "r"((a)[0]), "r"((a)[1]), "r"((a)[2]), "r"((a)[3]), \
          "r"((b)[0]), "r"((b)[1]))
#define MMAF16(c, a, b) \
    asm volatile("mma.sync.aligned.m16n8k16.row.col.f32.f16.f16.f32 " \
        "{%0,%1,%2,%3}, {%4,%5,%6,%7}, {%8,%9}, {%0,%1,%2,%3};" \
        : "+f"((c)[0]), "+f"((c)[1]), "+f"((c)[2]), "+f"((c)[3]) \
        : "r"((a)[0]), "r"((a)[1]), "r"((a)[2]), "r"((a)[3]), \
          "r"((b)[0]), "r"((b)[1]))

__device__ __forceinline__ float tanh_fast_(float x) {
    float y;
    asm("tanh.approx.f32 %0, %1;" : "=f"(y) : "f"(x));
    return y;
}
__device__ __forceinline__ float sigmoid_fast_(float x) {
    return fmaf(tanh_fast_(0.5f * x), 0.5f, 0.5f);
}

// full arrive+wait barrier (used once at startup)
__device__ __forceinline__ void dir_sync_(int dir, unsigned nblk) {
    __syncthreads();
    if (threadIdx.x == 0) {
        unsigned* arr = &g_arr2[dir][0];
        unsigned* gen = &g_gen2[dir][0];
        unsigned cur;
        asm volatile("ld.acquire.gpu.global.u32 %0, [%1];" : "=r"(cur) : "l"(gen));
        unsigned prev;
        asm volatile("atom.release.gpu.global.add.u32 %0, [%1], 1;"
                     : "=r"(prev) : "l"(arr) : "memory");
        if (prev == nblk - 1) {
            *arr = 0u;
            unsigned nxt = cur + 1u;
            asm volatile("st.release.gpu.global.u32 [%0], %1;" :: "l"(gen), "r"(nxt) : "memory");
        } else {
            unsigned g;
            do {
                asm volatile("ld.acquire.gpu.global.u32 %0, [%1];" : "=r"(g) : "l"(gen));
            } while (g == cur);
        }
    }
    __syncthreads();
}

// =================== BN fold =================================================
__global__ void bnprep_kernel(
    const float* __restrict__ b1, const float* __restrict__ s1, const float* __restrict__ o1,
    const float* __restrict__ m1, const float* __restrict__ v1,
    const float* __restrict__ b2, const float* __restrict__ s2, const float* __restrict__ o2,
    const float* __restrict__ m2, const float* __restrict__ v2,
    const float* __restrict__ b3, const float* __restrict__ s3, const float* __restrict__ o3,
    const float* __restrict__ m3, const float* __restrict__ v3)
{
    int i = threadIdx.x;
    if (i < DIM) {
        float g;
        g = s1[i] * rsqrtf(v1[i] + 1e-5f); g_alpha[0][i] = g; g_beta[0][i] = (b1[i] - m1[i]) * g + o1[i];
        g = s2[i] * rsqrtf(v2[i] + 1e-5f); g_alpha[1][i] = g; g_beta[1][i] = (b2[i] - m2[i]) * g + o2[i];
        g = s3[i] * rsqrtf(v3[i] + 1e-5f); g_alpha[2][i] = g; g_beta[2][i] = (b3[i] - m3[i]) * g + o3[i];
    }
}

// =================== weight prep ==============================================
__global__ void wprep_conv_kernel(const float* __restrict__ Wc, int layer)
{
    int idx = blockIdx.x * 256 + threadIdx.x;
    if (idx >= 3 * DIM * DIM) return;
    int tap = idx / (DIM * DIM);
    int rem = idx - tap * DIM * DIM;
    int n = rem / DIM, k = rem % DIM;
    float v = Wc[(size_t)(tap * DIM + k) * DIM + n];
    __nv_bfloat16 h = __float2bfloat16(v);
    __nv_bfloat16 l = __float2bfloat16(v - __bfloat162float(h));
    g_wcHi[layer][(size_t)(tap * DIM + n) * DIM + k] = h;
    g_wcLo[layer][(size_t)(tap * DIM + n) * DIM + k] = l;
}
// input-gate W (bf16 pair), coalesced 32x32 transpose
__global__ void wprep_gate_kernel(const float* __restrict__ W,
                                  __nv_bfloat16* __restrict__ dstHi,
                                  __nv_bfloat16* __restrict__ dstLo)
{
    __shared__ float tile[32][33];
    const int tx = threadIdx.x, ty = threadIdx.y;
    const int k0 = blockIdx.x * 32, n0 = blockIdx.y * 32;
    #pragma unroll
    for (int i = 0; i < 4; i++)
        tile[ty + i * 8][tx] = W[(size_t)(k0 + ty + i * 8) * GDIM + n0 + tx];
    __syncthreads();
    #pragma unroll
    for (int i = 0; i < 4; i++) {
        int n = n0 + ty + i * 8;
        float v = tile[tx][ty + i * 8];
        __nv_bfloat16 h = __float2bfloat16(v);
        __nv_bfloat16 l = __float2bfloat16(v - __bfloat162float(h));
        dstHi[(size_t)n * DIM + k0 + tx] = h;
        dstLo[(size_t)n * DIM + k0 + tx] = l;
    }
}
// recurrent W (fp16 pair), rows 512..1023 of the LSTM weight
__global__ void wprep_rec_kernel(const float* __restrict__ W,
                                 __half* __restrict__ dstHi,
                                 __half* __restrict__ dstLo)
{
    __shared__ float tile[32][33];
    const int tx = threadIdx.x, ty = threadIdx.y;
    const int k0 = blockIdx.x * 32, n0 = blockIdx.y * 32;
    #pragma unroll
    for (int i = 0; i < 4; i++)
        tile[ty + i * 8][tx] = W[(size_t)(DIM + k0 + ty + i * 8) * GDIM + n0 + tx];
    __syncthreads();
    #pragma unroll
    for (int i = 0; i < 4; i++) {
        int n = n0 + ty + i * 8;
        float v = tile[tx][ty + i * 8];
        __half h = __float2half_rn(v);
        __half l = __float2half_rn(v - __half2float(h));
        dstHi[(size_t)n * DIM + k0 + tx] = h;
        dstLo[(size_t)n * DIM + k0 + tx] = l;
    }
}

// =================== embedding -> bf16 hi/lo =================================
__global__ void embed_kernel(const int* __restrict__ x, const float* __restrict__ ew)
{
    int m = blockIdx.x;
    int tok = x[m];
    int j = threadIdx.x;
    float4 v = ((const float4*)(ew + (size_t)tok * DIM))[j];
    float f[4] = {v.x, v.y, v.z, v.w};
    __nv_bfloat16 h[4], l[4];
    #pragma unroll
    for (int i = 0; i < 4; i++) {
        h[i] = __float2bfloat16(f[i]);
        l[i] = __float2bfloat16(f[i] - __bfloat162float(h[i]));
    }
    *(uint2*)(g_aHi + (size_t)m * DIM + j * 4) = *(uint2*)h;
    *(uint2*)(g_aLo + (size_t)m * DIM + j * 4) = *(uint2*)l;
}

// =================== bf16 mma.sync GEMM (unchanged engine) ====================
__global__ void __launch_bounds__(256, 2) mma_gemm_kernel(
    const __nv_bfloat16* __restrict__ Ahi, const __nv_bfloat16* __restrict__ Alo,
    const __nv_bfloat16* __restrict__ BwHi, const __nv_bfloat16* __restrict__ BwLo,
    int taps, int layer, int bperm,
    __nv_bfloat16* __restrict__ outHi, __nv_bfloat16* __restrict__ outLo,
    const float* __restrict__ biasA, const float* __restrict__ biasB,
    float* __restrict__ gout)
{
    extern __shared__ char smem[];
    const int tid = threadIdx.x;
    const int lane = tid & 31, wid = tid >> 5;
    const int wm = wid & 3, wn = wid >> 2;
    const int m0 = blockIdx.x * 128, n0 = blockIdx.y * 128;
    const int t0 = m0 & (LSEQ - 1);
    const int tb4 = blockIdx.x * 4;
    const int dz = blockIdx.z;
    const uint32_t sb = smem_to_u32(smem);

    if (bperm) {
        BwHi += (size_t)dz * GDIM * DIM;
        BwLo += (size_t)dz * GDIM * DIM;
        gout += (size_t)dz * MTOT * GDIM;
    }
    const float* bias = dz ? biasB : biasA;

    const int off0  = taps >> 1;
    const int arows = 128 + (taps - 1);

    float acc[2][8][4];
    #pragma unroll
    for (int a = 0; a < 2; a++)
        #pragma unroll
        for (int b = 0; b < 8; b++)
            #pragma unroll
            for (int c = 0; c < 4; c++) acc[a][b][c] = 0.f;

    #define DO_COPY_A(SLICE) do { \
        const int _kb = (SLICE) << 6; \
        const int _tot = arows * 8; \
        for (int _i = tid; _i < _tot; _i += 256) { \
            int _r = _i >> 3, _c8 = (_i & 7) << 3; \
            uint32_t _off = (uint32_t)(_r * 128) + (((uint32_t)_c8 * 2) ^ (((uint32_t)_r & 7) << 4)); \
            uint4 _vh = make_uint4(0u,0u,0u,0u), _vl = _vh; \
            if (bperm) { \
                size_t _ga = (size_t)(((_r & 31) << 10) + tb4 + (_r >> 5)) * DIM + _kb + _c8; \
                _vh = *(const uint4*)(Ahi + _ga); \
                _vl = *(const uint4*)(Alo + _ga); \
            } else { \
                int _tl = t0 + _r - off0; \
                if (_tl >= 0 && _tl < LSEQ) { \
                    size_t _ga = (size_t)(m0 + _r - off0) * DIM + _kb + _c8; \
                    _vh = *(const uint4*)(Ahi + _ga); \
                    _vl = *(const uint4*)(Alo + _ga); \
                } \
            } \
            *(uint4*)(smem + _off) = _vh; \
            *(uint4*)(smem + 16640 + _off) = _vl; \
        } \
    } while (0)

    #define DO_COPY_B(IDX, ST) do { \
        const int _sl = (IDX) / taps, _tp = (IDX) % taps; \
        const int _kb = _sl << 6; \
        const int _rbase = (taps == 3 ? _tp * DIM : 0) + n0; \
        char* _bp = smem + 33280 + (ST) * 32768; \
        for (int _i = tid; _i < 1024; _i += 256) { \
            int _r = _i >> 3, _c8 = (_i & 7) << 3; \
            uint32_t _off = (uint32_t)(_r * 128) + (((uint32_t)_c8 * 2) ^ (((uint32_t)_r & 7) << 4)); \
            size_t _ga = (size_t)(_rbase + _r) * DIM + _kb + _c8; \
            *(uint4*)(_bp + _off) = *(const uint4*)(BwHi + _ga); \
            *(uint4*)(_bp + 16384 + _off) = *(const uint4*)(BwLo + _ga); \
        } \
    } while (0)

    const int NB = 8 * taps;
    DO_COPY_A(0);
    DO_COPY_B(0, 0);
    __syncthreads();

    for (int idx = 0; idx < NB; idx++) {
        const int tap = idx % taps;
        const int bsel = idx & 1;
        const bool lastTap = (tap == taps - 1);

        if (idx + 1 < NB) DO_COPY_B(idx + 1, bsel ^ 1);

        const uint32_t aHiB = sb;
        const uint32_t aLoB = sb + 16640;
        const uint32_t bHiB = sb + 33280 + (uint32_t)bsel * 32768;
        const uint32_t bLoB = bHiB + 16384;
        #pragma unroll
        for (int k16 = 0; k16 < 4; k16++) {
            const uint32_t colA = (uint32_t)(k16 * 32) + (((uint32_t)lane >> 4) << 4);
            const uint32_t colB = (uint32_t)(k16 * 32) + ((((uint32_t)lane >> 3) & 1) << 4);
            uint32_t afh[2][4], afl[2][4];
            #pragma unroll
            for (int mt = 0; mt < 2; mt++) {
                uint32_t row = (uint32_t)(wm * 32 + mt * 16 + (lane & 15) + tap);
                uint32_t ad = row * 128 + (colA ^ ((row & 7) << 4));
                LDSM_X4(afh[mt][0], afh[mt][1], afh[mt][2], afh[mt][3], aHiB + ad);
                LDSM_X4(afl[mt][0], afl[mt][1], afl[mt][2], afl[mt][3], aLoB + ad);
            }
            #pragma unroll
            for (int half = 0; half < 2; half++) {
                uint32_t bfh[4][2], bfl[4][2];
                #pragma unroll
                for (int np = 0; np < 2; np++) {
                    uint32_t row = (uint32_t)(wn * 64 + (half * 2 + np) * 16 +
                                              (((lane >> 4) << 3) | (lane & 7)));
                    uint32_t bd = row * 128 + (colB ^ ((row & 7) << 4));
                    LDSM_X4(bfh[2*np][0], bfh[2*np][1], bfh[2*np+1][0], bfh[2*np+1][1], bHiB + bd);
                    LDSM_X4(bfl[2*np][0], bfl[2*np][1], bfl[2*np+1][0], bfl[2*np+1][1], bLoB + bd);
                }
                #pragma unroll
                for (int mt = 0; mt < 2; mt++)
                    #pragma unroll
                    for (int nt = 0; nt < 4; nt++) {
                        float* ac = acc[mt][half * 4 + nt];
                        MMA16816(ac, afh[mt], bfh[nt]);
                        MMA16816(ac, afl[mt], bfh[nt]);
                        MMA16816(ac, afh[mt], bfl[nt]);
                    }
            }
        }
        __syncthreads();
        if (lastTap && idx + 1 < NB) {
            DO_COPY_A((idx + 1) / taps);
            __syncthreads();
        }
    }
    #undef DO_COPY_A
    #undef DO_COPY_B

    const int g  = lane >> 2;
    const int tg = lane & 3;
    if (gout == nullptr) {            // conv epilogue
        #pragma unroll
        for (int mt = 0; mt < 2; mt++) {
            const int mlo = m0 + wm * 32 + mt * 16 + g;
            const int mhi = mlo + 8;
            #pragma unroll
            for (int nt = 0; nt < 8; nt++) {
                const int n = n0 + wn * 64 + nt * 8 + tg * 2;
                const float al0 = g_alpha[layer][n],     be0 = g_beta[layer][n];
                const float al1 = g_alpha[layer][n + 1], be1 = g_beta[layer][n + 1];
                float v00 = fmaxf(fmaf(acc[mt][nt][0], al0, be0), 0.f);
                float v01 = fmaxf(fmaf(acc[mt][nt][1], al1, be1), 0.f);
                float v10 = fmaxf(fmaf(acc[mt][nt][2], al0, be0), 0.f);
                float v11 = fmaxf(fmaf(acc[mt][nt][3], al1, be1), 0.f);
                __nv_bfloat16 h00 = __float2bfloat16(v00), h01 = __float2bfloat16(v01);
                __nv_bfloat16 h10 = __float2bfloat16(v10), h11 = __float2bfloat16(v11);
                __nv_bfloat16 l00 = __float2bfloat16(v00 - __bfloat162float(h00));
                __nv_bfloat16 l01 = __float2bfloat16(v01 - __bfloat162float(h01));
                __nv_bfloat16 l10 = __float2bfloat16(v10 - __bfloat162float(h10));
                __nv_bfloat16 l11 = __float2bfloat16(v11 - __bfloat162float(h11));
                __nv_bfloat162 ph0; ph0.x = h00; ph0.y = h01;
                __nv_bfloat162 ph1; ph1.x = h10; ph1.y = h11;
                __nv_bfloat162 pl0; pl0.x = l00; pl0.y = l01;
                __nv_bfloat162 pl1; pl1.x = l10; pl1.y = l11;
                *(__nv_bfloat162*)(outHi + (size_t)mlo * DIM + n) = ph0;
                *(__nv_bfloat162*)(outHi + (size_t)mhi * DIM + n) = ph1;
                *(__nv_bfloat162*)(outLo + (size_t)mlo * DIM + n) = pl0;
                *(__nv_bfloat162*)(outLo + (size_t)mhi * DIM + n) = pl1;
            }
        }
    } else {                          // gates (bperm): smem transpose -> coalesced
        float* tile = (float*)smem;
        #pragma unroll
        for (int mt = 0; mt < 2; mt++) {
            const int rlo = wm * 32 + mt * 16 + g;
            const int rhi = rlo + 8;
            #pragma unroll
            for (int nt = 0; nt < 8; nt++) {
                const int nl = wn * 64 + nt * 8 + tg * 2;
                const float b0 = bias[n0 + nl], b1 = bias[n0 + nl + 1];
                tile[rlo * 129 + nl    ] = acc[mt][nt][0] + b0;
                tile[rlo * 129 + nl + 1] = acc[mt][nt][1] + b1;
                tile[rhi * 129 + nl    ] = acc[mt][nt][2] + b0;
                tile[rhi * 129 + nl + 1] = acc[mt][nt][3] + b1;
            }
        }
        __syncthreads();
        for (int i = tid; i < 16384; i += 256) {
            int b_  = i & 31;
            int nl  = (i >> 5) & 127;
            int tt  = i >> 12;
            gout[((size_t)(tb4 + tt) * GDIM + n0 + nl) * 32 + b_] =
                tile[(tt * 32 + b_) * 129 + nl];
        }
    }
}

// =================== persistent LSTM recurrence — fp16 h, K_eff=1024 ==========
#define R_WHI 0
#define R_WLO 33280
#define R_A   66560
#define R_PART 99840                        // 16*32*33*4 = 67584
#define R_OBH  167424                       // float[288] = 1152
#define R_OBP  168576                       // ushort[288] = 576
#define R_SMEM 169728

__global__ void __launch_bounds__(512, 1) lstm_recur_kernel(
    const __half* __restrict__ wrHi, const __half* __restrict__ wrLo,
    const int* __restrict__ lengths, const float* __restrict__ gpreAll,
    float* __restrict__ out)
{
    extern __shared__ char sm[];
    float* part = (float*)(sm + R_PART);
    float* obh  = (float*)(sm + R_OBH);
    unsigned short* obp16 = (unsigned short*)(sm + R_OBP);
    __shared__ int len_s[32];

    const int tid = threadIdx.x;
    const int lane = tid & 31, u = tid >> 5;        // u in [0,16)
    const int dir = blockIdx.x >> 6;
    const int dc  = (blockIdx.x & 63) << 3;
    const uint32_t sb = smem_to_u32(sm);
    const float* gpre = gpreAll + (size_t)dir * MTOT * GDIM;
    const __half* wHi = wrHi + (size_t)dir * GDIM * DIM;
    const __half* wLo = wrLo + (size_t)dir * GDIM * DIM;

    // stage W (permuted rows, 1040B padded stride): 32 rows x 1024B each
    for (int i = tid; i < 2048; i += 512) {
        int r = i >> 6, c16 = i & 63;
        int n = ((r >> 3) << 9) + dc + (r & 7);
        uint4 vh = *(const uint4*)(wHi + (size_t)n * DIM + c16 * 8);
        uint4 vl = *(const uint4*)(wLo + (size_t)n * DIM + c16 * 8);
        *(uint4*)(sm + R_WHI + r * 1040 + c16 * 16) = vh;
        *(uint4*)(sm + R_WLO + r * 1040 + c16 * 16) = vl;
    }
    if (tid < 32) len_s[tid] = lengths[tid];
    if (tid < 32)   // zero parity-0 h slice (8 halves = uint4 per batch row)
        ((uint4*)g_h16[0][dir])[tid * 64 + (dc >> 3)] = make_uint4(0u, 0u, 0u, 0u);
    __syncthreads();

    // preload W fragments: 4 tiles/warp (tt = u*4+i; sec 0=hi,1=lo; kk = tt&31)
    uint32_t wf[4][8];
    {
        const uint32_t rB = (uint32_t)(((lane >> 4) << 3) | (lane & 7));
        const uint32_t hB = (uint32_t)(((lane >> 3) & 1) << 4);
        #pragma unroll
        for (int i = 0; i < 4; i++) {
            int tt = u * 4 + i;
            int sec = tt >> 5, kk = tt & 31;
            uint32_t base = sb + (sec ? R_WLO : R_WHI);
            uint32_t col = (uint32_t)(kk * 32) + hB;
            LDSM_X4(wf[i][0], wf[i][1], wf[i][2], wf[i][3], base + rB * 1040 + col);
            LDSM_X4(wf[i][4], wf[i][5], wf[i][6], wf[i][7], base + (rB + 16) * 1040 + col);
        }
    }
    const int lenb = len_s[lane];
    dir_sync_(dir, 64);

    const uint32_t rA = (uint32_t)(lane & 15);
    const uint32_t hA = (uint32_t)((lane >> 4) << 4);
    float cst = 0.f;

    unsigned* arrP = &g_arr2[dir][0];
    unsigned* genP = &g_gen2[dir][0];

    // gpre double-buffer: preload step 0
    float gp0 = 0.f, gp1 = 0.f, gp2 = 0.f, gp3 = 0.f;
    if (u < 8) {
        const int t0_ = dir ? (LSEQ - 1) : 0;
        const float* gq = gpre + ((size_t)t0_ * GDIM + dc + u) * 32 + lane;
        gp0 = __ldg(gq);
        gp1 = __ldg(gq + (size_t)512 * 32);
        gp2 = __ldg(gq + (size_t)1024 * 32);
        gp3 = __ldg(gq + (size_t)1536 * 32);
    }

    for (int s = 0; s < LSEQ; s++) {
        const int t = dir ? (LSEQ - 1 - s) : s;
        const int p = s & 1;

        // next-step gpre loads (hidden behind this step)
        float gn0 = 0.f, gn1 = 0.f, gn2 = 0.f, gn3 = 0.f;
        if (u < 8 && s + 1 < LSEQ) {
            const int tn = dir ? (LSEQ - 2 - s) : (s + 1);
            const float* gq = gpre + ((size_t)tn * GDIM + dc + u) * 32 + lane;
            gn0 = __ldg(gq);
            gn1 = __ldg(gq + (size_t)512 * 32);
            gn2 = __ldg(gq + (size_t)1024 * 32);
            gn3 = __ldg(gq + (size_t)1536 * 32);
        }

        {   // stage h_prev fp16: 32KB, 4 uint4 per thread
            const uint4* hp = (const uint4*)g_h16[p][dir];
            #pragma unroll
            for (int i = 0; i < 4; i++) {
                int idx = i * 512 + tid;            // 0..2047
                int b_ = idx >> 6, c = idx & 63;
                uint4 v = __ldcg(hp + idx);
                if (dir && t >= len_s[b_] - 1) v = make_uint4(0u, 0u, 0u, 0u);
                *(uint4*)(sm + R_A + b_ * 1040 + c * 16) = v;
            }
        }
        __syncthreads();

        float acc[2][4][4];
        #pragma unroll
        for (int a = 0; a < 2; a++)
            #pragma unroll
            for (int b = 0; b < 4; b++)
                #pragma unroll
                for (int c = 0; c < 4; c++) acc[a][b][c] = 0.f;

        #pragma unroll
        for (int i = 0; i < 4; i++) {
            int tt = u * 4 + i;
            int kk = tt & 31;
            uint32_t col = (uint32_t)(kk * 32) + hA;
            uint32_t af0[4], af1[4];
            LDSM_X4(af0[0], af0[1], af0[2], af0[3], sb + R_A + rA * 1040 + col);
            LDSM_X4(af1[0], af1[1], af1[2], af1[3], sb + R_A + (rA + 16) * 1040 + col);
            #pragma unroll
            for (int nt = 0; nt < 4; nt++) {
                MMAF16(acc[0][nt], af0, &wf[i][nt * 2]);
                MMAF16(acc[1][nt], af1, &wf[i][nt * 2]);
            }
        }

        {
            int row = lane >> 2, colp = (lane & 3) * 2;
            #pragma unroll
            for (int mt = 0; mt < 2; mt++)
                #pragma unroll
                for (int nt = 0; nt < 4; nt++) {
                    float* p0 = part + (u * 32 + mt * 16 + row) * 33 + nt * 8 + colp;
                    p0[0] = acc[mt][nt][0]; p0[1] = acc[mt][nt][1];
                    float* p1 = part + (u * 32 + mt * 16 + row + 8) * 33 + nt * 8 + colp;
                    p1[0] = acc[mt][nt][2]; p1[1] = acc[mt][nt][3];
                }
        }
        __syncthreads();

        if (u < 8) {   // thread (b=lane, dim=dc+u): reduce + cell update
            float s0 = 0.f, s1 = 0.f, s2 = 0.f, s3 = 0.f;
            #pragma unroll
            for (int w = 0; w < 16; w++) {
                const float* pr = part + (w * 32 + lane) * 33;
                s0 += pr[u]; s1 += pr[8 + u]; s2 += pr[16 + u]; s3 += pr[24 + u];
            }
            float iv = sigmoid_fast_(gp0 + s0);
            float gv = tanh_fast_(gp1 + s1);
            float fv = sigmoid_fast_(gp2 + s2 + 1.f);
            float ov = sigmoid_fast_(gp3 + s3);
            if (dir && t >= lenb - 1) cst = 0.f;
            cst = fv * cst + iv * gv;
            float hh = ov * tanh_fast_(cst);
            obh[lane * 9 + u] = hh;
            obp16[lane * 9 + u] = __half_as_ushort(__float2half_rn(hh));
        }
        gp0 = gn0; gp1 = gn1; gp2 = gn2; gp3 = gn3;
        __syncthreads();

        // publish h FIRST (critical path), one STG.128 per batch row
        if (tid < 32) {
            const unsigned short* sp = obp16 + tid * 9;
            uint4 o;
            o.x = (unsigned)sp[0] | ((unsigned)sp[1] << 16);
            o.y = (unsigned)sp[2] | ((unsigned)sp[3] << 16);
            o.z = (unsigned)sp[4] | ((unsigned)sp[5] << 16);
            o.w = (unsigned)sp[6] | ((unsigned)sp[7] << 16);
            ((uint4*)g_h16[p ^ 1][dir])[tid * 64 + (dc >> 3)] = o;
        }
        __syncthreads();   // order h STG before the release-arrive

        unsigned curGen = 0u;
        if (tid == 0) {    // arrive (release publishes h writes)
            asm volatile("ld.acquire.gpu.global.u32 %0, [%1];" : "=r"(curGen) : "l"(genP));
            unsigned prev;
            asm volatile("atom.release.gpu.global.add.u32 %0, [%1], 1;"
                         : "=r"(prev) : "l"(arrP) : "memory");
            if (prev == 63u) {
                *arrP = 0u;
                unsigned nxt = curGen + 1u;
                asm volatile("st.release.gpu.global.u32 [%0], %1;" :: "l"(genP), "r"(nxt) : "memory");
            }
        }

        // out store OFF the critical path (nobody consumes it)
        if (tid < 256) {
            int b2 = tid >> 3, d2 = tid & 7;
            out[(((size_t)b2 << 10) + t) * 1024 + (dir << 9) + dc + d2] = obh[b2 * 9 + d2];
        }

        if (tid == 0) {    // wait
            unsigned g;
            do {
                asm volatile("ld.acquire.gpu.global.u32 %0, [%1];" : "=r"(g) : "l"(genP));
            } while (g == curGen);
        }
        __syncthreads();
    }
}

// =================== launch ===================================================
extern "C" void kernel_launch(void* const* d_in, const int* in_sizes, int n_in,
                              void* d_out, int out_size)
{
    (void)in_sizes; (void)n_in; (void)out_size;
    const int*   x        = (const int*)  d_in[0];
    const int*   lengths  = (const int*)  d_in[1];
    const float* embed_w  = (const float*)d_in[2];
    const float* c1w = (const float*)d_in[3];
    const float* c1b = (const float*)d_in[4];
    const float* c2w = (const float*)d_in[5];
    const float* c2b = (const float*)d_in[6];
    const float* c3w = (const float*)d_in[7];
    const float* c3b = (const float*)d_in[8];
    const float* wf  = (const float*)d_in[9];
    const float* bf  = (const float*)d_in[10];
    const float* wb  = (const float*)d_in[11];
    const float* bb  = (const float*)d_in[12];
    const float* s1 = (const float*)d_in[13]; const float* o1 = (const float*)d_in[14];
    const float* m1 = (const float*)d_in[15]; const float* v1 = (const float*)d_in[16];
    const float* s2 = (const float*)d_in[17]; const float* o2 = (const float*)d_in[18];
    const float* m2 = (const float*)d_in[19]; const float* v2 = (const float*)d_in[20];
    const float* s3 = (const float*)d_in[21]; const float* o3 = (const float*)d_in[22];
    const float* m3 = (const float*)d_in[23]; const float* v3 = (const float*)d_in[24];
    float* out = (float*)d_out;

    __nv_bfloat16 *aHi, *aLo, *bHi, *bLo, *wcH, *wcL, *wgH, *wgL;
    __half *wrH, *wrL;
    cudaGetSymbolAddress((void**)&aHi, g_aHi);
    cudaGetSymbolAddress((void**)&aLo, g_aLo);
    cudaGetSymbolAddress((void**)&bHi, g_bHi);
    cudaGetSymbolAddress((void**)&bLo, g_bLo);
    cudaGetSymbolAddress((void**)&wcH, g_wcHi);
    cudaGetSymbolAddress((void**)&wcL, g_wcLo);
    cudaGetSymbolAddress((void**)&wgH, g_wgHi);
    cudaGetSymbolAddress((void**)&wgL, g_wgLo);
    cudaGetSymbolAddress((void**)&wrH, g_wrHi);
    cudaGetSymbolAddress((void**)&wrL, g_wrLo);
    float* gpre;
    cudaGetSymbolAddress((void**)&gpre, g_gpre);

    const size_t WC = (size_t)3 * DIM * DIM;
    const size_t WG = (size_t)GDIM * DIM;

    const int SMEM_GEMM  = 33280 + 2 * 32768;     // 98816
    cudaFuncSetAttribute(mma_gemm_kernel,
                         cudaFuncAttributeMaxDynamicSharedMemorySize, SMEM_GEMM);
    cudaFuncSetAttribute(lstm_recur_kernel,
                         cudaFuncAttributeMaxDynamicSharedMemorySize, R_SMEM);

    dim3 gconv(MTOT / 128, DIM / 128, 1);
    dim3 ggate(MTOT / 128, GDIM / 128, 2);
    const int NWC = (3 * DIM * DIM + 255) / 256;
    dim3 gwp(DIM / 32, GDIM / 32);
    dim3 bwp(32, 8);

    wprep_conv_kernel<<<NWC, 256>>>(c1w, 0);
    bnprep_kernel<<<1, 512>>>(c1b, s1, o1, m1, v1,
                              c2b, s2, o2, m2, v2,
                              c3b, s3, o3, m3, v3);
    embed_kernel<<<MTOT, 128>>>(x, embed_w);
    mma_gemm_kernel<<<gconv, 256, SMEM_GEMM>>>(aHi, aLo, wcH + 0 * WC, wcL + 0 * WC,
        3, 0, 0, bHi, bLo, nullptr, nullptr, nullptr);
    wprep_conv_kernel<<<NWC, 256>>>(c2w, 1);
    mma_gemm_kernel<<<gconv, 256, SMEM_GEMM>>>(bHi, bLo, wcH + 1 * WC, wcL + 1 * WC,
        3, 1, 0, aHi, aLo, nullptr, nullptr, nullptr);
    wprep_conv_kernel<<<NWC, 256>>>(c3w, 2);
    mma_gemm_kernel<<<gconv, 256, SMEM_GEMM>>>(aHi, aLo, wcH + 2 * WC, wcL + 2 * WC,
        3, 2, 0, bHi, bLo, nullptr, nullptr, nullptr);
    wprep_gate_kernel<<<gwp, bwp>>>(wf, wgH + 0 * WG, wgL + 0 * WG);
    wprep_gate_kernel<<<gwp, bwp>>>(wb, wgH + 1 * WG, wgL + 1 * WG);
    wprep_rec_kernel<<<gwp, bwp>>>(wf, wrH + 0 * WG, wrL + 0 * WG);
    wprep_rec_kernel<<<gwp, bwp>>>(wb, wrH + 1 * WG, wrL + 1 * WG);
    mma_gemm_kernel<<<ggate, 256, SMEM_GEMM>>>(bHi, bLo, wgH, wgL,
        1, -1, 1, nullptr, nullptr, bf, bb, gpre);
    lstm_recur_kernel<<<128, 512, R_SMEM>>>(wrH, wrL, lengths, gpre, out);
}

// round 11
// speedup vs baseline: 3.0859x; 1.0915x over previous
#include <cuda_runtime.h>
#include <cuda_bf16.h>
#include <cuda_fp16.h>
#include <stdint.h>
#include <math.h>

#define BSZ   32
#define LSEQ  1024
#define DIM   512
#define MTOT  (BSZ*LSEQ)          // 32768
#define GDIM  2048                // 4*DIM

// =================== scratch (device globals) ================================
__device__ __align__(128) __nv_bfloat16 g_aHi[(size_t)MTOT*DIM];
__device__ __align__(128) __nv_bfloat16 g_aLo[(size_t)MTOT*DIM];
__device__ __align__(128) __nv_bfloat16 g_bHi[(size_t)MTOT*DIM];
__device__ __align__(128) __nv_bfloat16 g_bLo[(size_t)MTOT*DIM];
__device__ __align__(128) __nv_bfloat16 g_wcHi[3][(size_t)3*DIM*DIM];   // [layer][tap*512+n][k]
__device__ __align__(128) __nv_bfloat16 g_wcLo[3][(size_t)3*DIM*DIM];
__device__ __align__(128) __nv_bfloat16 g_wgHi[2][(size_t)GDIM*DIM];    // [dir][n][k]
__device__ __align__(128) __nv_bfloat16 g_wgLo[2][(size_t)GDIM*DIM];
__device__ __align__(128) __half g_wrHi[2][(size_t)GDIM*DIM];           // recurrent W fp16
__device__ __align__(128) __half g_wrLo[2][(size_t)GDIM*DIM];
__device__ float g_gpre[2][(size_t)MTOT*GDIM];   // [dir][ (t*2048 + col)*32 + b ]
__device__ __align__(128) __half g_h16[2][2][BSZ*DIM];  // [parity][dir][b*512+d]
__device__ float g_alpha[3][DIM];
__device__ float g_beta[3][DIM];
__device__ __align__(1024) unsigned g_bar[2][256];    // monotonic, dirs 1KB apart

// =================== primitives ===============================================
__device__ __forceinline__ uint32_t smem_to_u32(const void* p) {
    uint32_t a;
    asm("{ .reg .u64 t; cvta.to.shared.u64 t, %1; cvt.u32.u64 %0, t; }" : "=r"(a) : "l"(p));
    return a;
}
#define LDSM_X4(r0, r1, r2, r3, addr) \
    asm volatile("ldmatrix.sync.aligned.m8n8.x4.shared.b16 {%0,%1,%2,%3}, [%4];" \
        : "=r"(r0), "=r"(r1), "=r"(r2), "=r"(r3) : "r"(addr))
#define MMA16816(c, a, b) \
    asm volatile("mma.sync.aligned.m16n8k16.row.col.f32.bf16.bf16.f32 " \
        "{%0,%1,%2,%3}, {%4,%5,%6,%7}, {%8,%9}, {%0,%1,%2,%3};" \
        : "+f"((c)[0]), "+f"((c)[1]), "+f"((c)[2]), "+f"((c)[3]) \
        : "r"((a)[0]), "r"((a)[1]), "r"((a)[2]), "r"((a)[3]), \
          "r"((b)[0]), "r"((b)[1]))
#define MMAF16(c, a, b) \
    asm volatile("mma.sync.aligned.m16n8k16.row.col.f32.f16.f16.f32 " \
        "{%0,%1,%2,%3}, {%4,%5,%6,%7}, {%8,%9}, {%0,%1,%2,%3};" \
        : "+f"((c)[0]), "+f"((c)[1]), "+f"((c)[2]), "+f"((c)[3]) \
        : "r"((a)[0]), "r"((a)[1]), "r"((a)[2]), "r"((a)[3]), \
          "r"((b)[0]), "r"((b)[1]))

__device__ __forceinline__ float tanh_fast_(float x) {
    float y;
    asm("tanh.approx.f32 %0, %1;" : "=f"(y) : "f"(x));
    return y;
}
__device__ __forceinline__ float sigmoid_fast_(float x) {
    return fmaf(tanh_fast_(0.5f * x), 0.5f, 0.5f);
}
__device__ __forceinline__ unsigned bar_arrive_(unsigned* arr) {
    unsigned prev;
    asm volatile("atom.release.gpu.global.add.u32 %0, [%1], 1;"
                 : "=r"(prev) : "l"(arr) : "memory");
    return prev;
}
__device__ __forceinline__ void bar_wait_(unsigned* arr, unsigned tgt) {
    unsigned v;
    do {
        asm volatile("ld.acquire.gpu.global.u32 %0, [%1];" : "=r"(v) : "l"(arr));
    } while (v < tgt);
}

// =================== BN fold =================================================
__global__ void bnprep_kernel(
    const float* __restrict__ b1, const float* __restrict__ s1, const float* __restrict__ o1,
    const float* __restrict__ m1, const float* __restrict__ v1,
    const float* __restrict__ b2, const float* __restrict__ s2, const float* __restrict__ o2,
    const float* __restrict__ m2, const float* __restrict__ v2,
    const float* __restrict__ b3, const float* __restrict__ s3, const float* __restrict__ o3,
    const float* __restrict__ m3, const float* __restrict__ v3)
{
    int i = threadIdx.x;
    if (i < DIM) {
        float g;
        g = s1[i] * rsqrtf(v1[i] + 1e-5f); g_alpha[0][i] = g; g_beta[0][i] = (b1[i] - m1[i]) * g + o1[i];
        g = s2[i] * rsqrtf(v2[i] + 1e-5f); g_alpha[1][i] = g; g_beta[1][i] = (b2[i] - m2[i]) * g + o2[i];
        g = s3[i] * rsqrtf(v3[i] + 1e-5f); g_alpha[2][i] = g; g_beta[2][i] = (b3[i] - m3[i]) * g + o3[i];
    }
}

// =================== weight prep (coalesced 32x32 transposes) =================
// conv: src [tap*512 + k][n] -> dst [layer][tap*512 + n][k]; grid z = layer*3+tap
__global__ void wprep_conv_kernel(const float* __restrict__ c1,
                                  const float* __restrict__ c2,
                                  const float* __restrict__ c3)
{
    __shared__ float tile[32][33];
    const int tx = threadIdx.x, ty = threadIdx.y;
    const int k0 = blockIdx.x * 32, n0 = blockIdx.y * 32;
    const int layer = blockIdx.z / 3, tap = blockIdx.z % 3;
    const float* W = (layer == 0) ? c1 : ((layer == 1) ? c2 : c3);
    #pragma unroll
    for (int i = 0; i < 4; i++)
        tile[ty + i * 8][tx] = W[(size_t)(tap * DIM + k0 + ty + i * 8) * DIM + n0 + tx];
    __syncthreads();
    #pragma unroll
    for (int i = 0; i < 4; i++) {
        int n = n0 + ty + i * 8;
        float v = tile[tx][ty + i * 8];
        __nv_bfloat16 h = __float2bfloat16(v);
        __nv_bfloat16 l = __float2bfloat16(v - __bfloat162float(h));
        g_wcHi[layer][(size_t)(tap * DIM + n) * DIM + k0 + tx] = h;
        g_wcLo[layer][(size_t)(tap * DIM + n) * DIM + k0 + tx] = l;
    }
}
// input-gate W (bf16 pair); grid z = dir
__global__ void wprep_gate_kernel(const float* __restrict__ Wf,
                                  const float* __restrict__ Wb)
{
    __shared__ float tile[32][33];
    const int tx = threadIdx.x, ty = threadIdx.y;
    const int k0 = blockIdx.x * 32, n0 = blockIdx.y * 32;
    const int dir = blockIdx.z;
    const float* W = dir ? Wb : Wf;
    #pragma unroll
    for (int i = 0; i < 4; i++)
        tile[ty + i * 8][tx] = W[(size_t)(k0 + ty + i * 8) * GDIM + n0 + tx];
    __syncthreads();
    #pragma unroll
    for (int i = 0; i < 4; i++) {
        int n = n0 + ty + i * 8;
        float v = tile[tx][ty + i * 8];
        __nv_bfloat16 h = __float2bfloat16(v);
        __nv_bfloat16 l = __float2bfloat16(v - __bfloat162float(h));
        g_wgHi[dir][(size_t)n * DIM + k0 + tx] = h;
        g_wgLo[dir][(size_t)n * DIM + k0 + tx] = l;
    }
}
// recurrent W (fp16 pair), rows 512..1023; grid z = dir
__global__ void wprep_rec_kernel(const float* __restrict__ Wf,
                                 const float* __restrict__ Wb)
{
    __shared__ float tile[32][33];
    const int tx = threadIdx.x, ty = threadIdx.y;
    const int k0 = blockIdx.x * 32, n0 = blockIdx.y * 32;
    const int dir = blockIdx.z;
    const float* W = dir ? Wb : Wf;
    #pragma unroll
    for (int i = 0; i < 4; i++)
        tile[ty + i * 8][tx] = W[(size_t)(DIM + k0 + ty + i * 8) * GDIM + n0 + tx];
    __syncthreads();
    #pragma unroll
    for (int i = 0; i < 4; i++) {
        int n = n0 + ty + i * 8;
        float v = tile[tx][ty + i * 8];
        __half h = __float2half_rn(v);
        __half l = __float2half_rn(v - __half2float(h));
        g_wrHi[dir][(size_t)n * DIM + k0 + tx] = h;
        g_wrLo[dir][(size_t)n * DIM + k0 + tx] = l;
    }
}

// =================== embedding -> bf16 hi/lo =================================
__global__ void embed_kernel(const int* __restrict__ x, const float* __restrict__ ew)
{
    int m = blockIdx.x;
    int tok = x[m];
    int j = threadIdx.x;
    float4 v = ((const float4*)(ew + (size_t)tok * DIM))[j];
    float f[4] = {v.x, v.y, v.z, v.w};
    __nv_bfloat16 h[4], l[4];
    #pragma unroll
    for (int i = 0; i < 4; i++) {
        h[i] = __float2bfloat16(f[i]);
        l[i] = __float2bfloat16(f[i] - __bfloat162float(h[i]));
    }
    *(uint2*)(g_aHi + (size_t)m * DIM + j * 4) = *(uint2*)h;
    *(uint2*)(g_aLo + (size_t)m * DIM + j * 4) = *(uint2*)l;
}

// =================== bf16 mma.sync GEMM (unchanged engine) ====================
__global__ void __launch_bounds__(256, 2) mma_gemm_kernel(
    const __nv_bfloat16* __restrict__ Ahi, const __nv_bfloat16* __restrict__ Alo,
    const __nv_bfloat16* __restrict__ BwHi, const __nv_bfloat16* __restrict__ BwLo,
    int taps, int layer, int bperm,
    __nv_bfloat16* __restrict__ outHi, __nv_bfloat16* __restrict__ outLo,
    const float* __restrict__ biasA, const float* __restrict__ biasB,
    float* __restrict__ gout)
{
    extern __shared__ char smem[];
    const int tid = threadIdx.x;
    const int lane = tid & 31, wid = tid >> 5;
    const int wm = wid & 3, wn = wid >> 2;
    const int m0 = blockIdx.x * 128, n0 = blockIdx.y * 128;
    const int t0 = m0 & (LSEQ - 1);
    const int tb4 = blockIdx.x * 4;
    const int dz = blockIdx.z;
    const uint32_t sb = smem_to_u32(smem);

    if (bperm) {
        BwHi += (size_t)dz * GDIM * DIM;
        BwLo += (size_t)dz * GDIM * DIM;
        gout += (size_t)dz * MTOT * GDIM;
    }
    const float* bias = dz ? biasB : biasA;

    const int off0  = taps >> 1;
    const int arows = 128 + (taps - 1);

    float acc[2][8][4];
    #pragma unroll
    for (int a = 0; a < 2; a++)
        #pragma unroll
        for (int b = 0; b < 8; b++)
            #pragma unroll
            for (int c = 0; c < 4; c++) acc[a][b][c] = 0.f;

    #define DO_COPY_A(SLICE) do { \
        const int _kb = (SLICE) << 6; \
        const int _tot = arows * 8; \
        for (int _i = tid; _i < _tot; _i += 256) { \
            int _r = _i >> 3, _c8 = (_i & 7) << 3; \
            uint32_t _off = (uint32_t)(_r * 128) + (((uint32_t)_c8 * 2) ^ (((uint32_t)_r & 7) << 4)); \
            uint4 _vh = make_uint4(0u,0u,0u,0u), _vl = _vh; \
            if (bperm) { \
                size_t _ga = (size_t)(((_r & 31) << 10) + tb4 + (_r >> 5)) * DIM + _kb + _c8; \
                _vh = *(const uint4*)(Ahi + _ga); \
                _vl = *(const uint4*)(Alo + _ga); \
            } else { \
                int _tl = t0 + _r - off0; \
                if (_tl >= 0 && _tl < LSEQ) { \
                    size_t _ga = (size_t)(m0 + _r - off0) * DIM + _kb + _c8; \
                    _vh = *(const uint4*)(Ahi + _ga); \
                    _vl = *(const uint4*)(Alo + _ga); \
                } \
            } \
            *(uint4*)(smem + _off) = _vh; \
            *(uint4*)(smem + 16640 + _off) = _vl; \
        } \
    } while (0)

    #define DO_COPY_B(IDX, ST) do { \
        const int _sl = (IDX) / taps, _tp = (IDX) % taps; \
        const int _kb = _sl << 6; \
        const int _rbase = (taps == 3 ? _tp * DIM : 0) + n0; \
        char* _bp = smem + 33280 + (ST) * 32768; \
        for (int _i = tid; _i < 1024; _i += 256) { \
            int _r = _i >> 3, _c8 = (_i & 7) << 3; \
            uint32_t _off = (uint32_t)(_r * 128) + (((uint32_t)_c8 * 2) ^ (((uint32_t)_r & 7) << 4)); \
            size_t _ga = (size_t)(_rbase + _r) * DIM + _kb + _c8; \
            *(uint4*)(_bp + _off) = *(const uint4*)(BwHi + _ga); \
            *(uint4*)(_bp + 16384 + _off) = *(const uint4*)(BwLo + _ga); \
        } \
    } while (0)

    const int NB = 8 * taps;
    DO_COPY_A(0);
    DO_COPY_B(0, 0);
    __syncthreads();

    for (int idx = 0; idx < NB; idx++) {
        const int tap = idx % taps;
        const int bsel = idx & 1;
        const bool lastTap = (tap == taps - 1);

        if (idx + 1 < NB) DO_COPY_B(idx + 1, bsel ^ 1);

        const uint32_t aHiB = sb;
        const uint32_t aLoB = sb + 16640;
        const uint32_t bHiB = sb + 33280 + (uint32_t)bsel * 32768;
        const uint32_t bLoB = bHiB + 16384;
        #pragma unroll
        for (int k16 = 0; k16 < 4; k16++) {
            const uint32_t colA = (uint32_t)(k16 * 32) + (((uint32_t)lane >> 4) << 4);
            const uint32_t colB = (uint32_t)(k16 * 32) + ((((uint32_t)lane >> 3) & 1) << 4);
            uint32_t afh[2][4], afl[2][4];
            #pragma unroll
            for (int mt = 0; mt < 2; mt++) {
                uint32_t row = (uint32_t)(wm * 32 + mt * 16 + (lane & 15) + tap);
                uint32_t ad = row * 128 + (colA ^ ((row & 7) << 4));
                LDSM_X4(afh[mt][0], afh[mt][1], afh[mt][2], afh[mt][3], aHiB + ad);
                LDSM_X4(afl[mt][0], afl[mt][1], afl[mt][2], afl[mt][3], aLoB + ad);
            }
            #pragma unroll
            for (int half = 0; half < 2; half++) {
                uint32_t bfh[4][2], bfl[4][2];
                #pragma unroll
                for (int np = 0; np < 2; np++) {
                    uint32_t row = (uint32_t)(wn * 64 + (half * 2 + np) * 16 +
                                              (((lane >> 4) << 3) | (lane & 7)));
                    uint32_t bd = row * 128 + (colB ^ ((row & 7) << 4));
                    LDSM_X4(bfh[2*np][0], bfh[2*np][1], bfh[2*np+1][0], bfh[2*np+1][1], bHiB + bd);
                    LDSM_X4(bfl[2*np][0], bfl[2*np][1], bfl[2*np+1][0], bfl[2*np+1][1], bLoB + bd);
                }
                #pragma unroll
                for (int mt = 0; mt < 2; mt++)
                    #pragma unroll
                    for (int nt = 0; nt < 4; nt++) {
                        float* ac = acc[mt][half * 4 + nt];
                        MMA16816(ac, afh[mt], bfh[nt]);
                        MMA16816(ac, afl[mt], bfh[nt]);
                        MMA16816(ac, afh[mt], bfl[nt]);
                    }
            }
        }
        __syncthreads();
        if (lastTap && idx + 1 < NB) {
            DO_COPY_A((idx + 1) / taps);
            __syncthreads();
        }
    }
    #undef DO_COPY_A
    #undef DO_COPY_B

    const int g  = lane >> 2;
    const int tg = lane & 3;
    if (gout == nullptr) {            // conv epilogue
        #pragma unroll
        for (int mt = 0; mt < 2; mt++) {
            const int mlo = m0 + wm * 32 + mt * 16 + g;
            const int mhi = mlo + 8;
            #pragma unroll
            for (int nt = 0; nt < 8; nt++) {
                const int n = n0 + wn * 64 + nt * 8 + tg * 2;
                const float al0 = g_alpha[layer][n],     be0 = g_beta[layer][n];
                const float al1 = g_alpha[layer][n + 1], be1 = g_beta[layer][n + 1];
                float v00 = fmaxf(fmaf(acc[mt][nt][0], al0, be0), 0.f);
                float v01 = fmaxf(fmaf(acc[mt][nt][1], al1, be1), 0.f);
                float v10 = fmaxf(fmaf(acc[mt][nt][2], al0, be0), 0.f);
                float v11 = fmaxf(fmaf(acc[mt][nt][3], al1, be1), 0.f);
                __nv_bfloat16 h00 = __float2bfloat16(v00), h01 = __float2bfloat16(v01);
                __nv_bfloat16 h10 = __float2bfloat16(v10), h11 = __float2bfloat16(v11);
                __nv_bfloat16 l00 = __float2bfloat16(v00 - __bfloat162float(h00));
                __nv_bfloat16 l01 = __float2bfloat16(v01 - __bfloat162float(h01));
                __nv_bfloat16 l10 = __float2bfloat16(v10 - __bfloat162float(h10));
                __nv_bfloat16 l11 = __float2bfloat16(v11 - __bfloat162float(h11));
                __nv_bfloat162 ph0; ph0.x = h00; ph0.y = h01;
                __nv_bfloat162 ph1; ph1.x = h10; ph1.y = h11;
                __nv_bfloat162 pl0; pl0.x = l00; pl0.y = l01;
                __nv_bfloat162 pl1; pl1.x = l10; pl1.y = l11;
                *(__nv_bfloat162*)(outHi + (size_t)mlo * DIM + n) = ph0;
                *(__nv_bfloat162*)(outHi + (size_t)mhi * DIM + n) = ph1;
                *(__nv_bfloat162*)(outLo + (size_t)mlo * DIM + n) = pl0;
                *(__nv_bfloat162*)(outLo + (size_t)mhi * DIM + n) = pl1;
            }
        }
    } else {                          // gates (bperm): smem transpose -> coalesced
        float* tile = (float*)smem;
        #pragma unroll
        for (int mt = 0; mt < 2; mt++) {
            const int rlo = wm * 32 + mt * 16 + g;
            const int rhi = rlo + 8;
            #pragma unroll
            for (int nt = 0; nt < 8; nt++) {
                const int nl = wn * 64 + nt * 8 + tg * 2;
                const float b0 = bias[n0 + nl], b1 = bias[n0 + nl + 1];
                tile[rlo * 129 + nl    ] = acc[mt][nt][0] + b0;
                tile[rlo * 129 + nl + 1] = acc[mt][nt][1] + b1;
                tile[rhi * 129 + nl    ] = acc[mt][nt][2] + b0;
                tile[rhi * 129 + nl + 1] = acc[mt][nt][3] + b1;
            }
        }
        __syncthreads();
        for (int i = tid; i < 16384; i += 256) {
            int b_  = i & 31;
            int nl  = (i >> 5) & 127;
            int tt  = i >> 12;
            gout[((size_t)(tb4 + tt) * GDIM + n0 + nl) * 32 + b_] =
                tile[(tt * 32 + b_) * 129 + nl];
        }
    }
}

// =================== persistent LSTM recurrence — fp16 h, K_eff=1024 ==========
#define R_WHI 0
#define R_WLO 33280
#define R_A   66560
#define R_PART 99840                        // 16*32*33*4 = 67584
#define R_OBH  167424                       // float[288] = 1152
#define R_OBP  168576                       // ushort[288] = 576
#define R_RED  169152                       // float[32*33] = 4224
#define R_SMEM 173376

__global__ void __launch_bounds__(512, 1) lstm_recur_kernel(
    const __half* __restrict__ wrHi, const __half* __restrict__ wrLo,
    const int* __restrict__ lengths, const float* __restrict__ gpreAll,
    float* __restrict__ out)
{
    extern __shared__ char sm[];
    float* part = (float*)(sm + R_PART);
    float* obh  = (float*)(sm + R_OBH);
    unsigned short* obp16 = (unsigned short*)(sm + R_OBP);
    float* red  = (float*)(sm + R_RED);
    __shared__ int len_s[32];

    const int tid = threadIdx.x;
    const int lane = tid & 31, u = tid >> 5;        // u in [0,16)
    const int dir = blockIdx.x >> 6;
    const int dc  = (blockIdx.x & 63) << 3;
    const uint32_t sb = smem_to_u32(sm);
    const float* gpre = gpreAll + (size_t)dir * MTOT * GDIM;
    const __half* wHi = wrHi + (size_t)dir * GDIM * DIM;
    const __half* wLo = wrLo + (size_t)dir * GDIM * DIM;
    unsigned* barP = &g_bar[dir][0];

    // stage W (permuted rows, 1040B padded stride)
    for (int i = tid; i < 2048; i += 512) {
        int r = i >> 6, c16 = i & 63;
        int n = ((r >> 3) << 9) + dc + (r & 7);
        uint4 vh = *(const uint4*)(wHi + (size_t)n * DIM + c16 * 8);
        uint4 vl = *(const uint4*)(wLo + (size_t)n * DIM + c16 * 8);
        *(uint4*)(sm + R_WHI + r * 1040 + c16 * 16) = vh;
        *(uint4*)(sm + R_WLO + r * 1040 + c16 * 16) = vl;
    }
    if (tid < 32) len_s[tid] = lengths[tid];
    if (tid < 32)
        ((uint4*)g_h16[0][dir])[tid * 64 + (dc >> 3)] = make_uint4(0u, 0u, 0u, 0u);
    __syncthreads();

    // preload W fragments: 4 tiles/warp
    uint32_t wf[4][8];
    {
        const uint32_t rB = (uint32_t)(((lane >> 4) << 3) | (lane & 7));
        const uint32_t hB = (uint32_t)(((lane >> 3) & 1) << 4);
        #pragma unroll
        for (int i = 0; i < 4; i++) {
            int tt = u * 4 + i;
            int sec = tt >> 5, kk = tt & 31;
            uint32_t base = sb + (sec ? R_WLO : R_WHI);
            uint32_t col = (uint32_t)(kk * 32) + hB;
            LDSM_X4(wf[i][0], wf[i][1], wf[i][2], wf[i][3], base + rB * 1040 + col);
            LDSM_X4(wf[i][4], wf[i][5], wf[i][6], wf[i][7], base + (rB + 16) * 1040 + col);
        }
    }
    const int lenb = len_s[lane];

    // startup barrier (monotonic, target 64)
    __syncthreads();
    if (tid == 0) {
        unsigned prev = bar_arrive_(barP);
        if (prev != 63u) bar_wait_(barP, 64u);
    }
    __syncthreads();

    const uint32_t rA = (uint32_t)(lane & 15);
    const uint32_t hA = (uint32_t)((lane >> 4) << 4);
    float cst = 0.f;

    // gpre double-buffer: preload step 0
    float gp0 = 0.f, gp1 = 0.f, gp2 = 0.f, gp3 = 0.f;
    if (u < 8) {
        const int t0_ = dir ? (LSEQ - 1) : 0;
        const float* gq = gpre + ((size_t)t0_ * GDIM + dc + u) * 32 + lane;
        gp0 = __ldg(gq);
        gp1 = __ldg(gq + (size_t)512 * 32);
        gp2 = __ldg(gq + (size_t)1024 * 32);
        gp3 = __ldg(gq + (size_t)1536 * 32);
    }

    for (int s = 0; s < LSEQ; s++) {
        const int t = dir ? (LSEQ - 1 - s) : s;
        const int p = s & 1;
        const unsigned tgt = 64u * (unsigned)(s + 2);

        // next-step gpre loads (hidden behind this step)
        float gn0 = 0.f, gn1 = 0.f, gn2 = 0.f, gn3 = 0.f;
        if (u < 8 && s + 1 < LSEQ) {
            const int tn = dir ? (LSEQ - 2 - s) : (s + 1);
            const float* gq = gpre + ((size_t)tn * GDIM + dc + u) * 32 + lane;
            gn0 = __ldg(gq);
            gn1 = __ldg(gq + (size_t)512 * 32);
            gn2 = __ldg(gq + (size_t)1024 * 32);
            gn3 = __ldg(gq + (size_t)1536 * 32);
        }

        {   // stage h_prev fp16: 32KB
            const uint4* hp = (const uint4*)g_h16[p][dir];
            #pragma unroll
            for (int i = 0; i < 4; i++) {
                int idx = i * 512 + tid;
                int b_ = idx >> 6, c = idx & 63;
                uint4 v = __ldcg(hp + idx);
                if (dir && t >= len_s[b_] - 1) v = make_uint4(0u, 0u, 0u, 0u);
                *(uint4*)(sm + R_A + b_ * 1040 + c * 16) = v;
            }
        }
        __syncthreads();                                 // (1)

        float acc[2][4][4];
        #pragma unroll
        for (int a = 0; a < 2; a++)
            #pragma unroll
            for (int b = 0; b < 4; b++)
                #pragma unroll
                for (int c = 0; c < 4; c++) acc[a][b][c] = 0.f;

        #pragma unroll
        for (int i = 0; i < 4; i++) {
            int tt = u * 4 + i;
            int kk = tt & 31;
            uint32_t col = (uint32_t)(kk * 32) + hA;
            uint32_t af0[4], af1[4];
            LDSM_X4(af0[0], af0[1], af0[2], af0[3], sb + R_A + rA * 1040 + col);
            LDSM_X4(af1[0], af1[1], af1[2], af1[3], sb + R_A + (rA + 16) * 1040 + col);
            #pragma unroll
            for (int nt = 0; nt < 4; nt++) {
                MMAF16(acc[0][nt], af0, &wf[i][nt * 2]);
                MMAF16(acc[1][nt], af1, &wf[i][nt * 2]);
            }
        }

        {
            int row = lane >> 2, colp = (lane & 3) * 2;
            #pragma unroll
            for (int mt = 0; mt < 2; mt++)
                #pragma unroll
                for (int nt = 0; nt < 4; nt++) {
                    float* p0 = part + (u * 32 + mt * 16 + row) * 33 + nt * 8 + colp;
                    p0[0] = acc[mt][nt][0]; p0[1] = acc[mt][nt][1];
                    float* p1 = part + (u * 32 + mt * 16 + row + 8) * 33 + nt * 8 + colp;
                    p1[0] = acc[mt][nt][2]; p1[1] = acc[mt][nt][3];
                }
        }
        __syncthreads();                                 // (2)

        // stage A reduce: all 512 threads, 2 outputs each (sum 16 warps)
        {
            int o = tid;
            #pragma unroll
            for (int rep = 0; rep < 2; rep++, o += 512) {
                int b_ = o >> 5, cl = o & 31;
                float sum = 0.f;
                #pragma unroll
                for (int w = 0; w < 16; w++)
                    sum += part[(w * 32 + b_) * 33 + cl];
                red[b_ * 33 + cl] = sum;
            }
        }
        __syncthreads();                                 // (3)

        if (u < 8) {   // stage B: cell update (b=lane, dim=dc+u)
            float s0 = red[lane * 33 + u];
            float s1 = red[lane * 33 + 8 + u];
            float s2 = red[lane * 33 + 16 + u];
            float s3 = red[lane * 33 + 24 + u];
            float iv = sigmoid_fast_(gp0 + s0);
            float gv = tanh_fast_(gp1 + s1);
            float fv = sigmoid_fast_(gp2 + s2 + 1.f);
            float ov = sigmoid_fast_(gp3 + s3);
            if (dir && t >= lenb - 1) cst = 0.f;
            cst = fv * cst + iv * gv;
            float hh = ov * tanh_fast_(cst);
            obh[lane * 9 + u] = hh;
            obp16[lane * 9 + u] = __half_as_ushort(__float2half_rn(hh));
        }
        gp0 = gn0; gp1 = gn1; gp2 = gn2; gp3 = gn3;

        unsigned sdone = 0u;
        if (tid < 256) {
            asm volatile("bar.sync 1, 256;" ::: "memory");   // warps 0-7 only
            if (tid < 32) {   // publish h: one STG.128 per batch row
                const unsigned short* sp = obp16 + tid * 9;
                uint4 o4;
                o4.x = (unsigned)sp[0] | ((unsigned)sp[1] << 16);
                o4.y = (unsigned)sp[2] | ((unsigned)sp[3] << 16);
                o4.z = (unsigned)sp[4] | ((unsigned)sp[5] << 16);
                o4.w = (unsigned)sp[6] | ((unsigned)sp[7] << 16);
                ((uint4*)g_h16[p ^ 1][dir])[tid * 64 + (dc >> 3)] = o4;
                __syncwarp();
                if (tid == 0) {
                    unsigned prev = bar_arrive_(barP);
                    sdone = (prev == tgt - 1u) ? 1u : 0u;
                }
            }
            // out store off the critical path
            int b2 = tid >> 3, d2 = tid & 7;
            out[(((size_t)b2 << 10) + t) * 1024 + (dir << 9) + dc + d2] = obh[b2 * 9 + d2];
        }
        if (tid == 0 && !sdone) bar_wait_(barP, tgt);
        __syncthreads();                                 // (4)
    }
}

// =================== launch ===================================================
extern "C" void kernel_launch(void* const* d_in, const int* in_sizes, int n_in,
                              void* d_out, int out_size)
{
    (void)in_sizes; (void)n_in; (void)out_size;
    const int*   x        = (const int*)  d_in[0];
    const int*   lengths  = (const int*)  d_in[1];
    const float* embed_w  = (const float*)d_in[2];
    const float* c1w = (const float*)d_in[3];
    const float* c1b = (const float*)d_in[4];
    const float* c2w = (const float*)d_in[5];
    const float* c2b = (const float*)d_in[6];
    const float* c3w = (const float*)d_in[7];
    const float* c3b = (const float*)d_in[8];
    const float* wf  = (const float*)d_in[9];
    const float* bf  = (const float*)d_in[10];
    const float* wb  = (const float*)d_in[11];
    const float* bb  = (const float*)d_in[12];
    const float* s1 = (const float*)d_in[13]; const float* o1 = (const float*)d_in[14];
    const float* m1 = (const float*)d_in[15]; const float* v1 = (const float*)d_in[16];
    const float* s2 = (const float*)d_in[17]; const float* o2 = (const float*)d_in[18];
    const float* m2 = (const float*)d_in[19]; const float* v2 = (const float*)d_in[20];
    const float* s3 = (const float*)d_in[21]; const float* o3 = (const float*)d_in[22];
    const float* m3 = (const float*)d_in[23]; const float* v3 = (const float*)d_in[24];
    float* out = (float*)d_out;

    __nv_bfloat16 *aHi, *aLo, *bHi, *bLo, *wcH, *wcL, *wgH, *wgL;
    __half *wrH, *wrL;
    cudaGetSymbolAddress((void**)&aHi, g_aHi);
    cudaGetSymbolAddress((void**)&aLo, g_aLo);
    cudaGetSymbolAddress((void**)&bHi, g_bHi);
    cudaGetSymbolAddress((void**)&bLo, g_bLo);
    cudaGetSymbolAddress((void**)&wcH, g_wcHi);
    cudaGetSymbolAddress((void**)&wcL, g_wcLo);
    cudaGetSymbolAddress((void**)&wgH, g_wgHi);
    cudaGetSymbolAddress((void**)&wgL, g_wgLo);
    cudaGetSymbolAddress((void**)&wrH, g_wrHi);
    cudaGetSymbolAddress((void**)&wrL, g_wrLo);
    float* gpre;
    cudaGetSymbolAddress((void**)&gpre, g_gpre);

    const size_t WC = (size_t)3 * DIM * DIM;

    const int SMEM_GEMM  = 33280 + 2 * 32768;     // 98816
    cudaFuncSetAttribute(mma_gemm_kernel,
                         cudaFuncAttributeMaxDynamicSharedMemorySize, SMEM_GEMM);
    cudaFuncSetAttribute(lstm_recur_kernel,
                         cudaFuncAttributeMaxDynamicSharedMemorySize, R_SMEM);

    dim3 gconv(MTOT / 128, DIM / 128, 1);
    dim3 ggate(MTOT / 128, GDIM / 128, 2);
    dim3 bwp(32, 8);
    dim3 gwc(DIM / 32, DIM / 32, 9);          // conv wprep: (k,n,layer*3+tap)
    dim3 gwg(DIM / 32, GDIM / 32, 2);         // gate/rec wprep: (k,n,dir)

    wprep_conv_kernel<<<gwc, bwp>>>(c1w, c2w, c3w);
    bnprep_kernel<<<1, 512>>>(c1b, s1, o1, m1, v1,
                              c2b, s2, o2, m2, v2,
                              c3b, s3, o3, m3, v3);
    embed_kernel<<<MTOT, 128>>>(x, embed_w);
    mma_gemm_kernel<<<gconv, 256, SMEM_GEMM>>>(aHi, aLo, wcH + 0 * WC, wcL + 0 * WC,
        3, 0, 0, bHi, bLo, nullptr, nullptr, nullptr);
    mma_gemm_kernel<<<gconv, 256, SMEM_GEMM>>>(bHi, bLo, wcH + 1 * WC, wcL + 1 * WC,
        3, 1, 0, aHi, aLo, nullptr, nullptr, nullptr);
    mma_gemm_kernel<<<gconv, 256, SMEM_GEMM>>>(aHi, aLo, wcH + 2 * WC, wcL + 2 * WC,
        3, 2, 0, bHi, bLo, nullptr, nullptr, nullptr);
    wprep_gate_kernel<<<gwg, bwp>>>(wf, wb);
    wprep_rec_kernel<<<gwg, bwp>>>(wf, wb);
    mma_gemm_kernel<<<ggate, 256, SMEM_GEMM>>>(bHi, bLo, wgH, wgL,
        1, -1, 1, nullptr, nullptr, bf, bb, gpre);
    lstm_recur_kernel<<<128, 512, R_SMEM>>>(wrH, wrL, lengths, gpre, out);
}

// round 12
// speedup vs baseline: 3.2203x; 1.0436x over previous
#include <cuda_runtime.h>
#include <cuda_bf16.h>
#include <cuda_fp16.h>
#include <stdint.h>
#include <math.h>

#define BSZ   32
#define LSEQ  1024
#define DIM   512
#define MTOT  (BSZ*LSEQ)          // 32768
#define GDIM  2048                // 4*DIM

// =================== scratch (device globals) ================================
__device__ __align__(128) __nv_bfloat16 g_aHi[(size_t)MTOT*DIM];
__device__ __align__(128) __nv_bfloat16 g_aLo[(size_t)MTOT*DIM];
__device__ __align__(128) __nv_bfloat16 g_bHi[(size_t)MTOT*DIM];
__device__ __align__(128) __nv_bfloat16 g_bLo[(size_t)MTOT*DIM];
__device__ __align__(128) __nv_bfloat16 g_wcHi[3][(size_t)3*DIM*DIM];   // [layer][tap*512+n][k]
__device__ __align__(128) __nv_bfloat16 g_wcLo[3][(size_t)3*DIM*DIM];
__device__ __align__(128) __nv_bfloat16 g_wgHi[2][(size_t)GDIM*DIM];    // [dir][n][k]
__device__ __align__(128) __nv_bfloat16 g_wgLo[2][(size_t)GDIM*DIM];
__device__ __align__(128) __half g_wrHi[2][(size_t)GDIM*DIM];           // recurrent W fp16 (hi only)
__device__ float g_gpre[2][(size_t)MTOT*GDIM];   // [dir][ (t*2048 + col)*32 + b ]
__device__ __align__(128) __half g_h16[2][2][BSZ*DIM];  // [parity][dir][b*512+d]
__device__ float g_alpha[3][DIM];
__device__ float g_beta[3][DIM];
__device__ __align__(1024) unsigned g_bar[2][256];    // monotonic, dirs 1KB apart

// =================== primitives ===============================================
__device__ __forceinline__ uint32_t smem_to_u32(const void* p) {
    uint32_t a;
    asm("{ .reg .u64 t; cvta.to.shared.u64 t, %1; cvt.u32.u64 %0, t; }" : "=r"(a) : "l"(p));
    return a;
}
#define LDSM_X4(r0, r1, r2, r3, addr) \
    asm volatile("ldmatrix.sync.aligned.m8n8.x4.shared.b16 {%0,%1,%2,%3}, [%4];" \
        : "=r"(r0), "=r"(r1), "=r"(r2), "=r"(r3) : "r"(addr))
#define MMA16816(c, a, b) \
    asm volatile("mma.sync.aligned.m16n8k16.row.col.f32.bf16.bf16.f32 " \
        "{%0,%1,%2,%3}, {%4,%5,%6,%7}, {%8,%9}, {%0,%1,%2,%3};" \
        : "+f"((c)[0]), "+f"((c)[1]), "+f"((c)[2]), "+f"((c)[3]) \
        : "r"((a)[0]), "r"((a)[1]), "r"((a)[2]), "r"((a)[3]), \
          "r"((b)[0]), "r"((b)[1]))
#define MMAF16(c, a, b) \
    asm volatile("mma.sync.aligned.m16n8k16.row.col.f32.f16.f16.f32 " \
        "{%0,%1,%2,%3}, {%4,%5,%6,%7}, {%8,%9}, {%0,%1,%2,%3};" \
        : "+f"((c)[0]), "+f"((c)[1]), "+f"((c)[2]), "+f"((c)[3]) \
        : "r"((a)[0]), "r"((a)[1]), "r"((a)[2]), "r"((a)[3]), \
          "r"((b)[0]), "r"((b)[1]))

__device__ __forceinline__ float tanh_fast_(float x) {
    float y;
    asm("tanh.approx.f32 %0, %1;" : "=f"(y) : "f"(x));
    return y;
}
__device__ __forceinline__ float sigmoid_fast_(float x) {
    return fmaf(tanh_fast_(0.5f * x), 0.5f, 0.5f);
}
__device__ __forceinline__ unsigned bar_arrive_(unsigned* arr) {
    unsigned prev;
    asm volatile("atom.release.gpu.global.add.u32 %0, [%1], 1;"
                 : "=r"(prev) : "l"(arr) : "memory");
    return prev;
}
__device__ __forceinline__ void bar_wait_(unsigned* arr, unsigned tgt) {
    unsigned v;
    do {
        asm volatile("ld.acquire.gpu.global.u32 %0, [%1];" : "=r"(v) : "l"(arr));
    } while (v < tgt);
}

// =================== BN fold =================================================
__global__ void bnprep_kernel(
    const float* __restrict__ b1, const float* __restrict__ s1, const float* __restrict__ o1,
    const float* __restrict__ m1, const float* __restrict__ v1,
    const float* __restrict__ b2, const float* __restrict__ s2, const float* __restrict__ o2,
    const float* __restrict__ m2, const float* __restrict__ v2,
    const float* __restrict__ b3, const float* __restrict__ s3, const float* __restrict__ o3,
    const float* __restrict__ m3, const float* __restrict__ v3)
{
    int i = threadIdx.x;
    if (i < DIM) {
        float g;
        g = s1[i] * rsqrtf(v1[i] + 1e-5f); g_alpha[0][i] = g; g_beta[0][i] = (b1[i] - m1[i]) * g + o1[i];
        g = s2[i] * rsqrtf(v2[i] + 1e-5f); g_alpha[1][i] = g; g_beta[1][i] = (b2[i] - m2[i]) * g + o2[i];
        g = s3[i] * rsqrtf(v3[i] + 1e-5f); g_alpha[2][i] = g; g_beta[2][i] = (b3[i] - m3[i]) * g + o3[i];
    }
}

// =================== weight prep (coalesced 32x32 transposes) =================
__global__ void wprep_conv_kernel(const float* __restrict__ c1,
                                  const float* __restrict__ c2,
                                  const float* __restrict__ c3)
{
    __shared__ float tile[32][33];
    const int tx = threadIdx.x, ty = threadIdx.y;
    const int k0 = blockIdx.x * 32, n0 = blockIdx.y * 32;
    const int layer = blockIdx.z / 3, tap = blockIdx.z % 3;
    const float* W = (layer == 0) ? c1 : ((layer == 1) ? c2 : c3);
    #pragma unroll
    for (int i = 0; i < 4; i++)
        tile[ty + i * 8][tx] = W[(size_t)(tap * DIM + k0 + ty + i * 8) * DIM + n0 + tx];
    __syncthreads();
    #pragma unroll
    for (int i = 0; i < 4; i++) {
        int n = n0 + ty + i * 8;
        float v = tile[tx][ty + i * 8];
        __nv_bfloat16 h = __float2bfloat16(v);
        __nv_bfloat16 l = __float2bfloat16(v - __bfloat162float(h));
        g_wcHi[layer][(size_t)(tap * DIM + n) * DIM + k0 + tx] = h;
        g_wcLo[layer][(size_t)(tap * DIM + n) * DIM + k0 + tx] = l;
    }
}
__global__ void wprep_gate_kernel(const float* __restrict__ Wf,
                                  const float* __restrict__ Wb)
{
    __shared__ float tile[32][33];
    const int tx = threadIdx.x, ty = threadIdx.y;
    const int k0 = blockIdx.x * 32, n0 = blockIdx.y * 32;
    const int dir = blockIdx.z;
    const float* W = dir ? Wb : Wf;
    #pragma unroll
    for (int i = 0; i < 4; i++)
        tile[ty + i * 8][tx] = W[(size_t)(k0 + ty + i * 8) * GDIM + n0 + tx];
    __syncthreads();
    #pragma unroll
    for (int i = 0; i < 4; i++) {
        int n = n0 + ty + i * 8;
        float v = tile[tx][ty + i * 8];
        __nv_bfloat16 h = __float2bfloat16(v);
        __nv_bfloat16 l = __float2bfloat16(v - __bfloat162float(h));
        g_wgHi[dir][(size_t)n * DIM + k0 + tx] = h;
        g_wgLo[dir][(size_t)n * DIM + k0 + tx] = l;
    }
}
// recurrent W fp16 (hi only), rows 512..1023
__global__ void wprep_rec_kernel(const float* __restrict__ Wf,
                                 const float* __restrict__ Wb)
{
    __shared__ float tile[32][33];
    const int tx = threadIdx.x, ty = threadIdx.y;
    const int k0 = blockIdx.x * 32, n0 = blockIdx.y * 32;
    const int dir = blockIdx.z;
    const float* W = dir ? Wb : Wf;
    #pragma unroll
    for (int i = 0; i < 4; i++)
        tile[ty + i * 8][tx] = W[(size_t)(DIM + k0 + ty + i * 8) * GDIM + n0 + tx];
    __syncthreads();
    #pragma unroll
    for (int i = 0; i < 4; i++) {
        int n = n0 + ty + i * 8;
        g_wrHi[dir][(size_t)n * DIM + k0 + tx] = __float2half_rn(tile[tx][ty + i * 8]);
    }
}

// =================== embedding -> bf16 hi/lo =================================
__global__ void embed_kernel(const int* __restrict__ x, const float* __restrict__ ew)
{
    int m = blockIdx.x;
    int tok = x[m];
    int j = threadIdx.x;
    float4 v = ((const float4*)(ew + (size_t)tok * DIM))[j];
    float f[4] = {v.x, v.y, v.z, v.w};
    __nv_bfloat16 h[4], l[4];
    #pragma unroll
    for (int i = 0; i < 4; i++) {
        h[i] = __float2bfloat16(f[i]);
        l[i] = __float2bfloat16(f[i] - __bfloat162float(h[i]));
    }
    *(uint2*)(g_aHi + (size_t)m * DIM + j * 4) = *(uint2*)h;
    *(uint2*)(g_aLo + (size_t)m * DIM + j * 4) = *(uint2*)l;
}

// =================== bf16 mma.sync GEMM (unchanged engine) ====================
__global__ void __launch_bounds__(256, 2) mma_gemm_kernel(
    const __nv_bfloat16* __restrict__ Ahi, const __nv_bfloat16* __restrict__ Alo,
    const __nv_bfloat16* __restrict__ BwHi, const __nv_bfloat16* __restrict__ BwLo,
    int taps, int layer, int bperm,
    __nv_bfloat16* __restrict__ outHi, __nv_bfloat16* __restrict__ outLo,
    const float* __restrict__ biasA, const float* __restrict__ biasB,
    float* __restrict__ gout)
{
    extern __shared__ char smem[];
    const int tid = threadIdx.x;
    const int lane = tid & 31, wid = tid >> 5;
    const int wm = wid & 3, wn = wid >> 2;
    const int m0 = blockIdx.x * 128, n0 = blockIdx.y * 128;
    const int t0 = m0 & (LSEQ - 1);
    const int tb4 = blockIdx.x * 4;
    const int dz = blockIdx.z;
    const uint32_t sb = smem_to_u32(smem);

    if (bperm) {
        BwHi += (size_t)dz * GDIM * DIM;
        BwLo += (size_t)dz * GDIM * DIM;
        gout += (size_t)dz * MTOT * GDIM;
    }
    const float* bias = dz ? biasB : biasA;

    const int off0  = taps >> 1;
    const int arows = 128 + (taps - 1);

    float acc[2][8][4];
    #pragma unroll
    for (int a = 0; a < 2; a++)
        #pragma unroll
        for (int b = 0; b < 8; b++)
            #pragma unroll
            for (int c = 0; c < 4; c++) acc[a][b][c] = 0.f;

    #define DO_COPY_A(SLICE) do { \
        const int _kb = (SLICE) << 6; \
        const int _tot = arows * 8; \
        for (int _i = tid; _i < _tot; _i += 256) { \
            int _r = _i >> 3, _c8 = (_i & 7) << 3; \
            uint32_t _off = (uint32_t)(_r * 128) + (((uint32_t)_c8 * 2) ^ (((uint32_t)_r & 7) << 4)); \
            uint4 _vh = make_uint4(0u,0u,0u,0u), _vl = _vh; \
            if (bperm) { \
                size_t _ga = (size_t)(((_r & 31) << 10) + tb4 + (_r >> 5)) * DIM + _kb + _c8; \
                _vh = *(const uint4*)(Ahi + _ga); \
                _vl = *(const uint4*)(Alo + _ga); \
            } else { \
                int _tl = t0 + _r - off0; \
                if (_tl >= 0 && _tl < LSEQ) { \
                    size_t _ga = (size_t)(m0 + _r - off0) * DIM + _kb + _c8; \
                    _vh = *(const uint4*)(Ahi + _ga); \
                    _vl = *(const uint4*)(Alo + _ga); \
                } \
            } \
            *(uint4*)(smem + _off) = _vh; \
            *(uint4*)(smem + 16640 + _off) = _vl; \
        } \
    } while (0)

    #define DO_COPY_B(IDX, ST) do { \
        const int _sl = (IDX) / taps, _tp = (IDX) % taps; \
        const int _kb = _sl << 6; \
        const int _rbase = (taps == 3 ? _tp * DIM : 0) + n0; \
        char* _bp = smem + 33280 + (ST) * 32768; \
        for (int _i = tid; _i < 1024; _i += 256) { \
            int _r = _i >> 3, _c8 = (_i & 7) << 3; \
            uint32_t _off = (uint32_t)(_r * 128) + (((uint32_t)_c8 * 2) ^ (((uint32_t)_r & 7) << 4)); \
            size_t _ga = (size_t)(_rbase + _r) * DIM + _kb + _c8; \
            *(uint4*)(_bp + _off) = *(const uint4*)(BwHi + _ga); \
            *(uint4*)(_bp + 16384 + _off) = *(const uint4*)(BwLo + _ga); \
        } \
    } while (0)

    const int NB = 8 * taps;
    DO_COPY_A(0);
    DO_COPY_B(0, 0);
    __syncthreads();

    for (int idx = 0; idx < NB; idx++) {
        const int tap = idx % taps;
        const int bsel = idx & 1;
        const bool lastTap = (tap == taps - 1);

        if (idx + 1 < NB) DO_COPY_B(idx + 1, bsel ^ 1);

        const uint32_t aHiB = sb;
        const uint32_t aLoB = sb + 16640;
        const uint32_t bHiB = sb + 33280 + (uint32_t)bsel * 32768;
        const uint32_t bLoB = bHiB + 16384;
        #pragma unroll
        for (int k16 = 0; k16 < 4; k16++) {
            const uint32_t colA = (uint32_t)(k16 * 32) + (((uint32_t)lane >> 4) << 4);
            const uint32_t colB = (uint32_t)(k16 * 32) + ((((uint32_t)lane >> 3) & 1) << 4);
            uint32_t afh[2][4], afl[2][4];
            #pragma unroll
            for (int mt = 0; mt < 2; mt++) {
                uint32_t row = (uint32_t)(wm * 32 + mt * 16 + (lane & 15) + tap);
                uint32_t ad = row * 128 + (colA ^ ((row & 7) << 4));
                LDSM_X4(afh[mt][0], afh[mt][1], afh[mt][2], afh[mt][3], aHiB + ad);
                LDSM_X4(afl[mt][0], afl[mt][1], afl[mt][2], afl[mt][3], aLoB + ad);
            }
            #pragma unroll
            for (int half = 0; half < 2; half++) {
                uint32_t bfh[4][2], bfl[4][2];
                #pragma unroll
                for (int np = 0; np < 2; np++) {
                    uint32_t row = (uint32_t)(wn * 64 + (half * 2 + np) * 16 +
                                              (((lane >> 4) << 3) | (lane & 7)));
                    uint32_t bd = row * 128 + (colB ^ ((row & 7) << 4));
                    LDSM_X4(bfh[2*np][0], bfh[2*np][1], bfh[2*np+1][0], bfh[2*np+1][1], bHiB + bd);
                    LDSM_X4(bfl[2*np][0], bfl[2*np][1], bfl[2*np+1][0], bfl[2*np+1][1], bLoB + bd);
                }
                #pragma unroll
                for (int mt = 0; mt < 2; mt++)
                    #pragma unroll
                    for (int nt = 0; nt < 4; nt++) {
                        float* ac = acc[mt][half * 4 + nt];
                        MMA16816(ac, afh[mt], bfh[nt]);
                        MMA16816(ac, afl[mt], bfh[nt]);
                        MMA16816(ac, afh[mt], bfl[nt]);
                    }
            }
        }
        __syncthreads();
        if (lastTap && idx + 1 < NB) {
            DO_COPY_A((idx + 1) / taps);
            __syncthreads();
        }
    }
    #undef DO_COPY_A
    #undef DO_COPY_B

    const int g  = lane >> 2;
    const int tg = lane & 3;
    if (gout == nullptr) {            // conv epilogue
        #pragma unroll
        for (int mt = 0; mt < 2; mt++) {
            const int mlo = m0 + wm * 32 + mt * 16 + g;
            const int mhi = mlo + 8;
            #pragma unroll
            for (int nt = 0; nt < 8; nt++) {
                const int n = n0 + wn * 64 + nt * 8 + tg * 2;
                const float al0 = g_alpha[layer][n],     be0 = g_beta[layer][n];
                const float al1 = g_alpha[layer][n + 1], be1 = g_beta[layer][n + 1];
                float v00 = fmaxf(fmaf(acc[mt][nt][0], al0, be0), 0.f);
                float v01 = fmaxf(fmaf(acc[mt][nt][1], al1, be1), 0.f);
                float v10 = fmaxf(fmaf(acc[mt][nt][2], al0, be0), 0.f);
                float v11 = fmaxf(fmaf(acc[mt][nt][3], al1, be1), 0.f);
                __nv_bfloat16 h00 = __float2bfloat16(v00), h01 = __float2bfloat16(v01);
                __nv_bfloat16 h10 = __float2bfloat16(v10), h11 = __float2bfloat16(v11);
                __nv_bfloat16 l00 = __float2bfloat16(v00 - __bfloat162float(h00));
                __nv_bfloat16 l01 = __float2bfloat16(v01 - __bfloat162float(h01));
                __nv_bfloat16 l10 = __float2bfloat16(v10 - __bfloat162float(h10));
                __nv_bfloat16 l11 = __float2bfloat16(v11 - __bfloat162float(h11));
                __nv_bfloat162 ph0; ph0.x = h00; ph0.y = h01;
                __nv_bfloat162 ph1; ph1.x = h10; ph1.y = h11;
                __nv_bfloat162 pl0; pl0.x = l00; pl0.y = l01;
                __nv_bfloat162 pl1; pl1.x = l10; pl1.y = l11;
                *(__nv_bfloat162*)(outHi + (size_t)mlo * DIM + n) = ph0;
                *(__nv_bfloat162*)(outHi + (size_t)mhi * DIM + n) = ph1;
                *(__nv_bfloat162*)(outLo + (size_t)mlo * DIM + n) = pl0;
                *(__nv_bfloat162*)(outLo + (size_t)mhi * DIM + n) = pl1;
            }
        }
    } else {                          // gates (bperm): smem transpose -> coalesced
        float* tile = (float*)smem;
        #pragma unroll
        for (int mt = 0; mt < 2; mt++) {
            const int rlo = wm * 32 + mt * 16 + g;
            const int rhi = rlo + 8;
            #pragma unroll
            for (int nt = 0; nt < 8; nt++) {
                const int nl = wn * 64 + nt * 8 + tg * 2;
                const float b0 = bias[n0 + nl], b1 = bias[n0 + nl + 1];
                tile[rlo * 129 + nl    ] = acc[mt][nt][0] + b0;
                tile[rlo * 129 + nl + 1] = acc[mt][nt][1] + b1;
                tile[rhi * 129 + nl    ] = acc[mt][nt][2] + b0;
                tile[rhi * 129 + nl + 1] = acc[mt][nt][3] + b1;
            }
        }
        __syncthreads();
        for (int i = tid; i < 16384; i += 256) {
            int b_  = i & 31;
            int nl  = (i >> 5) & 127;
            int tt  = i >> 12;
            gout[((size_t)(tb4 + tt) * GDIM + n0 + nl) * 32 + b_] =
                tile[(tt * 32 + b_) * 129 + nl];
        }
    }
}

// =================== persistent LSTM recurrence — fp16 h/W, K_eff=512 =========
#define R_WHI 0
#define R_A   33280
#define R_PART 66560                        // 16*32*33*4 = 67584
#define R_OBH  134144                       // float[288] = 1152
#define R_OBP  135296                       // ushort[288] = 576
#define R_RED  135872                       // float[32*33] = 4224
#define R_SMEM 140096

__global__ void __launch_bounds__(512, 1) lstm_recur_kernel(
    const __half* __restrict__ wrHi,
    const int* __restrict__ lengths, const float* __restrict__ gpreAll,
    float* __restrict__ out)
{
    extern __shared__ char sm[];
    float* part = (float*)(sm + R_PART);
    float* obh  = (float*)(sm + R_OBH);
    unsigned short* obp16 = (unsigned short*)(sm + R_OBP);
    float* red  = (float*)(sm + R_RED);
    __shared__ int len_s[32];

    const int tid = threadIdx.x;
    const int lane = tid & 31, u = tid >> 5;        // u in [0,16)
    const int dir = blockIdx.x >> 6;
    const int dc  = (blockIdx.x & 63) << 3;
    const uint32_t sb = smem_to_u32(sm);
    const float* gpre = gpreAll + (size_t)dir * MTOT * GDIM;
    const __half* wHi = wrHi + (size_t)dir * GDIM * DIM;
    unsigned* barP = &g_bar[dir][0];

    // stage W hi (permuted rows, 1040B padded stride)
    for (int i = tid; i < 2048; i += 512) {
        int r = i >> 6, c16 = i & 63;
        int n = ((r >> 3) << 9) + dc + (r & 7);
        uint4 vh = *(const uint4*)(wHi + (size_t)n * DIM + c16 * 8);
        *(uint4*)(sm + R_WHI + r * 1040 + c16 * 16) = vh;
    }
    if (tid < 32) len_s[tid] = lengths[tid];
    if (tid < 32)
        ((uint4*)g_h16[0][dir])[tid * 64 + (dc >> 3)] = make_uint4(0u, 0u, 0u, 0u);
    __syncthreads();

    // preload W fragments: 2 k16-tiles per warp (K_eff=512 -> 32 tiles)
    uint32_t wf[2][8];
    {
        const uint32_t rB = (uint32_t)(((lane >> 4) << 3) | (lane & 7));
        const uint32_t hB = (uint32_t)(((lane >> 3) & 1) << 4);
        #pragma unroll
        for (int i = 0; i < 2; i++) {
            int kk = u * 2 + i;
            uint32_t col = (uint32_t)(kk * 32) + hB;
            LDSM_X4(wf[i][0], wf[i][1], wf[i][2], wf[i][3], sb + R_WHI + rB * 1040 + col);
            LDSM_X4(wf[i][4], wf[i][5], wf[i][6], wf[i][7], sb + R_WHI + (rB + 16) * 1040 + col);
        }
    }
    const int lenb = len_s[lane];

    // startup barrier (monotonic, target 64)
    __syncthreads();
    if (tid == 0) {
        unsigned prev = bar_arrive_(barP);
        if (prev != 63u) bar_wait_(barP, 64u);
    }
    __syncthreads();

    const uint32_t rA = (uint32_t)(lane & 15);
    const uint32_t hA = (uint32_t)((lane >> 4) << 4);
    float cst = 0.f;

    // gpre double-buffer: preload step 0
    float gp0 = 0.f, gp1 = 0.f, gp2 = 0.f, gp3 = 0.f;
    if (u < 8) {
        const int t0_ = dir ? (LSEQ - 1) : 0;
        const float* gq = gpre + ((size_t)t0_ * GDIM + dc + u) * 32 + lane;
        gp0 = __ldg(gq);
        gp1 = __ldg(gq + (size_t)512 * 32);
        gp2 = __ldg(gq + (size_t)1024 * 32);
        gp3 = __ldg(gq + (size_t)1536 * 32);
    }

    for (int s = 0; s < LSEQ; s++) {
        const int t = dir ? (LSEQ - 1 - s) : s;
        const int p = s & 1;
        const unsigned tgt = 64u * (unsigned)(s + 2);

        // next-step gpre loads (hidden behind this step)
        float gn0 = 0.f, gn1 = 0.f, gn2 = 0.f, gn3 = 0.f;
        if (u < 8 && s + 1 < LSEQ) {
            const int tn = dir ? (LSEQ - 2 - s) : (s + 1);
            const float* gq = gpre + ((size_t)tn * GDIM + dc + u) * 32 + lane;
            gn0 = __ldg(gq);
            gn1 = __ldg(gq + (size_t)512 * 32);
            gn2 = __ldg(gq + (size_t)1024 * 32);
            gn3 = __ldg(gq + (size_t)1536 * 32);
        }

        {   // stage h_prev fp16: 32KB
            const uint4* hp = (const uint4*)g_h16[p][dir];
            #pragma unroll
            for (int i = 0; i < 4; i++) {
                int idx = i * 512 + tid;
                int b_ = idx >> 6, c = idx & 63;
                uint4 v = __ldcg(hp + idx);
                if (dir && t >= len_s[b_] - 1) v = make_uint4(0u, 0u, 0u, 0u);
                *(uint4*)(sm + R_A + b_ * 1040 + c * 16) = v;
            }
        }
        __syncthreads();                                 // (1)

        float acc[2][4][4];
        #pragma unroll
        for (int a = 0; a < 2; a++)
            #pragma unroll
            for (int b = 0; b < 4; b++)
                #pragma unroll
                for (int c = 0; c < 4; c++) acc[a][b][c] = 0.f;

        #pragma unroll
        for (int i = 0; i < 2; i++) {
            int kk = u * 2 + i;
            uint32_t col = (uint32_t)(kk * 32) + hA;
            uint32_t af0[4], af1[4];
            LDSM_X4(af0[0], af0[1], af0[2], af0[3], sb + R_A + rA * 1040 + col);
            LDSM_X4(af1[0], af1[1], af1[2], af1[3], sb + R_A + (rA + 16) * 1040 + col);
            #pragma unroll
            for (int nt = 0; nt < 4; nt++) {
                MMAF16(acc[0][nt], af0, &wf[i][nt * 2]);
                MMAF16(acc[1][nt], af1, &wf[i][nt * 2]);
            }
        }

        {
            int row = lane >> 2, colp = (lane & 3) * 2;
            #pragma unroll
            for (int mt = 0; mt < 2; mt++)
                #pragma unroll
                for (int nt = 0; nt < 4; nt++) {
                    float* p0 = part + (u * 32 + mt * 16 + row) * 33 + nt * 8 + colp;
                    p0[0] = acc[mt][nt][0]; p0[1] = acc[mt][nt][1];
                    float* p1 = part + (u * 32 + mt * 16 + row + 8) * 33 + nt * 8 + colp;
                    p1[0] = acc[mt][nt][2]; p1[1] = acc[mt][nt][3];
                }
        }
        __syncthreads();                                 // (2)

        // stage A reduce: all 512 threads, 2 outputs each (sum 16 warps)
        {
            int o = tid;
            #pragma unroll
            for (int rep = 0; rep < 2; rep++, o += 512) {
                int b_ = o >> 5, cl = o & 31;
                float sum = 0.f;
                #pragma unroll
                for (int w = 0; w < 16; w++)
                    sum += part[(w * 32 + b_) * 33 + cl];
                red[b_ * 33 + cl] = sum;
            }
        }
        __syncthreads();                                 // (3)

        if (u < 8) {   // stage B: cell update (b=lane, dim=dc+u)
            float s0 = red[lane * 33 + u];
            float s1 = red[lane * 33 + 8 + u];
            float s2 = red[lane * 33 + 16 + u];
            float s3 = red[lane * 33 + 24 + u];
            float iv = sigmoid_fast_(gp0 + s0);
            float gv = tanh_fast_(gp1 + s1);
            float fv = sigmoid_fast_(gp2 + s2 + 1.f);
            float ov = sigmoid_fast_(gp3 + s3);
            if (dir && t >= lenb - 1) cst = 0.f;
            cst = fv * cst + iv * gv;
            float hh = ov * tanh_fast_(cst);
            obh[lane * 9 + u] = hh;
            obp16[lane * 9 + u] = __half_as_ushort(__float2half_rn(hh));
        }
        gp0 = gn0; gp1 = gn1; gp2 = gn2; gp3 = gn3;

        unsigned sdone = 0u;
        if (tid < 256) {
            asm volatile("bar.sync 1, 256;" ::: "memory");   // warps 0-7 only
            if (tid < 32) {   // publish h: one STG.128 per batch row
                const unsigned short* sp = obp16 + tid * 9;
                uint4 o4;
                o4.x = (unsigned)sp[0] | ((unsigned)sp[1] << 16);
                o4.y = (unsigned)sp[2] | ((unsigned)sp[3] << 16);
                o4.z = (unsigned)sp[4] | ((unsigned)sp[5] << 16);
                o4.w = (unsigned)sp[6] | ((unsigned)sp[7] << 16);
                ((uint4*)g_h16[p ^ 1][dir])[tid * 64 + (dc >> 3)] = o4;
                __syncwarp();
                if (tid == 0) {
                    unsigned prev = bar_arrive_(barP);
                    sdone = (prev == tgt - 1u) ? 1u : 0u;
                }
            }
            // out store off the critical path
            int b2 = tid >> 3, d2 = tid & 7;
            out[(((size_t)b2 << 10) + t) * 1024 + (dir << 9) + dc + d2] = obh[b2 * 9 + d2];
        }
        if (tid == 0 && !sdone) bar_wait_(barP, tgt);
        __syncthreads();                                 // (4)
    }
}

// =================== launch ===================================================
extern "C" void kernel_launch(void* const* d_in, const int* in_sizes, int n_in,
                              void* d_out, int out_size)
{
    (void)in_sizes; (void)n_in; (void)out_size;
    const int*   x        = (const int*)  d_in[0];
    const int*   lengths  = (const int*)  d_in[1];
    const float* embed_w  = (const float*)d_in[2];
    const float* c1w = (const float*)d_in[3];
    const float* c1b = (const float*)d_in[4];
    const float* c2w = (const float*)d_in[5];
    const float* c2b = (const float*)d_in[6];
    const float* c3w = (const float*)d_in[7];
    const float* c3b = (const float*)d_in[8];
    const float* wf  = (const float*)d_in[9];
    const float* bf  = (const float*)d_in[10];
    const float* wb  = (const float*)d_in[11];
    const float* bb  = (const float*)d_in[12];
    const float* s1 = (const float*)d_in[13]; const float* o1 = (const float*)d_in[14];
    const float* m1 = (const float*)d_in[15]; const float* v1 = (const float*)d_in[16];
    const float* s2 = (const float*)d_in[17]; const float* o2 = (const float*)d_in[18];
    const float* m2 = (const float*)d_in[19]; const float* v2 = (const float*)d_in[20];
    const float* s3 = (const float*)d_in[21]; const float* o3 = (const float*)d_in[22];
    const float* m3 = (const float*)d_in[23]; const float* v3 = (const float*)d_in[24];
    float* out = (float*)d_out;

    __nv_bfloat16 *aHi, *aLo, *bHi, *bLo, *wcH, *wcL, *wgH, *wgL;
    __half *wrH;
    cudaGetSymbolAddress((void**)&aHi, g_aHi);
    cudaGetSymbolAddress((void**)&aLo, g_aLo);
    cudaGetSymbolAddress((void**)&bHi, g_bHi);
    cudaGetSymbolAddress((void**)&bLo, g_bLo);
    cudaGetSymbolAddress((void**)&wcH, g_wcHi);
    cudaGetSymbolAddress((void**)&wcL, g_wcLo);
    cudaGetSymbolAddress((void**)&wgH, g_wgHi);
    cudaGetSymbolAddress((void**)&wgL, g_wgLo);
    cudaGetSymbolAddress((void**)&wrH, g_wrHi);
    float* gpre;
    cudaGetSymbolAddress((void**)&gpre, g_gpre);

    const size_t WC = (size_t)3 * DIM * DIM;

    const int SMEM_GEMM  = 33280 + 2 * 32768;     // 98816
    cudaFuncSetAttribute(mma_gemm_kernel,
                         cudaFuncAttributeMaxDynamicSharedMemorySize, SMEM_GEMM);
    cudaFuncSetAttribute(lstm_recur_kernel,
                         cudaFuncAttributeMaxDynamicSharedMemorySize, R_SMEM);

    dim3 gconv(MTOT / 128, DIM / 128, 1);
    dim3 ggate(MTOT / 128, GDIM / 128, 2);
    dim3 bwp(32, 8);
    dim3 gwc(DIM / 32, DIM / 32, 9);
    dim3 gwg(DIM / 32, GDIM / 32, 2);

    wprep_conv_kernel<<<gwc, bwp>>>(c1w, c2w, c3w);
    bnprep_kernel<<<1, 512>>>(c1b, s1, o1, m1, v1,
                              c2b, s2, o2, m2, v2,
                              c3b, s3, o3, m3, v3);
    embed_kernel<<<MTOT, 128>>>(x, embed_w);
    mma_gemm_kernel<<<gconv, 256, SMEM_GEMM>>>(aHi, aLo, wcH + 0 * WC, wcL + 0 * WC,
        3, 0, 0, bHi, bLo, nullptr, nullptr, nullptr);
    mma_gemm_kernel<<<gconv, 256, SMEM_GEMM>>>(bHi, bLo, wcH + 1 * WC, wcL + 1 * WC,
        3, 1, 0, aHi, aLo, nullptr, nullptr, nullptr);
    mma_gemm_kernel<<<gconv, 256, SMEM_GEMM>>>(aHi, aLo, wcH + 2 * WC, wcL + 2 * WC,
        3, 2, 0, bHi, bLo, nullptr, nullptr, nullptr);
    wprep_gate_kernel<<<gwg, bwp>>>(wf, wb);
    wprep_rec_kernel<<<gwg, bwp>>>(wf, wb);
    mma_gemm_kernel<<<ggate, 256, SMEM_GEMM>>>(bHi, bLo, wgH, wgL,
        1, -1, 1, nullptr, nullptr, bf, bb, gpre);
    lstm_recur_kernel<<<128, 512, R_SMEM>>>(wrH, lengths, gpre, out);
}

// round 14
// speedup vs baseline: 3.6238x; 1.1253x over previous
#include <cuda_runtime.h>
#include <cuda_bf16.h>
#include <cuda_fp16.h>
#include <stdint.h>
#include <math.h>

#define BSZ   32
#define LSEQ  1024
#define DIM   512
#define MTOT  (BSZ*LSEQ)          // 32768
#define GDIM  2048                // 4*DIM

// =================== scratch (device globals) ================================
__device__ __align__(128) __nv_bfloat16 g_aHi[(size_t)MTOT*DIM];
__device__ __align__(128) __nv_bfloat16 g_aLo[(size_t)MTOT*DIM];
__device__ __align__(128) __nv_bfloat16 g_bHi[(size_t)MTOT*DIM];
__device__ __align__(128) __nv_bfloat16 g_bLo[(size_t)MTOT*DIM];
__device__ __align__(128) __nv_bfloat16 g_wcHi[3][(size_t)3*DIM*DIM];   // [layer][tap*512+n][k]
__device__ __align__(128) __nv_bfloat16 g_wcLo[3][(size_t)3*DIM*DIM];
__device__ __align__(128) __nv_bfloat16 g_wgHi[2][(size_t)GDIM*DIM];    // [dir][n][k]
__device__ __align__(128) __nv_bfloat16 g_wgLo[2][(size_t)GDIM*DIM];
__device__ __align__(128) __half g_wrHi[2][(size_t)GDIM*DIM];           // recurrent W fp16 (hi only)
__device__ float g_gpre[2][(size_t)MTOT*GDIM];   // [dir][ (t*2048 + col)*32 + b ]
__device__ __align__(128) __half g_h16[2][2][BSZ*DIM];  // [parity][dir][b*512+d]
__device__ float g_alpha[3][DIM];
__device__ float g_beta[3][DIM];
__device__ __align__(1024) unsigned g_bar[2][256];    // monotonic, dirs 1KB apart

// =================== primitives ===============================================
__device__ __forceinline__ uint32_t smem_to_u32(const void* p) {
    uint32_t a;
    asm("{ .reg .u64 t; cvta.to.shared.u64 t, %1; cvt.u32.u64 %0, t; }" : "=r"(a) : "l"(p));
    return a;
}
#define LDSM_X4(r0, r1, r2, r3, addr) \
    asm volatile("ldmatrix.sync.aligned.m8n8.x4.shared.b16 {%0,%1,%2,%3}, [%4];" \
        : "=r"(r0), "=r"(r1), "=r"(r2), "=r"(r3) : "r"(addr))
#define MMA16816(c, a, b) \
    asm volatile("mma.sync.aligned.m16n8k16.row.col.f32.bf16.bf16.f32 " \
        "{%0,%1,%2,%3}, {%4,%5,%6,%7}, {%8,%9}, {%0,%1,%2,%3};" \
        : "+f"((c)[0]), "+f"((c)[1]), "+f"((c)[2]), "+f"((c)[3]) \
        : "r"((a)[0]), "r"((a)[1]), "r"((a)[2]), "r"((a)[3]), \
          "r"((b)[0]), "r"((b)[1]))
#define MMAF16(c, a, b) \
    asm volatile("mma.sync.aligned.m16n8k16.row.col.f32.f16.f16.f32 " \
        "{%0,%1,%2,%3}, {%4,%5,%6,%7}, {%8,%9}, {%0,%1,%2,%3};" \
        : "+f"((c)[0]), "+f"((c)[1]), "+f"((c)[2]), "+f"((c)[3]) \
        : "r"((a)[0]), "r"((a)[1]), "r"((a)[2]), "r"((a)[3]), \
          "r"((b)[0]), "r"((b)[1]))

__device__ __forceinline__ float tanh_fast_(float x) {
    float y;
    asm("tanh.approx.f32 %0, %1;" : "=f"(y) : "f"(x));
    return y;
}
__device__ __forceinline__ float sigmoid_fast_(float x) {
    return fmaf(tanh_fast_(0.5f * x), 0.5f, 0.5f);
}
__device__ __forceinline__ unsigned bar_arrive_(unsigned* arr) {
    unsigned prev;
    asm volatile("atom.release.gpu.global.add.u32 %0, [%1], 1;"
                 : "=r"(prev) : "l"(arr) : "memory");
    return prev;
}
__device__ __forceinline__ void bar_wait_(unsigned* arr, unsigned tgt) {
    unsigned v;
    do {
        asm volatile("ld.acquire.gpu.global.u32 %0, [%1];" : "=r"(v) : "l"(arr));
    } while (v < tgt);
}

// =================== barrier reset (determinism across graph replays) ========
// The monotonic barrier counter MUST start at 0 every launch; a leftover value
// from a previous replay disables all inter-block synchronization (R13 bug).
__global__ void bar_reset_kernel()
{
    g_bar[threadIdx.x >> 8][threadIdx.x & 255] = 0u;
}

// =================== BN fold =================================================
__global__ void bnprep_kernel(
    const float* __restrict__ b1, const float* __restrict__ s1, const float* __restrict__ o1,
    const float* __restrict__ m1, const float* __restrict__ v1,
    const float* __restrict__ b2, const float* __restrict__ s2, const float* __restrict__ o2,
    const float* __restrict__ m2, const float* __restrict__ v2,
    const float* __restrict__ b3, const float* __restrict__ s3, const float* __restrict__ o3,
    const float* __restrict__ m3, const float* __restrict__ v3)
{
    int i = threadIdx.x;
    if (i < DIM) {
        float g;
        g = s1[i] * rsqrtf(v1[i] + 1e-5f); g_alpha[0][i] = g; g_beta[0][i] = (b1[i] - m1[i]) * g + o1[i];
        g = s2[i] * rsqrtf(v2[i] + 1e-5f); g_alpha[1][i] = g; g_beta[1][i] = (b2[i] - m2[i]) * g + o2[i];
        g = s3[i] * rsqrtf(v3[i] + 1e-5f); g_alpha[2][i] = g; g_beta[2][i] = (b3[i] - m3[i]) * g + o3[i];
    }
}

// =================== weight prep (coalesced 32x32 transposes) =================
__global__ void wprep_conv_kernel(const float* __restrict__ c1,
                                  const float* __restrict__ c2,
                                  const float* __restrict__ c3)
{
    __shared__ float tile[32][33];
    const int tx = threadIdx.x, ty = threadIdx.y;
    const int k0 = blockIdx.x * 32, n0 = blockIdx.y * 32;
    const int layer = blockIdx.z / 3, tap = blockIdx.z % 3;
    const float* W = (layer == 0) ? c1 : ((layer == 1) ? c2 : c3);
    #pragma unroll
    for (int i = 0; i < 4; i++)
        tile[ty + i * 8][tx] = W[(size_t)(tap * DIM + k0 + ty + i * 8) * DIM + n0 + tx];
    __syncthreads();
    #pragma unroll
    for (int i = 0; i < 4; i++) {
        int n = n0 + ty + i * 8;
        float v = tile[tx][ty + i * 8];
        __nv_bfloat16 h = __float2bfloat16(v);
        __nv_bfloat16 l = __float2bfloat16(v - __bfloat162float(h));
        g_wcHi[layer][(size_t)(tap * DIM + n) * DIM + k0 + tx] = h;
        g_wcLo[layer][(size_t)(tap * DIM + n) * DIM + k0 + tx] = l;
    }
}
__global__ void wprep_gate_kernel(const float* __restrict__ Wf,
                                  const float* __restrict__ Wb)
{
    __shared__ float tile[32][33];
    const int tx = threadIdx.x, ty = threadIdx.y;
    const int k0 = blockIdx.x * 32, n0 = blockIdx.y * 32;
    const int dir = blockIdx.z;
    const float* W = dir ? Wb : Wf;
    #pragma unroll
    for (int i = 0; i < 4; i++)
        tile[ty + i * 8][tx] = W[(size_t)(k0 + ty + i * 8) * GDIM + n0 + tx];
    __syncthreads();
    #pragma unroll
    for (int i = 0; i < 4; i++) {
        int n = n0 + ty + i * 8;
        float v = tile[tx][ty + i * 8];
        __nv_bfloat16 h = __float2bfloat16(v);
        __nv_bfloat16 l = __float2bfloat16(v - __bfloat162float(h));
        g_wgHi[dir][(size_t)n * DIM + k0 + tx] = h;
        g_wgLo[dir][(size_t)n * DIM + k0 + tx] = l;
    }
}
// recurrent W fp16 (hi only), rows 512..1023
__global__ void wprep_rec_kernel(const float* __restrict__ Wf,
                                 const float* __restrict__ Wb)
{
    __shared__ float tile[32][33];
    const int tx = threadIdx.x, ty = threadIdx.y;
    const int k0 = blockIdx.x * 32, n0 = blockIdx.y * 32;
    const int dir = blockIdx.z;
    const float* W = dir ? Wb : Wf;
    #pragma unroll
    for (int i = 0; i < 4; i++)
        tile[ty + i * 8][tx] = W[(size_t)(DIM + k0 + ty + i * 8) * GDIM + n0 + tx];
    __syncthreads();
    #pragma unroll
    for (int i = 0; i < 4; i++) {
        int n = n0 + ty + i * 8;
        g_wrHi[dir][(size_t)n * DIM + k0 + tx] = __float2half_rn(tile[tx][ty + i * 8]);
    }
}

// =================== embedding -> bf16 hi/lo =================================
__global__ void embed_kernel(const int* __restrict__ x, const float* __restrict__ ew)
{
    int m = blockIdx.x;
    int tok = x[m];
    int j = threadIdx.x;
    float4 v = ((const float4*)(ew + (size_t)tok * DIM))[j];
    float f[4] = {v.x, v.y, v.z, v.w};
    __nv_bfloat16 h[4], l[4];
    #pragma unroll
    for (int i = 0; i < 4; i++) {
        h[i] = __float2bfloat16(f[i]);
        l[i] = __float2bfloat16(f[i] - __bfloat162float(h[i]));
    }
    *(uint2*)(g_aHi + (size_t)m * DIM + j * 4) = *(uint2*)h;
    *(uint2*)(g_aLo + (size_t)m * DIM + j * 4) = *(uint2*)l;
}

// =================== bf16 mma.sync GEMM (unchanged engine) ====================
__global__ void __launch_bounds__(256, 2) mma_gemm_kernel(
    const __nv_bfloat16* __restrict__ Ahi, const __nv_bfloat16* __restrict__ Alo,
    const __nv_bfloat16* __restrict__ BwHi, const __nv_bfloat16* __restrict__ BwLo,
    int taps, int layer, int bperm,
    __nv_bfloat16* __restrict__ outHi, __nv_bfloat16* __restrict__ outLo,
    const float* __restrict__ biasA, const float* __restrict__ biasB,
    float* __restrict__ gout)
{
    extern __shared__ char smem[];
    const int tid = threadIdx.x;
    const int lane = tid & 31, wid = tid >> 5;
    const int wm = wid & 3, wn = wid >> 2;
    const int m0 = blockIdx.x * 128, n0 = blockIdx.y * 128;
    const int t0 = m0 & (LSEQ - 1);
    const int tb4 = blockIdx.x * 4;
    const int dz = blockIdx.z;
    const uint32_t sb = smem_to_u32(smem);

    if (bperm) {
        BwHi += (size_t)dz * GDIM * DIM;
        BwLo += (size_t)dz * GDIM * DIM;
        gout += (size_t)dz * MTOT * GDIM;
    }
    const float* bias = dz ? biasB : biasA;

    const int off0  = taps >> 1;
    const int arows = 128 + (taps - 1);

    float acc[2][8][4];
    #pragma unroll
    for (int a = 0; a < 2; a++)
        #pragma unroll
        for (int b = 0; b < 8; b++)
            #pragma unroll
            for (int c = 0; c < 4; c++) acc[a][b][c] = 0.f;

    #define DO_COPY_A(SLICE) do { \
        const int _kb = (SLICE) << 6; \
        const int _tot = arows * 8; \
        for (int _i = tid; _i < _tot; _i += 256) { \
            int _r = _i >> 3, _c8 = (_i & 7) << 3; \
            uint32_t _off = (uint32_t)(_r * 128) + (((uint32_t)_c8 * 2) ^ (((uint32_t)_r & 7) << 4)); \
            uint4 _vh = make_uint4(0u,0u,0u,0u), _vl = _vh; \
            if (bperm) { \
                size_t _ga = (size_t)(((_r & 31) << 10) + tb4 + (_r >> 5)) * DIM + _kb + _c8; \
                _vh = *(const uint4*)(Ahi + _ga); \
                _vl = *(const uint4*)(Alo + _ga); \
            } else { \
                int _tl = t0 + _r - off0; \
                if (_tl >= 0 && _tl < LSEQ) { \
                    size_t _ga = (size_t)(m0 + _r - off0) * DIM + _kb + _c8; \
                    _vh = *(const uint4*)(Ahi + _ga); \
                    _vl = *(const uint4*)(Alo + _ga); \
                } \
            } \
            *(uint4*)(smem + _off) = _vh; \
            *(uint4*)(smem + 16640 + _off) = _vl; \
        } \
    } while (0)

    #define DO_COPY_B(IDX, ST) do { \
        const int _sl = (IDX) / taps, _tp = (IDX) % taps; \
        const int _kb = _sl << 6; \
        const int _rbase = (taps == 3 ? _tp * DIM : 0) + n0; \
        char* _bp = smem + 33280 + (ST) * 32768; \
        for (int _i = tid; _i < 1024; _i += 256) { \
            int _r = _i >> 3, _c8 = (_i & 7) << 3; \
            uint32_t _off = (uint32_t)(_r * 128) + (((uint32_t)_c8 * 2) ^ (((uint32_t)_r & 7) << 4)); \
            size_t _ga = (size_t)(_rbase + _r) * DIM + _kb + _c8; \
            *(uint4*)(_bp + _off) = *(const uint4*)(BwHi + _ga); \
            *(uint4*)(_bp + 16384 + _off) = *(const uint4*)(BwLo + _ga); \
        } \
    } while (0)

    const int NB = 8 * taps;
    DO_COPY_A(0);
    DO_COPY_B(0, 0);
    __syncthreads();

    for (int idx = 0; idx < NB; idx++) {
        const int tap = idx % taps;
        const int bsel = idx & 1;
        const bool lastTap = (tap == taps - 1);

        if (idx + 1 < NB) DO_COPY_B(idx + 1, bsel ^ 1);

        const uint32_t aHiB = sb;
        const uint32_t aLoB = sb + 16640;
        const uint32_t bHiB = sb + 33280 + (uint32_t)bsel * 32768;
        const uint32_t bLoB = bHiB + 16384;
        #pragma unroll
        for (int k16 = 0; k16 < 4; k16++) {
            const uint32_t colA = (uint32_t)(k16 * 32) + (((uint32_t)lane >> 4) << 4);
            const uint32_t colB = (uint32_t)(k16 * 32) + ((((uint32_t)lane >> 3) & 1) << 4);
            uint32_t afh[2][4], afl[2][4];
            #pragma unroll
            for (int mt = 0; mt < 2; mt++) {
                uint32_t row = (uint32_t)(wm * 32 + mt * 16 + (lane & 15) + tap);
                uint32_t ad = row * 128 + (colA ^ ((row & 7) << 4));
                LDSM_X4(afh[mt][0], afh[mt][1], afh[mt][2], afh[mt][3], aHiB + ad);
                LDSM_X4(afl[mt][0], afl[mt][1], afl[mt][2], afl[mt][3], aLoB + ad);
            }
            #pragma unroll
            for (int half = 0; half < 2; half++) {
                uint32_t bfh[4][2], bfl[4][2];
                #pragma unroll
                for (int np = 0; np < 2; np++) {
                    uint32_t row = (uint32_t)(wn * 64 + (half * 2 + np) * 16 +
                                              (((lane >> 4) << 3) | (lane & 7)));
                    uint32_t bd = row * 128 + (colB ^ ((row & 7) << 4));
                    LDSM_X4(bfh[2*np][0], bfh[2*np][1], bfh[2*np+1][0], bfh[2*np+1][1], bHiB + bd);
                    LDSM_X4(bfl[2*np][0], bfl[2*np][1], bfl[2*np+1][0], bfl[2*np+1][1], bLoB + bd);
                }
                #pragma unroll
                for (int mt = 0; mt < 2; mt++)
                    #pragma unroll
                    for (int nt = 0; nt < 4; nt++) {
                        float* ac = acc[mt][half * 4 + nt];
                        MMA16816(ac, afh[mt], bfh[nt]);
                        MMA16816(ac, afl[mt], bfh[nt]);
                        MMA16816(ac, afh[mt], bfl[nt]);
                    }
            }
        }
        __syncthreads();
        if (lastTap && idx + 1 < NB) {
            DO_COPY_A((idx + 1) / taps);
            __syncthreads();
        }
    }
    #undef DO_COPY_A
    #undef DO_COPY_B

    const int g  = lane >> 2;
    const int tg = lane & 3;
    if (gout == nullptr) {            // conv epilogue
        #pragma unroll
        for (int mt = 0; mt < 2; mt++) {
            const int mlo = m0 + wm * 32 + mt * 16 + g;
            const int mhi = mlo + 8;
            #pragma unroll
            for (int nt = 0; nt < 8; nt++) {
                const int n = n0 + wn * 64 + nt * 8 + tg * 2;
                const float al0 = g_alpha[layer][n],     be0 = g_beta[layer][n];
                const float al1 = g_alpha[layer][n + 1], be1 = g_beta[layer][n + 1];
                float v00 = fmaxf(fmaf(acc[mt][nt][0], al0, be0), 0.f);
                float v01 = fmaxf(fmaf(acc[mt][nt][1], al1, be1), 0.f);
                float v10 = fmaxf(fmaf(acc[mt][nt][2], al0, be0), 0.f);
                float v11 = fmaxf(fmaf(acc[mt][nt][3], al1, be1), 0.f);
                __nv_bfloat16 h00 = __float2bfloat16(v00), h01 = __float2bfloat16(v01);
                __nv_bfloat16 h10 = __float2bfloat16(v10), h11 = __float2bfloat16(v11);
                __nv_bfloat16 l00 = __float2bfloat16(v00 - __bfloat162float(h00));
                __nv_bfloat16 l01 = __float2bfloat16(v01 - __bfloat162float(h01));
                __nv_bfloat16 l10 = __float2bfloat16(v10 - __bfloat162float(h10));
                __nv_bfloat16 l11 = __float2bfloat16(v11 - __bfloat162float(h11));
                __nv_bfloat162 ph0; ph0.x = h00; ph0.y = h01;
                __nv_bfloat162 ph1; ph1.x = h10; ph1.y = h11;
                __nv_bfloat162 pl0; pl0.x = l00; pl0.y = l01;
                __nv_bfloat162 pl1; pl1.x = l10; pl1.y = l11;
                *(__nv_bfloat162*)(outHi + (size_t)mlo * DIM + n) = ph0;
                *(__nv_bfloat162*)(outHi + (size_t)mhi * DIM + n) = ph1;
                *(__nv_bfloat162*)(outLo + (size_t)mlo * DIM + n) = pl0;
                *(__nv_bfloat162*)(outLo + (size_t)mhi * DIM + n) = pl1;
            }
        }
    } else {                          // gates (bperm): smem transpose -> coalesced
        float* tile = (float*)smem;
        #pragma unroll
        for (int mt = 0; mt < 2; mt++) {
            const int rlo = wm * 32 + mt * 16 + g;
            const int rhi = rlo + 8;
            #pragma unroll
            for (int nt = 0; nt < 8; nt++) {
                const int nl = wn * 64 + nt * 8 + tg * 2;
                const float b0 = bias[n0 + nl], b1 = bias[n0 + nl + 1];
                tile[rlo * 129 + nl    ] = acc[mt][nt][0] + b0;
                tile[rlo * 129 + nl + 1] = acc[mt][nt][1] + b1;
                tile[rhi * 129 + nl    ] = acc[mt][nt][2] + b0;
                tile[rhi * 129 + nl + 1] = acc[mt][nt][3] + b1;
            }
        }
        __syncthreads();
        for (int i = tid; i < 16384; i += 256) {
            int b_  = i & 31;
            int nl  = (i >> 5) & 127;
            int tt  = i >> 12;
            gout[((size_t)(tb4 + tt) * GDIM + n0 + nl) * 32 + b_] =
                tile[(tt * 32 + b_) * 129 + nl];
        }
    }
}

// =================== persistent LSTM recurrence — 256 thr, fused reduce =======
#define R_WHI 0
#define R_A   33280
#define R_PART 66560                        // 8*32*33*4 = 33792
#define R_OBH  100352                       // float[288] = 1152
#define R_OBP  101504                       // ushort[288] = 576
#define R_SMEM 102080

__global__ void __launch_bounds__(256, 1) lstm_recur_kernel(
    const __half* __restrict__ wrHi,
    const int* __restrict__ lengths, const float* __restrict__ gpreAll,
    float* __restrict__ out)
{
    extern __shared__ char sm[];
    float* part = (float*)(sm + R_PART);
    float* obh  = (float*)(sm + R_OBH);
    unsigned short* obp16 = (unsigned short*)(sm + R_OBP);
    __shared__ int len_s[32];

    const int tid = threadIdx.x;
    const int lane = tid & 31, u = tid >> 5;        // u in [0,8)
    const int dir = blockIdx.x >> 6;
    const int dc  = (blockIdx.x & 63) << 3;
    const uint32_t sb = smem_to_u32(sm);
    const float* gpre = gpreAll + (size_t)dir * MTOT * GDIM;
    const __half* wHi = wrHi + (size_t)dir * GDIM * DIM;
    unsigned* barP = &g_bar[dir][0];

    // stage W hi (permuted rows, 1040B padded stride)
    for (int i = tid; i < 2048; i += 256) {
        int r = i >> 6, c16 = i & 63;
        int n = ((r >> 3) << 9) + dc + (r & 7);
        uint4 vh = *(const uint4*)(wHi + (size_t)n * DIM + c16 * 8);
        *(uint4*)(sm + R_WHI + r * 1040 + c16 * 16) = vh;
    }
    if (tid < 32) len_s[tid] = lengths[tid];
    if (tid < 32)
        ((uint4*)g_h16[0][dir])[tid * 64 + (dc >> 3)] = make_uint4(0u, 0u, 0u, 0u);
    __syncthreads();

    // preload W fragments: 4 k16-tiles per warp (8 warps x 4 = 32 tiles = K512)
    uint32_t wf[4][8];
    {
        const uint32_t rB = (uint32_t)(((lane >> 4) << 3) | (lane & 7));
        const uint32_t hB = (uint32_t)(((lane >> 3) & 1) << 4);
        #pragma unroll
        for (int i = 0; i < 4; i++) {
            int kk = u * 4 + i;
            uint32_t col = (uint32_t)(kk * 32) + hB;
            LDSM_X4(wf[i][0], wf[i][1], wf[i][2], wf[i][3], sb + R_WHI + rB * 1040 + col);
            LDSM_X4(wf[i][4], wf[i][5], wf[i][6], wf[i][7], sb + R_WHI + (rB + 16) * 1040 + col);
        }
    }
    const int lenb = len_s[lane];

    // startup barrier (monotonic; counter freshly zeroed by bar_reset_kernel)
    __syncthreads();
    if (tid == 0) {
        unsigned prev = bar_arrive_(barP);
        if (prev != 63u) bar_wait_(barP, 64u);
    }
    __syncthreads();

    const uint32_t rA = (uint32_t)(lane & 15);
    const uint32_t hA = (uint32_t)((lane >> 4) << 4);
    float cst = 0.f;

    // gpre double-buffer: preload step 0 (thread = batch lane, dim dc+u)
    float gp0, gp1, gp2, gp3;
    {
        const int t0_ = dir ? (LSEQ - 1) : 0;
        const float* gq = gpre + ((size_t)t0_ * GDIM + dc + u) * 32 + lane;
        gp0 = __ldg(gq);
        gp1 = __ldg(gq + (size_t)512 * 32);
        gp2 = __ldg(gq + (size_t)1024 * 32);
        gp3 = __ldg(gq + (size_t)1536 * 32);
    }

    for (int s = 0; s < LSEQ; s++) {
        const int t = dir ? (LSEQ - 1 - s) : s;
        const int p = s & 1;
        const unsigned tgt = 64u * (unsigned)(s + 2);

        // next-step gpre loads (hidden behind this step)
        float gn0 = 0.f, gn1 = 0.f, gn2 = 0.f, gn3 = 0.f;
        if (s + 1 < LSEQ) {
            const int tn = dir ? (LSEQ - 2 - s) : (s + 1);
            const float* gq = gpre + ((size_t)tn * GDIM + dc + u) * 32 + lane;
            gn0 = __ldg(gq);
            gn1 = __ldg(gq + (size_t)512 * 32);
            gn2 = __ldg(gq + (size_t)1024 * 32);
            gn3 = __ldg(gq + (size_t)1536 * 32);
        }

        {   // stage h_prev fp16: 32KB, 8 uint4/thread
            const uint4* hp = (const uint4*)g_h16[p][dir];
            #pragma unroll
            for (int i = 0; i < 8; i++) {
                int idx = i * 256 + tid;            // 0..2047
                int b_ = idx >> 6, c = idx & 63;
                uint4 v = __ldcg(hp + idx);
                if (dir && t >= len_s[b_] - 1) v = make_uint4(0u, 0u, 0u, 0u);
                *(uint4*)(sm + R_A + b_ * 1040 + c * 16) = v;
            }
        }
        __syncthreads();                                 // (1)

        float acc[2][4][4];
        #pragma unroll
        for (int a = 0; a < 2; a++)
            #pragma unroll
            for (int b = 0; b < 4; b++)
                #pragma unroll
                for (int c = 0; c < 4; c++) acc[a][b][c] = 0.f;

        #pragma unroll
        for (int i = 0; i < 4; i++) {
            int kk = u * 4 + i;
            uint32_t col = (uint32_t)(kk * 32) + hA;
            uint32_t af0[4], af1[4];
            LDSM_X4(af0[0], af0[1], af0[2], af0[3], sb + R_A + rA * 1040 + col);
            LDSM_X4(af1[0], af1[1], af1[2], af1[3], sb + R_A + (rA + 16) * 1040 + col);
            #pragma unroll
            for (int nt = 0; nt < 4; nt++) {
                MMAF16(acc[0][nt], af0, &wf[i][nt * 2]);
                MMAF16(acc[1][nt], af1, &wf[i][nt * 2]);
            }
        }

        {
            int row = lane >> 2, colp = (lane & 3) * 2;
            #pragma unroll
            for (int mt = 0; mt < 2; mt++)
                #pragma unroll
                for (int nt = 0; nt < 4; nt++) {
                    float* p0 = part + (u * 32 + mt * 16 + row) * 33 + nt * 8 + colp;
                    p0[0] = acc[mt][nt][0]; p0[1] = acc[mt][nt][1];
                    float* p1 = part + (u * 32 + mt * 16 + row + 8) * 33 + nt * 8 + colp;
                    p1[0] = acc[mt][nt][2]; p1[1] = acc[mt][nt][3];
                }
        }
        __syncthreads();                                 // (2)

        // fused reduce + cell update: thread (b=lane, dim=dc+u), all 256 threads
        {
            float s0 = 0.f, s1 = 0.f, s2 = 0.f, s3 = 0.f;
            #pragma unroll
            for (int w = 0; w < 8; w++) {
                const float* pr = part + (w * 32 + lane) * 33;
                s0 += pr[u]; s1 += pr[8 + u]; s2 += pr[16 + u]; s3 += pr[24 + u];
            }
            float iv = sigmoid_fast_(gp0 + s0);
            float gv = tanh_fast_(gp1 + s1);
            float fv = sigmoid_fast_(gp2 + s2 + 1.f);
            float ov = sigmoid_fast_(gp3 + s3);
            if (dir && t >= lenb - 1) cst = 0.f;
            cst = fv * cst + iv * gv;
            float hh = ov * tanh_fast_(cst);
            obh[lane * 9 + u] = hh;
            obp16[lane * 9 + u] = __half_as_ushort(__float2half_rn(hh));
        }
        gp0 = gn0; gp1 = gn1; gp2 = gn2; gp3 = gn3;
        __syncthreads();                                 // (3)

        unsigned sdone = 0u;
        if (tid < 32) {   // publish h: one STG.128 per batch row
            const unsigned short* sp = obp16 + tid * 9;
            uint4 o4;
            o4.x = (unsigned)sp[0] | ((unsigned)sp[1] << 16);
            o4.y = (unsigned)sp[2] | ((unsigned)sp[3] << 16);
            o4.z = (unsigned)sp[4] | ((unsigned)sp[5] << 16);
            o4.w = (unsigned)sp[6] | ((unsigned)sp[7] << 16);
            ((uint4*)g_h16[p ^ 1][dir])[tid * 64 + (dc >> 3)] = o4;
            __syncwarp();
            if (tid == 0) {
                unsigned prev = bar_arrive_(barP);
                sdone = (prev == tgt - 1u) ? 1u : 0u;
            }
        }
        // out store off the critical path
        {
            int b2 = tid >> 3, d2 = tid & 7;
            out[(((size_t)b2 << 10) + t) * 1024 + (dir << 9) + dc + d2] = obh[b2 * 9 + d2];
        }
        if (tid == 0 && !sdone) bar_wait_(barP, tgt);
        __syncthreads();                                 // (4)
    }
}

// =================== launch ===================================================
extern "C" void kernel_launch(void* const* d_in, const int* in_sizes, int n_in,
                              void* d_out, int out_size)
{
    (void)in_sizes; (void)n_in; (void)out_size;
    const int*   x        = (const int*)  d_in[0];
    const int*   lengths  = (const int*)  d_in[1];
    const float* embed_w  = (const float*)d_in[2];
    const float* c1w = (const float*)d_in[3];
    const float* c1b = (const float*)d_in[4];
    const float* c2w = (const float*)d_in[5];
    const float* c2b = (const float*)d_in[6];
    const float* c3w = (const float*)d_in[7];
    const float* c3b = (const float*)d_in[8];
    const float* wf  = (const float*)d_in[9];
    const float* bf  = (const float*)d_in[10];
    const float* wb  = (const float*)d_in[11];
    const float* bb  = (const float*)d_in[12];
    const float* s1 = (const float*)d_in[13]; const float* o1 = (const float*)d_in[14];
    const float* m1 = (const float*)d_in[15]; const float* v1 = (const float*)d_in[16];
    const float* s2 = (const float*)d_in[17]; const float* o2 = (const float*)d_in[18];
    const float* m2 = (const float*)d_in[19]; const float* v2 = (const float*)d_in[20];
    const float* s3 = (const float*)d_in[21]; const float* o3 = (const float*)d_in[22];
    const float* m3 = (const float*)d_in[23]; const float* v3 = (const float*)d_in[24];
    float* out = (float*)d_out;

    __nv_bfloat16 *aHi, *aLo, *bHi, *bLo, *wcH, *wcL, *wgH, *wgL;
    __half *wrH;
    cudaGetSymbolAddress((void**)&aHi, g_aHi);
    cudaGetSymbolAddress((void**)&aLo, g_aLo);
    cudaGetSymbolAddress((void**)&bHi, g_bHi);
    cudaGetSymbolAddress((void**)&bLo, g_bLo);
    cudaGetSymbolAddress((void**)&wcH, g_wcHi);
    cudaGetSymbolAddress((void**)&wcL, g_wcLo);
    cudaGetSymbolAddress((void**)&wgH, g_wgHi);
    cudaGetSymbolAddress((void**)&wgL, g_wgLo);
    cudaGetSymbolAddress((void**)&wrH, g_wrHi);
    float* gpre;
    cudaGetSymbolAddress((void**)&gpre, g_gpre);

    const size_t WC = (size_t)3 * DIM * DIM;

    const int SMEM_GEMM  = 33280 + 2 * 32768;     // 98816
    cudaFuncSetAttribute(mma_gemm_kernel,
                         cudaFuncAttributeMaxDynamicSharedMemorySize, SMEM_GEMM);
    cudaFuncSetAttribute(lstm_recur_kernel,
                         cudaFuncAttributeMaxDynamicSharedMemorySize, R_SMEM);

    dim3 gconv(MTOT / 128, DIM / 128, 1);
    dim3 ggate(MTOT / 128, GDIM / 128, 2);
    dim3 bwp(32, 8);
    dim3 gwc(DIM / 32, DIM / 32, 9);
    dim3 gwg(DIM / 32, GDIM / 32, 2);

    bar_reset_kernel<<<1, 512>>>();               // determinism across replays
    wprep_conv_kernel<<<gwc, bwp>>>(c1w, c2w, c3w);
    bnprep_kernel<<<1, 512>>>(c1b, s1, o1, m1, v1,
                              c2b, s2, o2, m2, v2,
                              c3b, s3, o3, m3, v3);
    embed_kernel<<<MTOT, 128>>>(x, embed_w);
    mma_gemm_kernel<<<gconv, 256, SMEM_GEMM>>>(aHi, aLo, wcH + 0 * WC, wcL + 0 * WC,
        3, 0, 0, bHi, bLo, nullptr, nullptr, nullptr);
    mma_gemm_kernel<<<gconv, 256, SMEM_GEMM>>>(bHi, bLo, wcH + 1 * WC, wcL + 1 * WC,
        3, 1, 0, aHi, aLo, nullptr, nullptr, nullptr);
    mma_gemm_kernel<<<gconv, 256, SMEM_GEMM>>>(aHi, aLo, wcH + 2 * WC, wcL + 2 * WC,
        3, 2, 0, bHi, bLo, nullptr, nullptr, nullptr);
    wprep_gate_kernel<<<gwg, bwp>>>(wf, wb);
    wprep_rec_kernel<<<gwg, bwp>>>(wf, wb);
    mma_gemm_kernel<<<ggate, 256, SMEM_GEMM>>>(bHi, bLo, wgH, wgL,
        1, -1, 1, nullptr, nullptr, bf, bb, gpre);
    lstm_recur_kernel<<<128, 256, R_SMEM>>>(wrH, lengths, gpre, out);
}